// round 3
// baseline (speedup 1.0000x reference)
#include <cuda_runtime.h>
#include <math.h>

#define KT   50
#define TT   50
#define RHOD 300
#define VV   20000
#define THH  800
#define EHH  200
#define SSRC 10
#define BB   256
#define DELTAF 0.005f
#define LOG_DELTA_F (-5.2983173665480363f)
#define EPSF 1e-6f

// ---------------- device scratch ----------------
__device__ float g_alphas[TT*KT*RHOD];
__device__ float g_E[(size_t)TT*KT*VV];     // 200MB
__device__ float g_invZ[TT*KT];
__device__ float g_part1[8*500*EHH];
__device__ float g_mapped[500*EHH];
__device__ float g_xz[500*4*EHH];
__device__ float g_WhhT[EHH*4*EHH];
__device__ float g_lstm_out[TT*SSRC*EHH];
__device__ float g_base_mu[TT*SSRC*KT];
__device__ float g_base_ls[TT*SSRC*KT];
__device__ float g_etas[SSRC*TT*KT];
__device__ float g_eta_std[BB*KT];
__device__ float g_part4[16*BB*THH];
__device__ float g_h1[BB*THH];
__device__ float g_h2[BB*THH];
__device__ float g_mu_t[BB*KT];
__device__ float g_ls_t[BB*KT];
__device__ float g_theta[BB*KT];
__device__ float g_pa[KT*TT];
__device__ float g_pnll[BB];
__device__ float g_pth[BB];
__device__ float g_ppred[BB];
__device__ float g_kleta[1];

__device__ __forceinline__ float sigm_(float x){ return 1.f/(1.f+expf(-x)); }

// ---------------- generic NT SGEMM: C[m,n] = sum_k A[m,k]*B[n,k] ----------------
template<int BM,int BN,int BK,int TM,int TN>
__global__ void __launch_bounds__((BM/TM)*(BN/TN))
sgemm_nt(int M,int N,int Kd,
         const float* __restrict__ A,int lda,
         const float* __restrict__ B,int ldb,
         float* __restrict__ C,int ldc,
         const float* __restrict__ bias1,
         const float* __restrict__ bias2,
         int op)  // 0 none, 1 relu, 2 exp
{
    constexpr int THREADS=(BM/TM)*(BN/TN);
    __shared__ float As[BK][BM+4];
    __shared__ float Bs[BK][BN+4];
    const int tid=threadIdx.x;
    const int bm=blockIdx.y*BM, bn=blockIdx.x*BN;
    int k0=0,k1=Kd;
    const int nz=gridDim.z;
    if(nz>1){
        int kChunk=((Kd + nz*BK - 1)/(nz*BK))*BK;
        k0=blockIdx.z*kChunk; k1=min(Kd,k0+kChunk);
        C += (size_t)blockIdx.z*(size_t)M*(size_t)ldc;
    }
    const int tx=tid%(BN/TN), ty=tid/(BN/TN);
    float acc[TM][TN];
#pragma unroll
    for(int i=0;i<TM;i++)
#pragma unroll
        for(int j=0;j<TN;j++) acc[i][j]=0.f;

    for(int kb=k0; kb<k1; kb+=BK){
        for(int i=tid;i<BM*BK;i+=THREADS){
            int m=i/BK, kk=i%BK; int gm=bm+m, gk=kb+kk;
            As[kk][m]=(gm<M && gk<k1)? A[(size_t)gm*lda+gk] : 0.f;
        }
        for(int i=tid;i<BN*BK;i+=THREADS){
            int n=i/BK, kk=i%BK; int gn=bn+n, gk=kb+kk;
            Bs[kk][n]=(gn<N && gk<k1)? B[(size_t)gn*ldb+gk] : 0.f;
        }
        __syncthreads();
#pragma unroll
        for(int kk=0;kk<BK;kk++){
            float ar[TM],br[TN];
#pragma unroll
            for(int i=0;i<TM;i++) ar[i]=As[kk][ty*TM+i];
#pragma unroll
            for(int j=0;j<TN;j++) br[j]=Bs[kk][tx*TN+j];
#pragma unroll
            for(int i=0;i<TM;i++)
#pragma unroll
                for(int j=0;j<TN;j++) acc[i][j]=fmaf(ar[i],br[j],acc[i][j]);
        }
        __syncthreads();
    }
    const bool raw=(nz>1);
#pragma unroll
    for(int i=0;i<TM;i++){
        int gm=bm+ty*TM+i; if(gm>=M) continue;
#pragma unroll
        for(int j=0;j<TN;j++){
            int gn=bn+tx*TN+j; if(gn>=N) continue;
            float v=acc[i][j];
            if(!raw){
                if(bias1) v+=bias1[gn];
                if(bias2) v+=bias2[gn];
                if(op==1) v=fmaxf(v,0.f);
                else if(op==2) v=expf(v);
            }
            C[(size_t)gm*ldc+gn]=v;
        }
    }
}

__global__ void reduce_split(const float* __restrict__ parts,int splits,int total,int N,
                             const float* __restrict__ bias1,const float* __restrict__ bias2,
                             float* __restrict__ out)
{
    int i=blockIdx.x*blockDim.x+threadIdx.x;
    if(i>=total) return;
    float v=0.f;
    for(int z=0;z<splits;z++) v+=parts[(size_t)z*total+i];
    if(bias1) v+=bias1[i%N];
    if(bias2) v+=bias2[i%N];
    out[i]=v;
}

// ---------------- prep: alpha transpose + Whh transpose ----------------
__global__ void prep_kernel(const float* __restrict__ mu_q_alpha,
                            const float* __restrict__ whh)
{
    int i=blockIdx.x*blockDim.x+threadIdx.x;
    if(i < TT*KT*RHOD){
        int r=i%RHOD; int tk=i/RHOD; int k=tk%KT, t=tk/KT;
        g_alphas[i]=mu_q_alpha[((size_t)k*TT+t)*RHOD + r];
    }
    if(i < EHH*4*EHH){
        int k=i/(4*EHH), j=i%(4*EHH);
        g_WhhT[i]=whh[(size_t)j*EHH + k];
    }
}

// ---------------- kl_alpha: one block per (k,t) row ----------------
__global__ void kl_alpha_kernel(const float* __restrict__ mu,const float* __restrict__ ls)
{
    __shared__ float red[128];
    int b=blockIdx.x; int t=b%TT;
    const float* mup=mu+(size_t)b*RHOD;
    const float* lsp=ls+(size_t)b*RHOD;
    const float* mpv=mu+(size_t)(b-1)*RHOD;
    float s=0.f;
    for(int r=threadIdx.x;r<RHOD;r+=128){
        float m=mup[r], l=lsp[r];
        if(t==0) s += (expf(l)+m*m)/(1.f+EPSF) - 1.f - l;
        else { float d=m-mpv[r]; s += (expf(l)+d*d)/(DELTAF+EPSF) - 1.f + LOG_DELTA_F - l; }
    }
    red[threadIdx.x]=s; __syncthreads();
    for(int off=64;off>0;off>>=1){ if(threadIdx.x<off) red[threadIdx.x]+=red[threadIdx.x+off]; __syncthreads(); }
    if(threadIdx.x==0) g_pa[b]=0.5f*red[0];
}

// ---------------- row sums of E ----------------
__global__ void rowsum_kernel()
{
    __shared__ float red[256];
    int r=blockIdx.x;
    const float* row=g_E+(size_t)r*VV;
    float s=0.f;
    for(int v=threadIdx.x;v<VV;v+=256) s+=row[v];
    red[threadIdx.x]=s; __syncthreads();
    for(int off=128;off>0;off>>=1){ if(threadIdx.x<off) red[threadIdx.x]+=red[threadIdx.x+off]; __syncthreads(); }
    if(threadIdx.x==0) g_invZ[r]=1.f/red[0];
}

// ---------------- LSTM: one block per source ----------------
__global__ void __launch_bounds__(4*EHH) lstm_kernel()
{
    __shared__ float hsm[EHH];
    __shared__ float zsm[4*EHH];
    const int s=blockIdx.x, j=threadIdx.x;
    float c=0.f;
    if(j<EHH) hsm[j]=0.f;
    __syncthreads();
    for(int t=0;t<TT;t++){
        float acc=g_xz[((size_t)s*TT+t)*(4*EHH)+j];
#pragma unroll 4
        for(int k=0;k<EHH;k++) acc=fmaf(hsm[k], g_WhhT[k*(4*EHH)+j], acc);
        zsm[j]=acc;
        __syncthreads();
        if(j<EHH){
            float ig=sigm_(zsm[j]), fg=sigm_(zsm[EHH+j]);
            float gg=tanhf(zsm[2*EHH+j]), og=sigm_(zsm[3*EHH+j]);
            c=fg*c+ig*gg;
            float h=og*tanhf(c);
            hsm[j]=h;
            g_lstm_out[((size_t)t*SSRC+s)*EHH+j]=h;
        }
        __syncthreads();
    }
}

// ---------------- eta: lstm-part of heads ----------------
__global__ void eta_base_kernel(const float* __restrict__ muW,const float* __restrict__ lsW)
{
    int i=blockIdx.x*blockDim.x+threadIdx.x;
    if(i>=TT*SSRC*KT) return;
    int k=i%KT; int ts=i/KT;
    const float* h=g_lstm_out+(size_t)ts*EHH;
    const float* wm=muW+(size_t)k*(EHH+KT);
    const float* wl=lsW+(size_t)k*(EHH+KT);
    float am=0.f, al=0.f;
    for(int j=0;j<EHH;j++){ float hv=h[j]; am=fmaf(hv,wm[j],am); al=fmaf(hv,wl[j],al); }
    g_base_mu[i]=am; g_base_ls[i]=al;
}

// ---------------- eta recurrence + kl_eta ----------------
__global__ void __launch_bounds__(512) eta_rec_kernel(const float* __restrict__ muW,const float* __restrict__ lsW,
                                                      const float* __restrict__ mub,const float* __restrict__ lsb)
{
    __shared__ float eprev[SSRC*KT];
    __shared__ float red[512];
    const int tid=threadIdx.x;
    const int s=tid/KT, k=tid%KT;
    const bool act = tid < SSRC*KT;
    float kl=0.f;
    if(act){
        float m=g_base_mu[tid]+mub[k];
        float l=g_base_ls[tid]+lsb[k];            // t=0: no clip
        kl += (expf(l)+m*m)/(1.f+EPSF) - 1.f - l;
        eprev[tid]=m;
        g_etas[((size_t)s*TT+0)*KT+k]=m;
    }
    __syncthreads();
    for(int t=1;t<TT;t++){
        float m=0.f;
        if(act){
            m=g_base_mu[(size_t)t*SSRC*KT+tid]+mub[k];
            float l=g_base_ls[(size_t)t*SSRC*KT+tid]+lsb[k];
            const float* er=eprev+s*KT;
            const float* wm=muW+(size_t)k*(EHH+KT)+EHH;
            const float* wl=lsW+(size_t)k*(EHH+KT)+EHH;
#pragma unroll
            for(int k2=0;k2<KT;k2++){ float e=er[k2]; m=fmaf(e,wm[k2],m); l=fmaf(e,wl[k2],l); }
            l=fminf(fmaxf(l,-10.f),10.f);
            float d=m-eprev[tid];
            kl += (expf(l)+d*d)/(DELTAF+EPSF) - 1.f + LOG_DELTA_F - l;
        }
        __syncthreads();
        if(act){ eprev[tid]=m; g_etas[((size_t)s*TT+t)*KT+k]=m; }
        __syncthreads();
    }
    red[tid]=kl; __syncthreads();
    for(int off=256;off>0;off>>=1){ if(tid<off) red[tid]+=red[tid+off]; __syncthreads(); }
    if(tid==0) g_kleta[0]=0.5f*red[0];
}

__global__ void gather_eta(const int* __restrict__ sources,const int* __restrict__ times)
{
    int i=blockIdx.x*blockDim.x+threadIdx.x;
    if(i>=BB*KT) return;
    int b=i/KT, k=i%KT;
    g_eta_std[i]=g_etas[((size_t)sources[b]*TT+times[b])*KT+k];
}

// ---------------- h1 epilogue: reduce splitK + eta part + bias + relu ----------------
__global__ void h1_epilogue(const float* __restrict__ W1,const float* __restrict__ b1)
{
    int i=blockIdx.x*blockDim.x+threadIdx.x;
    if(i>=BB*THH) return;
    int b=i/THH, j=i%THH;
    float v=0.f;
    for(int z=0;z<16;z++) v+=g_part4[(size_t)z*BB*THH+i];
    v+=b1[j];
    const float* w=W1+(size_t)j*(VV+KT)+VV;
    const float* e=g_eta_std+(size_t)b*KT;
#pragma unroll
    for(int k=0;k<KT;k++) v=fmaf(e[k],w[k],v);
    g_h1[i]=fmaxf(v,0.f);
}

// ---------------- theta heads ----------------
__global__ void theta_head(const float* __restrict__ muW,const float* __restrict__ mub,
                           const float* __restrict__ lsW,const float* __restrict__ lsb)
{
    int i=blockIdx.x*blockDim.x+threadIdx.x;
    if(i>=BB*KT) return;
    int b=i/KT, k=i%KT;
    const float* h=g_h2+(size_t)b*THH;
    const float* wm=muW+(size_t)k*THH;
    const float* wl=lsW+(size_t)k*THH;
    float am=mub[k], al=lsb[k];
    for(int j=0;j<THH;j++){ float hv=h[j]; am=fmaf(hv,wm[j],am); al=fmaf(hv,wl[j],al); }
    g_mu_t[i]=am;
    g_ls_t[i]=fminf(fmaxf(al,-10.f),10.f);
}

// ---------------- softmax(theta) + kl_theta per doc ----------------
__global__ void softmax_kltheta()
{
    __shared__ float red[64];
    const int b=blockIdx.x, tid=threadIdx.x;
    float m=(tid<KT)? g_mu_t[(size_t)b*KT+tid] : -1e30f;
    red[tid]=m; __syncthreads();
    for(int off=32;off>0;off>>=1){ if(tid<off) red[tid]=fmaxf(red[tid],red[tid+off]); __syncthreads(); }
    float mx=red[0]; __syncthreads();
    float e=(tid<KT)? expf(m-mx) : 0.f;
    red[tid]=e; __syncthreads();
    for(int off=32;off>0;off>>=1){ if(tid<off) red[tid]+=red[tid+off]; __syncthreads(); }
    float Z=red[0]; __syncthreads();
    if(tid<KT) g_theta[(size_t)b*KT+tid]=e/Z;
    float term=0.f;
    if(tid<KT){
        float l=g_ls_t[(size_t)b*KT+tid];
        float d=m-g_eta_std[(size_t)b*KT+tid];
        term=(expf(l)+d*d)/(1.f+EPSF)-1.f-l;
    }
    red[tid]=term; __syncthreads();
    for(int off=32;off>0;off>>=1){ if(tid<off) red[tid]+=red[tid+off]; __syncthreads(); }
    if(tid==0) g_pth[b]=0.5f*red[0];
}

// ---------------- source prediction loss per doc ----------------
__global__ void pred_kernel(const float* __restrict__ clsW,const float* __restrict__ clsb,
                            const int* __restrict__ sources)
{
    int b=blockIdx.x*blockDim.x+threadIdx.x;
    if(b>=BB) return;
    const float* th=g_theta+(size_t)b*KT;
    float lg[SSRC], mx=-1e30f;
#pragma unroll
    for(int i=0;i<SSRC;i++){
        float a=clsb[i];
        const float* w=clsW+(size_t)i*KT;
#pragma unroll
        for(int k=0;k<KT;k++) a=fmaf(th[k],w[k],a);
        lg[i]=a; mx=fmaxf(mx,a);
    }
    float se=0.f;
#pragma unroll
    for(int i=0;i<SSRC;i++) se+=expf(lg[i]-mx);
    float lse=mx+logf(se);
    g_ppred[b]=lse-lg[sources[b]];   // -logp[source]
}

// ---------------- NLL: one block per doc ----------------
__global__ void __launch_bounds__(256) nll_kernel(const float* __restrict__ bows,
                                                  const int* __restrict__ times)
{
    __shared__ float w[KT];
    __shared__ float red[256];
    const int b=blockIdx.x, tid=threadIdx.x;
    const int t=times[b];
    if(tid<KT) w[tid]=g_theta[(size_t)b*KT+tid]*g_invZ[t*KT+tid];
    __syncthreads();
    const float* Eb=g_E+(size_t)t*KT*VV;
    const float* bw=bows+(size_t)b*VV;
    float s=0.f;
    for(int v=tid; v<VV; v+=256){
        float mix=0.f;
#pragma unroll
        for(int k=0;k<KT;k++) mix=fmaf(w[k], Eb[(size_t)k*VV+v], mix);
        s=fmaf(logf(mix), bw[v], s);
    }
    red[tid]=s; __syncthreads();
    for(int off=128;off>0;off>>=1){ if(tid<off) red[tid]+=red[tid+off]; __syncthreads(); }
    if(tid==0) g_pnll[b]=red[0];
}

// ---------------- final combine ----------------
__global__ void __launch_bounds__(256) final_kernel(const void* __restrict__ ndocs_ptr,
                                                    float* __restrict__ out)
{
    __shared__ float red[256];
    const int tid=threadIdx.x;
    float sa=0.f;
    for(int i=tid;i<KT*TT;i+=256) sa+=g_pa[i];
    red[tid]=sa; __syncthreads();
    for(int off=128;off>0;off>>=1){ if(tid<off) red[tid]+=red[tid+off]; __syncthreads(); }
    float kl_alpha=red[0]; __syncthreads();

    red[tid]=g_pnll[tid]; __syncthreads();
    for(int off=128;off>0;off>>=1){ if(tid<off) red[tid]+=red[tid+off]; __syncthreads(); }
    float sum_ll=red[0]; __syncthreads();

    red[tid]=g_pth[tid]; __syncthreads();
    for(int off=128;off>0;off>>=1){ if(tid<off) red[tid]+=red[tid+off]; __syncthreads(); }
    float sum_th=red[0]; __syncthreads();

    red[tid]=g_ppred[tid]; __syncthreads();
    for(int off=128;off>0;off>>=1){ if(tid<off) red[tid]+=red[tid+off]; __syncthreads(); }
    float sum_pred=red[0]; __syncthreads();

    if(tid==0){
        int v0=*(const int*)ndocs_ptr;
        float nd;
        if(v0>0 && v0<(1<<30)) nd=(float)v0;
        else nd=*(const float*)ndocs_ptr;
        float coeff=nd/(float)BB;
        float nll=-sum_ll*coeff;
        float kl_eta=g_kleta[0];
        float kl_theta=sum_th*coeff;
        float pred=sum_pred*coeff;
        float nelbo=nll+kl_alpha+kl_eta+kl_theta+pred;
        out[0]=nelbo; out[1]=nll; out[2]=kl_alpha;
        out[3]=kl_eta; out[4]=kl_theta; out[5]=pred;
    }
}

// ---------------- launcher ----------------
extern "C" void kernel_launch(void* const* d_in, const int* in_sizes, int n_in,
                              void* d_out, int out_size)
{
    const float* bows      =(const float*)d_in[1];
    const float* nbows     =(const float*)d_in[2];
    const int*   times     =(const int*)  d_in[3];
    const int*   sources   =(const int*)  d_in[4];
    const float* rnn_inp   =(const float*)d_in[5];
    const void*  num_docs  =               d_in[6];
    const float* mu_q_alpha=(const float*)d_in[7];
    const float* ls_q_alpha=(const float*)d_in[8];
    const float* rho_W     =(const float*)d_in[9];
    const float* W1        =(const float*)d_in[10];
    const float* b1        =(const float*)d_in[11];
    const float* W2        =(const float*)d_in[12];
    const float* b2        =(const float*)d_in[13];
    const float* mu_th_W   =(const float*)d_in[14];
    const float* mu_th_b   =(const float*)d_in[15];
    const float* ls_th_W   =(const float*)d_in[16];
    const float* ls_th_b   =(const float*)d_in[17];
    const float* eta_map_W =(const float*)d_in[18];
    const float* eta_map_b =(const float*)d_in[19];
    const float* lstm_Wih  =(const float*)d_in[20];
    const float* lstm_Whh  =(const float*)d_in[21];
    const float* lstm_bih  =(const float*)d_in[22];
    const float* lstm_bhh  =(const float*)d_in[23];
    const float* mu_eta_W  =(const float*)d_in[24];
    const float* mu_eta_b  =(const float*)d_in[25];
    const float* ls_eta_W  =(const float*)d_in[26];
    const float* ls_eta_b  =(const float*)d_in[27];
    const float* cls_W     =(const float*)d_in[28];
    const float* cls_b     =(const float*)d_in[29];
    float* out=(float*)d_out;

    float *alphas,*E,*part1,*mapped,*xz,*part4,*h1,*h2;
    cudaGetSymbolAddress((void**)&alphas,g_alphas);
    cudaGetSymbolAddress((void**)&E,g_E);
    cudaGetSymbolAddress((void**)&part1,g_part1);
    cudaGetSymbolAddress((void**)&mapped,g_mapped);
    cudaGetSymbolAddress((void**)&xz,g_xz);
    cudaGetSymbolAddress((void**)&part4,g_part4);
    cudaGetSymbolAddress((void**)&h1,g_h1);
    cudaGetSymbolAddress((void**)&h2,g_h2);

    // prep
    prep_kernel<<<(TT*KT*RHOD+255)/256,256>>>(mu_q_alpha, lstm_Whh);
    kl_alpha_kernel<<<KT*TT,128>>>(mu_q_alpha, ls_q_alpha);

    // ---- beta path: E = exp(alphas @ rho_W^T), invZ = 1/rowsum ----
    {
        dim3 g((VV+63)/64,(TT*KT+63)/64,1);
        sgemm_nt<64,64,16,4,4><<<g,256>>>(TT*KT,VV,RHOD, alphas,RHOD, rho_W,RHOD,
                                          E,VV, nullptr,nullptr, 2);
    }
    rowsum_kernel<<<TT*KT,256>>>();

    // ---- eta path ----
    {   // mapped = rnn_inp @ eta_map_W^T + b   (splitK=8)
        dim3 g((EHH+63)/64,(500+63)/64,8);
        sgemm_nt<64,64,16,4,4><<<g,256>>>(500,EHH,VV, rnn_inp,VV, eta_map_W,VV,
                                          part1,EHH, nullptr,nullptr, 0);
        reduce_split<<<(500*EHH+255)/256,256>>>(part1,8,500*EHH,EHH, eta_map_b,nullptr, mapped);
    }
    {   // xz = mapped @ Wih^T + bih + bhh
        dim3 g((4*EHH+63)/64,(500+63)/64,1);
        sgemm_nt<64,64,16,4,4><<<g,256>>>(500,4*EHH,EHH, mapped,EHH, lstm_Wih,EHH,
                                          xz,4*EHH, lstm_bih,lstm_bhh, 0);
    }
    lstm_kernel<<<SSRC,4*EHH>>>();
    eta_base_kernel<<<(TT*SSRC*KT+255)/256,256>>>(mu_eta_W, ls_eta_W);
    eta_rec_kernel<<<1,512>>>(mu_eta_W, ls_eta_W, mu_eta_b, ls_eta_b);
    gather_eta<<<(BB*KT+255)/256,256>>>(sources, times);

    // ---- theta path ----
    {   // h1 bow-part, splitK=16 over V
        dim3 g((THH+63)/64,(BB+63)/64,16);
        sgemm_nt<64,64,16,4,4><<<g,256>>>(BB,THH,VV, nbows,VV, W1,VV+KT,
                                          part4,THH, nullptr,nullptr, 0);
    }
    h1_epilogue<<<(BB*THH+255)/256,256>>>(W1, b1);
    {   // h2
        dim3 g((THH+63)/64,(BB+63)/64,1);
        sgemm_nt<64,64,16,4,4><<<g,256>>>(BB,THH,THH, h1,THH, W2,THH,
                                          h2,THH, b2,nullptr, 1);
    }
    theta_head<<<(BB*KT+255)/256,256>>>(mu_th_W,mu_th_b, ls_th_W,ls_th_b);
    softmax_kltheta<<<BB,64>>>();
    pred_kernel<<<1,BB>>>(cls_W, cls_b, sources);

    // ---- NLL ----
    nll_kernel<<<BB,256>>>(bows, times);

    // ---- combine ----
    final_kernel<<<1,256>>>(num_docs, out);
    (void)in_sizes; (void)n_in; (void)out_size;
}

// round 4
// speedup vs baseline: 1.3931x; 1.3931x over previous
#include <cuda_runtime.h>
#include <math.h>

#define KT   50
#define TT   50
#define RHOD 300
#define RHOP 304            // padded K for E gemm
#define VV   20000
#define THH  800
#define EHH  200
#define SSRC 10
#define BB   256
#define DELTAF 0.005f
#define LOG_DELTA_F (-5.2983173665480363f)
#define EPSF 1e-6f
#define NVTILE 20           // 20 x 1024 >= 20000

// ---------------- device scratch ----------------
__device__ __align__(16) float g_alphas[TT*KT*RHOP];
__device__ __align__(16) float g_rhoP[(size_t)VV*RHOP];
__device__ __align__(16) float g_w1c[(size_t)THH*VV];
__device__ __align__(16) float g_E[(size_t)TT*KT*VV];     // 200MB
__device__ float g_invZ[TT*KT];
__device__ __align__(16) float g_part1[24*500*EHH];
__device__ __align__(16) float g_partx[4*500*4*EHH];
__device__ __align__(16) float g_mapped[500*EHH];
__device__ __align__(16) float g_xz[500*4*EHH];
__device__ float g_WhhT[EHH*4*EHH];
__device__ float g_lstm_out[TT*SSRC*EHH];
__device__ float g_base_mu[TT*SSRC*KT];
__device__ float g_base_ls[TT*SSRC*KT];
__device__ float g_etas[SSRC*TT*KT];
__device__ float g_eta_std[BB*KT];
__device__ __align__(16) float g_part4[16*BB*THH];
__device__ __align__(16) float g_part5[8*BB*THH];
__device__ __align__(16) float g_h1[BB*THH];
__device__ __align__(16) float g_h2[BB*THH];
__device__ float g_mu_t[BB*KT];
__device__ float g_ls_t[BB*KT];
__device__ float g_theta[BB*KT];
__device__ float g_wdoc[BB*KT];
__device__ float g_metaT[EHH*KT];
__device__ float g_letaT[EHH*KT];
__device__ float g_mthT[THH*KT];
__device__ float g_lthT[THH*KT];
__device__ int   g_dlist[TT*BB];
__device__ int   g_dcnt[TT];
__device__ float g_pa[KT*TT];
__device__ float g_pnllT[TT*NVTILE];
__device__ float g_pth[BB];
__device__ float g_ppred[BB];
__device__ float g_kleta[1];

__device__ __forceinline__ float sigm_(float x){ return 1.f/(1.f+expf(-x)); }

// ============ fast NT SGEMM: C[m,n] = sum_k A[m,k]*B[n,k] ============
// 128x128 tile, BK=8, TM=TN=8, 256 threads, float4 global loads.
// REQUIREMENTS: lda%4==0, ldb%4==0, base ptrs 16B aligned, and every
// k-range handled (full K or each split chunk) is a multiple of 8.
// OP: 0 none, 1 relu, 2 exp. splitK (gridDim.z>1) writes raw partials.
template<int OP>
__global__ void __launch_bounds__(256)
sgemm128(int M,int N,int Kd,
         const float* __restrict__ A,int lda,
         const float* __restrict__ B,int ldb,
         float* __restrict__ C,int ldc,
         const float* __restrict__ bias1,const float* __restrict__ bias2)
{
    __shared__ float As[8][128];
    __shared__ float Bs[8][128];
    const int tid=threadIdx.x;
    const int bm=blockIdx.y*128, bn=blockIdx.x*128;
    int k0=0,k1=Kd;
    const int nz=gridDim.z;
    if(nz>1){
        int kChunk=((Kd + nz*8 - 1)/(nz*8))*8;
        k0=blockIdx.z*kChunk; k1=min(Kd,k0+kChunk);
        C += (size_t)blockIdx.z*(size_t)M*(size_t)ldc;
    }
    const int lr=tid>>1, kq=(tid&1)*4;   // load row, k-quad
    const int tx=tid&15, ty=tid>>4;
    float acc[8][8];
#pragma unroll
    for(int i=0;i<8;i++)
#pragma unroll
        for(int j=0;j<8;j++) acc[i][j]=0.f;

    const bool aval=(bm+lr)<M, bval=(bn+lr)<N;
    const float* Ap=A+(size_t)(bm+lr)*lda;
    const float* Bp=B+(size_t)(bn+lr)*ldb;

    for(int kb=k0;kb<k1;kb+=8){
        float4 av=aval? *(const float4*)(Ap+kb+kq) : make_float4(0.f,0.f,0.f,0.f);
        float4 bv=bval? *(const float4*)(Bp+kb+kq) : make_float4(0.f,0.f,0.f,0.f);
        __syncthreads();
        As[kq+0][lr]=av.x; As[kq+1][lr]=av.y; As[kq+2][lr]=av.z; As[kq+3][lr]=av.w;
        Bs[kq+0][lr]=bv.x; Bs[kq+1][lr]=bv.y; Bs[kq+2][lr]=bv.z; Bs[kq+3][lr]=bv.w;
        __syncthreads();
#pragma unroll
        for(int kk=0;kk<8;kk++){
            float ar[8],br[8];
#pragma unroll
            for(int i=0;i<8;i++) ar[i]=As[kk][ty*8+i];
#pragma unroll
            for(int j=0;j<8;j++) br[j]=Bs[kk][tx*8+j];
#pragma unroll
            for(int i=0;i<8;i++)
#pragma unroll
                for(int j=0;j<8;j++) acc[i][j]=fmaf(ar[i],br[j],acc[i][j]);
        }
    }
    const bool raw=(nz>1);
#pragma unroll
    for(int i=0;i<8;i++){
        int gm=bm+ty*8+i; if(gm>=M) continue;
#pragma unroll
        for(int j=0;j<8;j++){
            int gn=bn+tx*8+j; if(gn>=N) continue;
            float v=acc[i][j];
            if(!raw){
                if(bias1) v+=bias1[gn];
                if(bias2) v+=bias2[gn];
                if(OP==1) v=fmaxf(v,0.f);
                else if(OP==2) v=expf(v);
            }
            C[(size_t)gm*ldc+gn]=v;
        }
    }
}

__global__ void reduce_split(const float* __restrict__ parts,int splits,int total,int N,
                             const float* __restrict__ bias1,const float* __restrict__ bias2,
                             int op, float* __restrict__ out)
{
    int i=blockIdx.x*blockDim.x+threadIdx.x;
    if(i>=total) return;
    float v=0.f;
    for(int z=0;z<splits;z++) v+=parts[(size_t)z*total+i];
    if(bias1) v+=bias1[i%N];
    if(bias2) v+=bias2[i%N];
    if(op==1) v=fmaxf(v,0.f);
    out[i]=v;
}

// ---------------- prep: padded alpha transpose + Whh transpose ----------------
__global__ void prep_kernel(const float* __restrict__ mu_q_alpha,
                            const float* __restrict__ whh)
{
    int i=blockIdx.x*blockDim.x+threadIdx.x;
    if(i < TT*KT*RHOP){
        int r=i%RHOP; int tk=i/RHOP; int k=tk%KT, t=tk/KT;
        g_alphas[i]=(r<RHOD)? mu_q_alpha[((size_t)k*TT+t)*RHOD + r] : 0.f;
    }
    if(i < EHH*4*EHH){
        int k=i/(4*EHH), j=i%(4*EHH);
        g_WhhT[i]=whh[(size_t)j*EHH + k];
    }
}

__global__ void rhopad_kernel(const float* __restrict__ rho)
{
    int i=blockIdx.x*blockDim.x+threadIdx.x;
    if(i>=VV*RHOP) return;
    int v=i/RHOP, r=i%RHOP;
    g_rhoP[i]=(r<RHOD)? rho[(size_t)v*RHOD+r] : 0.f;
}

__global__ void w1copy_kernel(const float* __restrict__ W1)
{
    int i=blockIdx.x*blockDim.x+threadIdx.x;
    if(i>=THH*(VV/2)) return;
    int j=i/(VV/2), vh=i%(VV/2);
    float2 s=*(const float2*)(W1+(size_t)j*(VV+KT)+ (size_t)vh*2);
    *(float2*)(g_w1c+(size_t)j*VV+(size_t)vh*2)=s;
}

__global__ void transpose_heads(const float* __restrict__ muEta,const float* __restrict__ lsEta,
                                const float* __restrict__ muTh,const float* __restrict__ lsTh)
{
    int i=blockIdx.x*blockDim.x+threadIdx.x;
    if(i<KT*EHH){
        int k=i/EHH, j=i%EHH;
        g_metaT[j*KT+k]=muEta[(size_t)k*(EHH+KT)+j];
        g_letaT[j*KT+k]=lsEta[(size_t)k*(EHH+KT)+j];
    }
    if(i<KT*THH){
        int k=i/THH, j=i%THH;
        g_mthT[j*KT+k]=muTh[(size_t)k*THH+j];
        g_lthT[j*KT+k]=lsTh[(size_t)k*THH+j];
    }
}

// ---------------- kl_alpha ----------------
__global__ void kl_alpha_kernel(const float* __restrict__ mu,const float* __restrict__ ls)
{
    __shared__ float red[128];
    int b=blockIdx.x; int t=b%TT;
    const float* mup=mu+(size_t)b*RHOD;
    const float* lsp=ls+(size_t)b*RHOD;
    const float* mpv=mu+(size_t)(b-1)*RHOD;
    float s=0.f;
    for(int r=threadIdx.x;r<RHOD;r+=128){
        float m=mup[r], l=lsp[r];
        if(t==0) s += (expf(l)+m*m)/(1.f+EPSF) - 1.f - l;
        else { float d=m-mpv[r]; s += (expf(l)+d*d)/(DELTAF+EPSF) - 1.f + LOG_DELTA_F - l; }
    }
    red[threadIdx.x]=s; __syncthreads();
    for(int off=64;off>0;off>>=1){ if(threadIdx.x<off) red[threadIdx.x]+=red[threadIdx.x+off]; __syncthreads(); }
    if(threadIdx.x==0) g_pa[b]=0.5f*red[0];
}

// ---------------- row sums of E ----------------
__global__ void rowsum_kernel()
{
    __shared__ float red[256];
    int r=blockIdx.x;
    const float* row=g_E+(size_t)r*VV;
    float s=0.f;
    for(int v=threadIdx.x;v<VV;v+=256) s+=row[v];
    red[threadIdx.x]=s; __syncthreads();
    for(int off=128;off>0;off>>=1){ if(threadIdx.x<off) red[threadIdx.x]+=red[threadIdx.x+off]; __syncthreads(); }
    if(threadIdx.x==0) g_invZ[r]=1.f/red[0];
}

// ---------------- LSTM ----------------
__global__ void __launch_bounds__(4*EHH) lstm_kernel()
{
    __shared__ float hsm[EHH];
    __shared__ float zsm[4*EHH];
    const int s=blockIdx.x, j=threadIdx.x;
    float c=0.f;
    if(j<EHH) hsm[j]=0.f;
    __syncthreads();
    for(int t=0;t<TT;t++){
        float acc=g_xz[((size_t)s*TT+t)*(4*EHH)+j];
#pragma unroll 4
        for(int k=0;k<EHH;k++) acc=fmaf(hsm[k], g_WhhT[k*(4*EHH)+j], acc);
        zsm[j]=acc;
        __syncthreads();
        if(j<EHH){
            float ig=sigm_(zsm[j]), fg=sigm_(zsm[EHH+j]);
            float gg=tanhf(zsm[2*EHH+j]), og=sigm_(zsm[3*EHH+j]);
            c=fg*c+ig*gg;
            float h=og*tanhf(c);
            hsm[j]=h;
            g_lstm_out[((size_t)t*SSRC+s)*EHH+j]=h;
        }
        __syncthreads();
    }
}

// ---------------- eta base (coalesced via transposed weights) ----------------
__global__ void eta_base_kernel()
{
    int i=blockIdx.x*blockDim.x+threadIdx.x;
    if(i>=TT*SSRC*KT) return;
    int k=i%KT; int ts=i/KT;
    const float* h=g_lstm_out+(size_t)ts*EHH;
    float am=0.f, al=0.f;
    for(int j=0;j<EHH;j++){
        float hv=h[j];
        am=fmaf(hv,g_metaT[j*KT+k],am);
        al=fmaf(hv,g_letaT[j*KT+k],al);
    }
    g_base_mu[i]=am; g_base_ls[i]=al;
}

// ---------------- eta recurrence + kl_eta ----------------
__global__ void __launch_bounds__(512) eta_rec_kernel(const float* __restrict__ muW,const float* __restrict__ lsW,
                                                      const float* __restrict__ mub,const float* __restrict__ lsb)
{
    __shared__ float eprev[SSRC*KT];
    __shared__ float red[512];
    const int tid=threadIdx.x;
    const int s=tid/KT, k=tid%KT;
    const bool act = tid < SSRC*KT;
    float kl=0.f;
    if(act){
        float m=g_base_mu[tid]+mub[k];
        float l=g_base_ls[tid]+lsb[k];            // t=0: no clip
        kl += (expf(l)+m*m)/(1.f+EPSF) - 1.f - l;
        eprev[tid]=m;
        g_etas[((size_t)s*TT+0)*KT+k]=m;
    }
    __syncthreads();
    for(int t=1;t<TT;t++){
        float m=0.f;
        if(act){
            m=g_base_mu[(size_t)t*SSRC*KT+tid]+mub[k];
            float l=g_base_ls[(size_t)t*SSRC*KT+tid]+lsb[k];
            const float* er=eprev+s*KT;
            const float* wm=muW+(size_t)k*(EHH+KT)+EHH;
            const float* wl=lsW+(size_t)k*(EHH+KT)+EHH;
#pragma unroll
            for(int k2=0;k2<KT;k2++){ float e=er[k2]; m=fmaf(e,wm[k2],m); l=fmaf(e,wl[k2],l); }
            l=fminf(fmaxf(l,-10.f),10.f);
            float d=m-eprev[tid];
            kl += (expf(l)+d*d)/(DELTAF+EPSF) - 1.f + LOG_DELTA_F - l;
        }
        __syncthreads();
        if(act){ eprev[tid]=m; g_etas[((size_t)s*TT+t)*KT+k]=m; }
        __syncthreads();
    }
    red[tid]=kl; __syncthreads();
    for(int off=256;off>0;off>>=1){ if(tid<off) red[tid]+=red[tid+off]; __syncthreads(); }
    if(tid==0) g_kleta[0]=0.5f*red[0];
}

__global__ void gather_eta(const int* __restrict__ sources,const int* __restrict__ times)
{
    int i=blockIdx.x*blockDim.x+threadIdx.x;
    if(i>=BB*KT) return;
    int b=i/KT, k=i%KT;
    g_eta_std[i]=g_etas[((size_t)sources[b]*TT+times[b])*KT+k];
}

// ---------------- h1 epilogue ----------------
__global__ void h1_epilogue(const float* __restrict__ W1,const float* __restrict__ b1)
{
    int i=blockIdx.x*blockDim.x+threadIdx.x;
    if(i>=BB*THH) return;
    int b=i/THH, j=i%THH;
    float v=0.f;
    for(int z=0;z<16;z++) v+=g_part4[(size_t)z*BB*THH+i];
    v+=b1[j];
    const float* w=W1+(size_t)j*(VV+KT)+VV;
    const float* e=g_eta_std+(size_t)b*KT;
#pragma unroll
    for(int k=0;k<KT;k++) v=fmaf(e[k],w[k],v);
    g_h1[i]=fmaxf(v,0.f);
}

// ---------------- theta heads (transposed weights) ----------------
__global__ void theta_head(const float* __restrict__ mub,const float* __restrict__ lsb)
{
    int i=blockIdx.x*blockDim.x+threadIdx.x;
    if(i>=BB*KT) return;
    int b=i/KT, k=i%KT;
    const float* h=g_h2+(size_t)b*THH;
    float am=mub[k], al=lsb[k];
    for(int j=0;j<THH;j++){
        float hv=h[j];
        am=fmaf(hv,g_mthT[j*KT+k],am);
        al=fmaf(hv,g_lthT[j*KT+k],al);
    }
    g_mu_t[i]=am;
    g_ls_t[i]=fminf(fmaxf(al,-10.f),10.f);
}

// ---------------- softmax(theta) + kl_theta ----------------
__global__ void softmax_kltheta()
{
    __shared__ float red[64];
    const int b=blockIdx.x, tid=threadIdx.x;
    float m=(tid<KT)? g_mu_t[(size_t)b*KT+tid] : -1e30f;
    red[tid]=m; __syncthreads();
    for(int off=32;off>0;off>>=1){ if(tid<off) red[tid]=fmaxf(red[tid],red[tid+off]); __syncthreads(); }
    float mx=red[0]; __syncthreads();
    float e=(tid<KT)? expf(m-mx) : 0.f;
    red[tid]=e; __syncthreads();
    for(int off=32;off>0;off>>=1){ if(tid<off) red[tid]+=red[tid+off]; __syncthreads(); }
    float Z=red[0]; __syncthreads();
    if(tid<KT) g_theta[(size_t)b*KT+tid]=e/Z;
    float term=0.f;
    if(tid<KT){
        float l=g_ls_t[(size_t)b*KT+tid];
        float d=m-g_eta_std[(size_t)b*KT+tid];
        term=(expf(l)+d*d)/(1.f+EPSF)-1.f-l;
    }
    red[tid]=term; __syncthreads();
    for(int off=32;off>0;off>>=1){ if(tid<off) red[tid]+=red[tid+off]; __syncthreads(); }
    if(tid==0) g_pth[b]=0.5f*red[0];
}

// ---------------- source prediction loss ----------------
__global__ void pred_kernel(const float* __restrict__ clsW,const float* __restrict__ clsb,
                            const int* __restrict__ sources)
{
    int b=blockIdx.x*blockDim.x+threadIdx.x;
    if(b>=BB) return;
    const float* th=g_theta+(size_t)b*KT;
    float lg[SSRC], mx=-1e30f;
#pragma unroll
    for(int i=0;i<SSRC;i++){
        float a=clsb[i];
        const float* w=clsW+(size_t)i*KT;
#pragma unroll
        for(int k=0;k<KT;k++) a=fmaf(th[k],w[k],a);
        lg[i]=a; mx=fmaxf(mx,a);
    }
    float se=0.f;
#pragma unroll
    for(int i=0;i<SSRC;i++) se+=expf(lg[i]-mx);
    float lse=mx+logf(se);
    g_ppred[b]=lse-lg[sources[b]];
}

// ---------------- NLL v2: docs grouped by time ----------------
__global__ void wdoc_kernel(const int* __restrict__ times)
{
    int i=blockIdx.x*blockDim.x+threadIdx.x;
    if(i>=BB*KT) return;
    int b=i/KT, k=i%KT;
    g_wdoc[i]=g_theta[i]*g_invZ[times[b]*KT+k];
}

__global__ void doclist_kernel(const int* __restrict__ times)
{
    int t=threadIdx.x;
    if(t>=TT) return;
    int cnt=0;
    for(int b=0;b<BB;b++)
        if(times[b]==t) g_dlist[t*BB + (cnt++)]=b;
    g_dcnt[t]=cnt;
}

__global__ void __launch_bounds__(256) nll2_kernel(const float* __restrict__ bows)
{
    const int t=blockIdx.x, vt=blockIdx.y, tid=threadIdx.x;
    __shared__ float ws[32][KT];
    __shared__ int   dls[32];
    __shared__ float red[256];
    const int cnt=g_dcnt[t];
    float s=0.f;
    for(int d0=0; d0<cnt; d0+=32){
        int ch=min(32,cnt-d0);
        __syncthreads();
        for(int i=tid;i<ch*KT;i+=256){
            int d=i/KT, k=i%KT;
            int b=g_dlist[t*BB+d0+d];
            ws[d][k]=g_wdoc[(size_t)b*KT+k];
            if(k==0) dls[d]=b;
        }
        __syncthreads();
        for(int vi=0;vi<4;vi++){
            int v=vt*1024+vi*256+tid;
            if(v>=VV) break;
            float e[KT];
            const float* Ep=g_E+(size_t)t*KT*VV+v;
#pragma unroll
            for(int k=0;k<KT;k++) e[k]=Ep[(size_t)k*VV];
            for(int d=0;d<ch;d++){
                float mix=0.f;
#pragma unroll
                for(int k=0;k<KT;k++) mix=fmaf(ws[d][k],e[k],mix);
                s=fmaf(logf(mix), bows[(size_t)dls[d]*VV+v], s);
            }
        }
    }
    red[tid]=s; __syncthreads();
    for(int off=128;off>0;off>>=1){ if(tid<off) red[tid]+=red[tid+off]; __syncthreads(); }
    if(tid==0) g_pnllT[t*NVTILE+vt]=red[0];
}

// ---------------- final combine ----------------
__global__ void __launch_bounds__(256) final_kernel(const void* __restrict__ ndocs_ptr,
                                                    float* __restrict__ out)
{
    __shared__ float red[256];
    const int tid=threadIdx.x;
    float sa=0.f;
    for(int i=tid;i<KT*TT;i+=256) sa+=g_pa[i];
    red[tid]=sa; __syncthreads();
    for(int off=128;off>0;off>>=1){ if(tid<off) red[tid]+=red[tid+off]; __syncthreads(); }
    float kl_alpha=red[0]; __syncthreads();

    float sl=0.f;
    for(int i=tid;i<TT*NVTILE;i+=256) sl+=g_pnllT[i];
    red[tid]=sl; __syncthreads();
    for(int off=128;off>0;off>>=1){ if(tid<off) red[tid]+=red[tid+off]; __syncthreads(); }
    float sum_ll=red[0]; __syncthreads();

    red[tid]=g_pth[tid]; __syncthreads();
    for(int off=128;off>0;off>>=1){ if(tid<off) red[tid]+=red[tid+off]; __syncthreads(); }
    float sum_th=red[0]; __syncthreads();

    red[tid]=g_ppred[tid]; __syncthreads();
    for(int off=128;off>0;off>>=1){ if(tid<off) red[tid]+=red[tid+off]; __syncthreads(); }
    float sum_pred=red[0]; __syncthreads();

    if(tid==0){
        int v0=*(const int*)ndocs_ptr;
        float nd;
        if(v0>0 && v0<(1<<30)) nd=(float)v0;
        else nd=*(const float*)ndocs_ptr;
        float coeff=nd/(float)BB;
        float nll=-sum_ll*coeff;
        float kl_eta=g_kleta[0];
        float kl_theta=sum_th*coeff;
        float pred=sum_pred*coeff;
        float nelbo=nll+kl_alpha+kl_eta+kl_theta+pred;
        out[0]=nelbo; out[1]=nll; out[2]=kl_alpha;
        out[3]=kl_eta; out[4]=kl_theta; out[5]=pred;
    }
}

// ---------------- launcher ----------------
extern "C" void kernel_launch(void* const* d_in, const int* in_sizes, int n_in,
                              void* d_out, int out_size)
{
    const float* bows      =(const float*)d_in[1];
    const float* nbows     =(const float*)d_in[2];
    const int*   times     =(const int*)  d_in[3];
    const int*   sources   =(const int*)  d_in[4];
    const float* rnn_inp   =(const float*)d_in[5];
    const void*  num_docs  =               d_in[6];
    const float* mu_q_alpha=(const float*)d_in[7];
    const float* ls_q_alpha=(const float*)d_in[8];
    const float* rho_W     =(const float*)d_in[9];
    const float* W1        =(const float*)d_in[10];
    const float* b1        =(const float*)d_in[11];
    const float* W2        =(const float*)d_in[12];
    const float* b2        =(const float*)d_in[13];
    const float* mu_th_W   =(const float*)d_in[14];
    const float* mu_th_b   =(const float*)d_in[15];
    const float* ls_th_W   =(const float*)d_in[16];
    const float* ls_th_b   =(const float*)d_in[17];
    const float* eta_map_W =(const float*)d_in[18];
    const float* eta_map_b =(const float*)d_in[19];
    const float* lstm_Wih  =(const float*)d_in[20];
    const float* lstm_Whh  =(const float*)d_in[21];
    const float* lstm_bih  =(const float*)d_in[22];
    const float* lstm_bhh  =(const float*)d_in[23];
    const float* mu_eta_W  =(const float*)d_in[24];
    const float* mu_eta_b  =(const float*)d_in[25];
    const float* ls_eta_W  =(const float*)d_in[26];
    const float* ls_eta_b  =(const float*)d_in[27];
    const float* cls_W     =(const float*)d_in[28];
    const float* cls_b     =(const float*)d_in[29];
    float* out=(float*)d_out;

    float *alphas,*rhoP,*w1c,*E,*part1,*partx,*mapped,*xz,*part4,*part5,*h1,*h2;
    cudaGetSymbolAddress((void**)&alphas,g_alphas);
    cudaGetSymbolAddress((void**)&rhoP,g_rhoP);
    cudaGetSymbolAddress((void**)&w1c,g_w1c);
    cudaGetSymbolAddress((void**)&E,g_E);
    cudaGetSymbolAddress((void**)&part1,g_part1);
    cudaGetSymbolAddress((void**)&partx,g_partx);
    cudaGetSymbolAddress((void**)&mapped,g_mapped);
    cudaGetSymbolAddress((void**)&xz,g_xz);
    cudaGetSymbolAddress((void**)&part4,g_part4);
    cudaGetSymbolAddress((void**)&part5,g_part5);
    cudaGetSymbolAddress((void**)&h1,g_h1);
    cudaGetSymbolAddress((void**)&h2,g_h2);

    // prep
    prep_kernel<<<(TT*KT*RHOP+255)/256,256>>>(mu_q_alpha, lstm_Whh);
    rhopad_kernel<<<(VV*RHOP+255)/256,256>>>(rho_W);
    w1copy_kernel<<<(THH*(VV/2)+255)/256,256>>>(W1);
    transpose_heads<<<(KT*THH+255)/256,256>>>(mu_eta_W, ls_eta_W, mu_th_W, ls_th_W);
    kl_alpha_kernel<<<KT*TT,128>>>(mu_q_alpha, ls_q_alpha);

    // ---- beta path: E = exp(alphas @ rhoP^T) ----
    {
        dim3 g((VV+127)/128,(TT*KT+127)/128,1);
        sgemm128<2><<<g,256>>>(TT*KT,VV,RHOP, alphas,RHOP, rhoP,RHOP,
                               E,VV, nullptr,nullptr);
    }
    rowsum_kernel<<<TT*KT,256>>>();

    // ---- eta path ----
    {   // mapped = rnn_inp @ eta_map_W^T + b   (splitK=24)
        dim3 g((EHH+127)/128,(500+127)/128,24);
        sgemm128<0><<<g,256>>>(500,EHH,VV, rnn_inp,VV, eta_map_W,VV,
                               part1,EHH, nullptr,nullptr);
        reduce_split<<<(500*EHH+255)/256,256>>>(part1,24,500*EHH,EHH, eta_map_b,nullptr,0, mapped);
    }
    {   // xz = mapped @ Wih^T + bih + bhh   (splitK=4)
        dim3 g((4*EHH+127)/128,(500+127)/128,4);
        sgemm128<0><<<g,256>>>(500,4*EHH,EHH, mapped,EHH, lstm_Wih,EHH,
                               partx,4*EHH, nullptr,nullptr);
        reduce_split<<<(500*4*EHH+255)/256,256>>>(partx,4,500*4*EHH,4*EHH, lstm_bih,lstm_bhh,0, xz);
    }
    lstm_kernel<<<SSRC,4*EHH>>>();
    eta_base_kernel<<<(TT*SSRC*KT+255)/256,256>>>();
    eta_rec_kernel<<<1,512>>>(mu_eta_W, ls_eta_W, mu_eta_b, ls_eta_b);
    gather_eta<<<(BB*KT+255)/256,256>>>(sources, times);

    // ---- theta path ----
    {   // h1 bow-part (splitK=16) on aligned W1 copy
        dim3 g((THH+127)/128,(BB+127)/128,16);
        sgemm128<0><<<g,256>>>(BB,THH,VV, nbows,VV, w1c,VV,
                               part4,THH, nullptr,nullptr);
    }
    h1_epilogue<<<(BB*THH+255)/256,256>>>(W1, b1);
    {   // h2 (splitK=8) + relu
        dim3 g((THH+127)/128,(BB+127)/128,8);
        sgemm128<0><<<g,256>>>(BB,THH,THH, h1,THH, W2,THH,
                               part5,THH, nullptr,nullptr);
        reduce_split<<<(BB*THH+255)/256,256>>>(part5,8,BB*THH,THH, b2,nullptr,1, h2);
    }
    theta_head<<<(BB*KT+255)/256,256>>>(mu_th_b, ls_th_b);
    softmax_kltheta<<<BB,64>>>();
    pred_kernel<<<1,BB>>>(cls_W, cls_b, sources);

    // ---- NLL (docs grouped by t) ----
    wdoc_kernel<<<(BB*KT+255)/256,256>>>(times);
    doclist_kernel<<<1,64>>>(times);
    {
        dim3 g(TT,NVTILE,1);
        nll2_kernel<<<g,256>>>(bows);
    }

    // ---- combine ----
    final_kernel<<<1,256>>>(num_docs, out);
    (void)in_sizes; (void)n_in; (void)out_size;
}

// round 6
// speedup vs baseline: 2.0275x; 1.4554x over previous
#include <cuda_runtime.h>
#include <cuda_bf16.h>
#include <math.h>
#include <stdint.h>

#define KT   50
#define TT   50
#define RHOD 300
#define KP   320            // K padded for bf16 MMA
#define VV   20000
#define VP   20096          // V padded to 157*128
#define NT   157            // N tiles of 128
#define NT2  (2*NT)         // rowsum partial slots (2 n-warps per tile)
#define MT   20             // M tiles of 128 (2500 -> 2560)
#define THH  800
#define EHH  200
#define SSRC 10
#define BB   256
#define DELTAF 0.005f
#define LOG_DELTA_F (-5.2983173665480363f)
#define EPSF 1e-6f
#define NVTILE 20

// ---------------- device scratch ----------------
__device__ __align__(16) __nv_bfloat16 g_Abf[(size_t)MT*128*KP];
__device__ __align__(16) __nv_bfloat16 g_Bbf[(size_t)VP*KP];
__device__ __align__(16) float g_w1c[(size_t)THH*VV];
__device__ __align__(16) float g_E[(size_t)TT*KT*VV];     // 200MB
__device__ float g_rsumP[(size_t)TT*KT*NT2];
__device__ float g_invZ[TT*KT];
__device__ __align__(16) float g_part1[24*500*EHH];
__device__ __align__(16) float g_partx[4*500*4*EHH];
__device__ __align__(16) float g_mapped[500*EHH];
__device__ __align__(16) float g_xz[500*4*EHH];
__device__ float g_WhhT[EHH*4*EHH];
__device__ float g_lstm_out[TT*SSRC*EHH];
__device__ float g_base_mu[TT*SSRC*KT];
__device__ float g_base_ls[TT*SSRC*KT];
__device__ float g_etas[SSRC*TT*KT];
__device__ float g_eta_std[BB*KT];
__device__ __align__(16) float g_part4[16*BB*THH];
__device__ __align__(16) float g_part5[8*BB*THH];
__device__ __align__(16) float g_h1[BB*THH];
__device__ __align__(16) float g_h2[BB*THH];
__device__ float g_mu_t[BB*KT];
__device__ float g_ls_t[BB*KT];
__device__ float g_theta[BB*KT];
__device__ float g_wdoc[BB*KT];
__device__ float g_metaT[EHH*KT];
__device__ float g_letaT[EHH*KT];
__device__ float g_mthT[THH*KT];
__device__ float g_lthT[THH*KT];
__device__ int   g_dlist[TT*BB];
__device__ int   g_dcnt[TT];
__device__ float g_pa[KT*TT];
__device__ float g_pnllT[TT*NVTILE];
__device__ float g_pth[BB];
__device__ float g_ppred[BB];
__device__ float g_kleta[1];

__device__ __forceinline__ float sigm_(float x){ return 1.f/(1.f+expf(-x)); }

// ================= HMMA bf16 GEMM: E = exp(A @ B^T), fused rowsum =========
// A: [2560, 320] bf16; B: [20096, 320] bf16. CTA: 128x128 tile, 8 warps
// (4 m-warps x 2 n-warps), warp tile 32x64, mma.sync m16n8k16.
// Stages of BK=64 (8 chunks of 16B per row), chunk-XOR swizzle.

__device__ __forceinline__ void ldsm_x4(uint32_t& r0,uint32_t& r1,uint32_t& r2,uint32_t& r3,uint32_t a){
    asm volatile("ldmatrix.sync.aligned.m8n8.x4.shared.b16 {%0,%1,%2,%3}, [%4];"
                 : "=r"(r0),"=r"(r1),"=r"(r2),"=r"(r3) : "r"(a));
}
__device__ __forceinline__ void mma16816(float* d,const uint32_t* a,const uint32_t* b){
    asm volatile("mma.sync.aligned.m16n8k16.row.col.f32.bf16.bf16.f32 "
        "{%0,%1,%2,%3}, {%4,%5,%6,%7}, {%8,%9}, {%0,%1,%2,%3};"
        : "+f"(d[0]),"+f"(d[1]),"+f"(d[2]),"+f"(d[3])
        : "r"(a[0]),"r"(a[1]),"r"(a[2]),"r"(a[3]), "r"(b[0]),"r"(b[1]));
}

__global__ void __launch_bounds__(256,2)
beta_hmma_kernel(const __nv_bfloat16* __restrict__ Abf,
                 const __nv_bfloat16* __restrict__ Bbf,
                 float* __restrict__ E, float* __restrict__ rsumP)
{
    __shared__ __align__(16) uint8_t smA[16384];   // 128 rows x 128B
    __shared__ __align__(16) uint8_t smB[16384];
    const int tid=threadIdx.x, l=tid&31, wid=tid>>5;
    const int wm=(wid&3)*32, wn=(wid>>2)*64;
    const int bn=blockIdx.x*128, bm=blockIdx.y*128;
    const uint32_t sA=(uint32_t)__cvta_generic_to_shared(smA);
    const uint32_t sB=(uint32_t)__cvta_generic_to_shared(smB);

    const uint4* Ag=(const uint4*)Abf;   // row stride 40 chunks
    const uint4* Bg=(const uint4*)Bbf;

    float acc[2][8][4];
#pragma unroll
    for(int i=0;i<2;i++)
#pragma unroll
        for(int j=0;j<8;j++)
#pragma unroll
            for(int q=0;q<4;q++) acc[i][j][q]=0.f;

    // A-frag ldmatrix address components (fixed row per thread)
    const int ar_=(l&15), ac_=(l>>4);              // row-in-16, chunk half
    // B-frag: row = j*8 + (l&7) + ((l>>4)&1)*8, chunk half = (l>>3)&1
    const int br_=(l&7)+((l>>4)&1)*8, bc_=(l>>3)&1;

#pragma unroll
    for(int s=0;s<5;s++){
        // ---- load stage s: chunks 8s..8s+7 of each row ----
        __syncthreads();
#pragma unroll
        for(int it=0;it<4;it++){
            int c=tid+256*it;           // 0..1023
            int row=c>>3, col=c&7;
            uint32_t off=(uint32_t)row*128u + (uint32_t)((col^(row&7))*16);
            *(uint4*)(smA+off)=Ag[(size_t)(bm+row)*40 + s*8 + col];
            *(uint4*)(smB+off)=Bg[(size_t)(bn+row)*40 + s*8 + col];
        }
        __syncthreads();
        // ---- 4 k-steps of 16 ----
#pragma unroll
        for(int ks=0;ks<4;ks++){
            uint32_t afr[2][4];
#pragma unroll
            for(int i=0;i<2;i++){
                int row=wm+i*16+ar_;
                int ch=ks*2+ac_;
                ldsm_x4(afr[i][0],afr[i][1],afr[i][2],afr[i][3],
                        sA + row*128 + ((ch^(row&7))*16));
            }
            uint32_t bfr[8][2];
#pragma unroll
            for(int jj=0;jj<4;jj++){
                int row=wn+jj*16+br_;
                int ch=ks*2+bc_;
                uint32_t r0,r1,r2,r3;
                ldsm_x4(r0,r1,r2,r3, sB + row*128 + ((ch^(row&7))*16));
                bfr[jj*2][0]=r0; bfr[jj*2][1]=r1;
                bfr[jj*2+1][0]=r2; bfr[jj*2+1][1]=r3;
            }
#pragma unroll
            for(int i=0;i<2;i++)
#pragma unroll
                for(int j=0;j<8;j++)
                    mma16816(acc[i][j],afr[i],bfr[j]);
        }
    }

    // ---- epilogue: exp, store, fused row-sum partials ----
#pragma unroll
    for(int i=0;i<2;i++){
        int r0=bm+wm+i*16+(l>>2);
        int r1=r0+8;
        float s0=0.f,s1=0.f;
#pragma unroll
        for(int j=0;j<8;j++){
            int gn=bn+wn+j*8+2*(l&3);
            bool v=gn<VV;
            float e0=expf(acc[i][j][0]), e1=expf(acc[i][j][1]);
            float e2=expf(acc[i][j][2]), e3=expf(acc[i][j][3]);
            if(v){
                if(r0<TT*KT) *(float2*)(E+(size_t)r0*VV+gn)=make_float2(e0,e1);
                if(r1<TT*KT) *(float2*)(E+(size_t)r1*VV+gn)=make_float2(e2,e3);
                s0+=e0+e1; s1+=e2+e3;
            }
        }
        s0+=__shfl_xor_sync(0xffffffffu,s0,1); s0+=__shfl_xor_sync(0xffffffffu,s0,2);
        s1+=__shfl_xor_sync(0xffffffffu,s1,1); s1+=__shfl_xor_sync(0xffffffffu,s1,2);
        if((l&3)==0){
            int slot=blockIdx.x*2+(wid>>2);
            if(r0<TT*KT) rsumP[(size_t)r0*NT2+slot]=s0;
            if(r1<TT*KT) rsumP[(size_t)r1*NT2+slot]=s1;
        }
    }
}

__global__ void rsum_reduce()
{
    int r=blockIdx.x*blockDim.x+threadIdx.x;
    if(r>=TT*KT) return;
    float s=0.f;
    for(int i=0;i<NT2;i++) s+=g_rsumP[(size_t)r*NT2+i];
    g_invZ[r]=1.f/s;
}

// ---------------- bf16 operand prep ----------------
__global__ void prep_abf(const float* __restrict__ mu)
{
    int i=blockIdx.x*blockDim.x+threadIdx.x;
    if(i>=MT*128*KP) return;
    int r=i%KP, m=i/KP;
    float v=0.f;
    if(m<TT*KT && r<RHOD){
        int t=m/KT, k=m%KT;
        v=mu[((size_t)k*TT+t)*RHOD + r];
    }
    g_Abf[i]=__float2bfloat16(v);
}

__global__ void prep_bbf(const float* __restrict__ rho)
{
    int i=blockIdx.x*blockDim.x+threadIdx.x;
    if(i>=(int)(VP*KP)) return;
    int r=i%KP, v=i/KP;
    float x=(v<VV && r<RHOD)? rho[(size_t)v*RHOD+r] : 0.f;
    g_Bbf[i]=__float2bfloat16(x);
}

// ============ fp32 NT SGEMM (unchanged) ============
template<int OP>
__global__ void __launch_bounds__(256)
sgemm128(int M,int N,int Kd,
         const float* __restrict__ A,int lda,
         const float* __restrict__ B,int ldb,
         float* __restrict__ C,int ldc,
         const float* __restrict__ bias1,const float* __restrict__ bias2)
{
    __shared__ float As[8][128];
    __shared__ float Bs[8][128];
    const int tid=threadIdx.x;
    const int bm=blockIdx.y*128, bn=blockIdx.x*128;
    int k0=0,k1=Kd;
    const int nz=gridDim.z;
    if(nz>1){
        int kChunk=((Kd + nz*8 - 1)/(nz*8))*8;
        k0=blockIdx.z*kChunk; k1=min(Kd,k0+kChunk);
        C += (size_t)blockIdx.z*(size_t)M*(size_t)ldc;
    }
    const int lr=tid>>1, kq=(tid&1)*4;
    const int tx=tid&15, ty=tid>>4;
    float acc[8][8];
#pragma unroll
    for(int i=0;i<8;i++)
#pragma unroll
        for(int j=0;j<8;j++) acc[i][j]=0.f;

    const bool aval=(bm+lr)<M, bval=(bn+lr)<N;
    const float* Ap=A+(size_t)(bm+lr)*lda;
    const float* Bp=B+(size_t)(bn+lr)*ldb;

    for(int kb=k0;kb<k1;kb+=8){
        float4 av=aval? *(const float4*)(Ap+kb+kq) : make_float4(0.f,0.f,0.f,0.f);
        float4 bv=bval? *(const float4*)(Bp+kb+kq) : make_float4(0.f,0.f,0.f,0.f);
        __syncthreads();
        As[kq+0][lr]=av.x; As[kq+1][lr]=av.y; As[kq+2][lr]=av.z; As[kq+3][lr]=av.w;
        Bs[kq+0][lr]=bv.x; Bs[kq+1][lr]=bv.y; Bs[kq+2][lr]=bv.z; Bs[kq+3][lr]=bv.w;
        __syncthreads();
#pragma unroll
        for(int kk=0;kk<8;kk++){
            float ar[8],br[8];
#pragma unroll
            for(int i=0;i<8;i++) ar[i]=As[kk][ty*8+i];
#pragma unroll
            for(int j=0;j<8;j++) br[j]=Bs[kk][tx*8+j];
#pragma unroll
            for(int i=0;i<8;i++)
#pragma unroll
                for(int j=0;j<8;j++) acc[i][j]=fmaf(ar[i],br[j],acc[i][j]);
        }
    }
    const bool raw=(nz>1);
#pragma unroll
    for(int i=0;i<8;i++){
        int gm=bm+ty*8+i; if(gm>=M) continue;
#pragma unroll
        for(int j=0;j<8;j++){
            int gn=bn+tx*8+j; if(gn>=N) continue;
            float v=acc[i][j];
            if(!raw){
                if(bias1) v+=bias1[gn];
                if(bias2) v+=bias2[gn];
                if(OP==1) v=fmaxf(v,0.f);
                else if(OP==2) v=expf(v);
            }
            C[(size_t)gm*ldc+gn]=v;
        }
    }
}

__global__ void reduce_split(const float* __restrict__ parts,int splits,int total,int N,
                             const float* __restrict__ bias1,const float* __restrict__ bias2,
                             int op, float* __restrict__ out)
{
    int i=blockIdx.x*blockDim.x+threadIdx.x;
    if(i>=total) return;
    float v=0.f;
    for(int z=0;z<splits;z++) v+=parts[(size_t)z*total+i];
    if(bias1) v+=bias1[i%N];
    if(bias2) v+=bias2[i%N];
    if(op==1) v=fmaxf(v,0.f);
    out[i]=v;
}

// ---------------- misc prep ----------------
__global__ void prep_whh(const float* __restrict__ whh)
{
    int i=blockIdx.x*blockDim.x+threadIdx.x;
    if(i>=EHH*4*EHH) return;
    int k=i/(4*EHH), j=i%(4*EHH);
    g_WhhT[i]=whh[(size_t)j*EHH + k];
}

__global__ void w1copy_kernel(const float* __restrict__ W1)
{
    int i=blockIdx.x*blockDim.x+threadIdx.x;
    if(i>=THH*(VV/2)) return;
    int j=i/(VV/2), vh=i%(VV/2);
    float2 s=*(const float2*)(W1+(size_t)j*(VV+KT)+ (size_t)vh*2);
    *(float2*)(g_w1c+(size_t)j*VV+(size_t)vh*2)=s;
}

__global__ void transpose_heads(const float* __restrict__ muEta,const float* __restrict__ lsEta,
                                const float* __restrict__ muTh,const float* __restrict__ lsTh)
{
    int i=blockIdx.x*blockDim.x+threadIdx.x;
    if(i<KT*EHH){
        int k=i/EHH, j=i%EHH;
        g_metaT[j*KT+k]=muEta[(size_t)k*(EHH+KT)+j];
        g_letaT[j*KT+k]=lsEta[(size_t)k*(EHH+KT)+j];
    }
    if(i<KT*THH){
        int k=i/THH, j=i%THH;
        g_mthT[j*KT+k]=muTh[(size_t)k*THH+j];
        g_lthT[j*KT+k]=lsTh[(size_t)k*THH+j];
    }
}

// ---------------- kl_alpha ----------------
__global__ void kl_alpha_kernel(const float* __restrict__ mu,const float* __restrict__ ls)
{
    __shared__ float red[128];
    int b=blockIdx.x; int t=b%TT;
    const float* mup=mu+(size_t)b*RHOD;
    const float* lsp=ls+(size_t)b*RHOD;
    const float* mpv=mu+(size_t)(b-1)*RHOD;
    float s=0.f;
    for(int r=threadIdx.x;r<RHOD;r+=128){
        float m=mup[r], l=lsp[r];
        if(t==0) s += (expf(l)+m*m)/(1.f+EPSF) - 1.f - l;
        else { float d=m-mpv[r]; s += (expf(l)+d*d)/(DELTAF+EPSF) - 1.f + LOG_DELTA_F - l; }
    }
    red[threadIdx.x]=s; __syncthreads();
    for(int off=64;off>0;off>>=1){ if(threadIdx.x<off) red[threadIdx.x]+=red[threadIdx.x+off]; __syncthreads(); }
    if(threadIdx.x==0) g_pa[b]=0.5f*red[0];
}

// ---------------- LSTM ----------------
__global__ void __launch_bounds__(4*EHH) lstm_kernel()
{
    __shared__ float hsm[EHH];
    __shared__ float zsm[4*EHH];
    const int s=blockIdx.x, j=threadIdx.x;
    float c=0.f;
    if(j<EHH) hsm[j]=0.f;
    __syncthreads();
    for(int t=0;t<TT;t++){
        float acc=g_xz[((size_t)s*TT+t)*(4*EHH)+j];
#pragma unroll 4
        for(int k=0;k<EHH;k++) acc=fmaf(hsm[k], g_WhhT[k*(4*EHH)+j], acc);
        zsm[j]=acc;
        __syncthreads();
        if(j<EHH){
            float ig=sigm_(zsm[j]), fg=sigm_(zsm[EHH+j]);
            float gg=tanhf(zsm[2*EHH+j]), og=sigm_(zsm[3*EHH+j]);
            c=fg*c+ig*gg;
            float h=og*tanhf(c);
            hsm[j]=h;
            g_lstm_out[((size_t)t*SSRC+s)*EHH+j]=h;
        }
        __syncthreads();
    }
}

// ---------------- eta base ----------------
__global__ void eta_base_kernel()
{
    int i=blockIdx.x*blockDim.x+threadIdx.x;
    if(i>=TT*SSRC*KT) return;
    int k=i%KT; int ts=i/KT;
    const float* h=g_lstm_out+(size_t)ts*EHH;
    float am=0.f, al=0.f;
    for(int j=0;j<EHH;j++){
        float hv=h[j];
        am=fmaf(hv,g_metaT[j*KT+k],am);
        al=fmaf(hv,g_letaT[j*KT+k],al);
    }
    g_base_mu[i]=am; g_base_ls[i]=al;
}

// ---------------- eta recurrence + kl_eta ----------------
__global__ void __launch_bounds__(512) eta_rec_kernel(const float* __restrict__ muW,const float* __restrict__ lsW,
                                                      const float* __restrict__ mub,const float* __restrict__ lsb)
{
    __shared__ float eprev[SSRC*KT];
    __shared__ float red[512];
    const int tid=threadIdx.x;
    const int s=tid/KT, k=tid%KT;
    const bool act = tid < SSRC*KT;
    float kl=0.f;
    if(act){
        float m=g_base_mu[tid]+mub[k];
        float l=g_base_ls[tid]+lsb[k];
        kl += (expf(l)+m*m)/(1.f+EPSF) - 1.f - l;
        eprev[tid]=m;
        g_etas[((size_t)s*TT+0)*KT+k]=m;
    }
    __syncthreads();
    for(int t=1;t<TT;t++){
        float m=0.f;
        if(act){
            m=g_base_mu[(size_t)t*SSRC*KT+tid]+mub[k];
            float l=g_base_ls[(size_t)t*SSRC*KT+tid]+lsb[k];
            const float* er=eprev+s*KT;
            const float* wm=muW+(size_t)k*(EHH+KT)+EHH;
            const float* wl=lsW+(size_t)k*(EHH+KT)+EHH;
#pragma unroll
            for(int k2=0;k2<KT;k2++){ float e=er[k2]; m=fmaf(e,wm[k2],m); l=fmaf(e,wl[k2],l); }
            l=fminf(fmaxf(l,-10.f),10.f);
            float d=m-eprev[tid];
            kl += (expf(l)+d*d)/(DELTAF+EPSF) - 1.f + LOG_DELTA_F - l;
        }
        __syncthreads();
        if(act){ eprev[tid]=m; g_etas[((size_t)s*TT+t)*KT+k]=m; }
        __syncthreads();
    }
    red[tid]=kl; __syncthreads();
    for(int off=256;off>0;off>>=1){ if(tid<off) red[tid]+=red[tid+off]; __syncthreads(); }
    if(tid==0) g_kleta[0]=0.5f*red[0];
}

__global__ void gather_eta(const int* __restrict__ sources,const int* __restrict__ times)
{
    int i=blockIdx.x*blockDim.x+threadIdx.x;
    if(i>=BB*KT) return;
    int b=i/KT, k=i%KT;
    g_eta_std[i]=g_etas[((size_t)sources[b]*TT+times[b])*KT+k];
}

// ---------------- h1 epilogue ----------------
__global__ void h1_epilogue(const float* __restrict__ W1,const float* __restrict__ b1)
{
    int i=blockIdx.x*blockDim.x+threadIdx.x;
    if(i>=BB*THH) return;
    int b=i/THH, j=i%THH;
    float v=0.f;
    for(int z=0;z<16;z++) v+=g_part4[(size_t)z*BB*THH+i];
    v+=b1[j];
    const float* w=W1+(size_t)j*(VV+KT)+VV;
    const float* e=g_eta_std+(size_t)b*KT;
#pragma unroll
    for(int k=0;k<KT;k++) v=fmaf(e[k],w[k],v);
    g_h1[i]=fmaxf(v,0.f);
}

// ---------------- theta heads ----------------
__global__ void theta_head(const float* __restrict__ mub,const float* __restrict__ lsb)
{
    int i=blockIdx.x*blockDim.x+threadIdx.x;
    if(i>=BB*KT) return;
    int b=i/KT, k=i%KT;
    const float* h=g_h2+(size_t)b*THH;
    float am=mub[k], al=lsb[k];
    for(int j=0;j<THH;j++){
        float hv=h[j];
        am=fmaf(hv,g_mthT[j*KT+k],am);
        al=fmaf(hv,g_lthT[j*KT+k],al);
    }
    g_mu_t[i]=am;
    g_ls_t[i]=fminf(fmaxf(al,-10.f),10.f);
}

// ---------------- softmax(theta) + kl_theta ----------------
__global__ void softmax_kltheta()
{
    __shared__ float red[64];
    const int b=blockIdx.x, tid=threadIdx.x;
    float m=(tid<KT)? g_mu_t[(size_t)b*KT+tid] : -1e30f;
    red[tid]=m; __syncthreads();
    for(int off=32;off>0;off>>=1){ if(tid<off) red[tid]=fmaxf(red[tid],red[tid+off]); __syncthreads(); }
    float mx=red[0]; __syncthreads();
    float e=(tid<KT)? expf(m-mx) : 0.f;
    red[tid]=e; __syncthreads();
    for(int off=32;off>0;off>>=1){ if(tid<off) red[tid]+=red[tid+off]; __syncthreads(); }
    float Z=red[0]; __syncthreads();
    if(tid<KT) g_theta[(size_t)b*KT+tid]=e/Z;
    float term=0.f;
    if(tid<KT){
        float l=g_ls_t[(size_t)b*KT+tid];
        float d=m-g_eta_std[(size_t)b*KT+tid];
        term=(expf(l)+d*d)/(1.f+EPSF)-1.f-l;
    }
    red[tid]=term; __syncthreads();
    for(int off=32;off>0;off>>=1){ if(tid<off) red[tid]+=red[tid+off]; __syncthreads(); }
    if(tid==0) g_pth[b]=0.5f*red[0];
}

// ---------------- source prediction loss ----------------
__global__ void pred_kernel(const float* __restrict__ clsW,const float* __restrict__ clsb,
                            const int* __restrict__ sources)
{
    int b=blockIdx.x*blockDim.x+threadIdx.x;
    if(b>=BB) return;
    const float* th=g_theta+(size_t)b*KT;
    float lg[SSRC], mx=-1e30f;
#pragma unroll
    for(int i=0;i<SSRC;i++){
        float a=clsb[i];
        const float* w=clsW+(size_t)i*KT;
#pragma unroll
        for(int k=0;k<KT;k++) a=fmaf(th[k],w[k],a);
        lg[i]=a; mx=fmaxf(mx,a);
    }
    float se=0.f;
#pragma unroll
    for(int i=0;i<SSRC;i++) se+=expf(lg[i]-mx);
    float lse=mx+logf(se);
    g_ppred[b]=lse-lg[sources[b]];
}

// ---------------- NLL (docs grouped by time) ----------------
__global__ void wdoc_kernel(const int* __restrict__ times)
{
    int i=blockIdx.x*blockDim.x+threadIdx.x;
    if(i>=BB*KT) return;
    int b=i/KT, k=i%KT;
    g_wdoc[i]=g_theta[i]*g_invZ[times[b]*KT+k];
}

__global__ void doclist_kernel(const int* __restrict__ times)
{
    int t=threadIdx.x;
    if(t>=TT) return;
    int cnt=0;
    for(int b=0;b<BB;b++)
        if(times[b]==t) g_dlist[t*BB + (cnt++)]=b;
    g_dcnt[t]=cnt;
}

__global__ void __launch_bounds__(256) nll2_kernel(const float* __restrict__ bows)
{
    const int t=blockIdx.x, vt=blockIdx.y, tid=threadIdx.x;
    __shared__ float ws[32][KT];
    __shared__ int   dls[32];
    __shared__ float red[256];
    const int cnt=g_dcnt[t];
    float s=0.f;
    for(int d0=0; d0<cnt; d0+=32){
        int ch=min(32,cnt-d0);
        __syncthreads();
        for(int i=tid;i<ch*KT;i+=256){
            int d=i/KT, k=i%KT;
            int b=g_dlist[t*BB+d0+d];
            ws[d][k]=g_wdoc[(size_t)b*KT+k];
            if(k==0) dls[d]=b;
        }
        __syncthreads();
        for(int vi=0;vi<4;vi++){
            int v=vt*1024+vi*256+tid;
            if(v>=VV) break;
            float e[KT];
            const float* Ep=g_E+(size_t)t*KT*VV+v;
#pragma unroll
            for(int k=0;k<KT;k++) e[k]=Ep[(size_t)k*VV];
            for(int d=0;d<ch;d++){
                float mix=0.f;
#pragma unroll
                for(int k=0;k<KT;k++) mix=fmaf(ws[d][k],e[k],mix);
                s=fmaf(logf(mix), bows[(size_t)dls[d]*VV+v], s);
            }
        }
    }
    red[tid]=s; __syncthreads();
    for(int off=128;off>0;off>>=1){ if(tid<off) red[tid]+=red[tid+off]; __syncthreads(); }
    if(tid==0) g_pnllT[t*NVTILE+vt]=red[0];
}

// ---------------- final combine ----------------
__global__ void __launch_bounds__(256) final_kernel(const void* __restrict__ ndocs_ptr,
                                                    float* __restrict__ out)
{
    __shared__ float red[256];
    const int tid=threadIdx.x;
    float sa=0.f;
    for(int i=tid;i<KT*TT;i+=256) sa+=g_pa[i];
    red[tid]=sa; __syncthreads();
    for(int off=128;off>0;off>>=1){ if(tid<off) red[tid]+=red[tid+off]; __syncthreads(); }
    float kl_alpha=red[0]; __syncthreads();

    float sl=0.f;
    for(int i=tid;i<TT*NVTILE;i+=256) sl+=g_pnllT[i];
    red[tid]=sl; __syncthreads();
    for(int off=128;off>0;off>>=1){ if(tid<off) red[tid]+=red[tid+off]; __syncthreads(); }
    float sum_ll=red[0]; __syncthreads();

    red[tid]=g_pth[tid]; __syncthreads();
    for(int off=128;off>0;off>>=1){ if(tid<off) red[tid]+=red[tid+off]; __syncthreads(); }
    float sum_th=red[0]; __syncthreads();

    red[tid]=g_ppred[tid]; __syncthreads();
    for(int off=128;off>0;off>>=1){ if(tid<off) red[tid]+=red[tid+off]; __syncthreads(); }
    float sum_pred=red[0]; __syncthreads();

    if(tid==0){
        int v0=*(const int*)ndocs_ptr;
        float nd;
        if(v0>0 && v0<(1<<30)) nd=(float)v0;
        else nd=*(const float*)ndocs_ptr;
        float coeff=nd/(float)BB;
        float nll=-sum_ll*coeff;
        float kl_eta=g_kleta[0];
        float kl_theta=sum_th*coeff;
        float pred=sum_pred*coeff;
        float nelbo=nll+kl_alpha+kl_eta+kl_theta+pred;
        out[0]=nelbo; out[1]=nll; out[2]=kl_alpha;
        out[3]=kl_eta; out[4]=kl_theta; out[5]=pred;
    }
}

// ---------------- launcher ----------------
extern "C" void kernel_launch(void* const* d_in, const int* in_sizes, int n_in,
                              void* d_out, int out_size)
{
    const float* bows      =(const float*)d_in[1];
    const float* nbows     =(const float*)d_in[2];
    const int*   times     =(const int*)  d_in[3];
    const int*   sources   =(const int*)  d_in[4];
    const float* rnn_inp   =(const float*)d_in[5];
    const void*  num_docs  =               d_in[6];
    const float* mu_q_alpha=(const float*)d_in[7];
    const float* ls_q_alpha=(const float*)d_in[8];
    const float* rho_W     =(const float*)d_in[9];
    const float* W1        =(const float*)d_in[10];
    const float* b1        =(const float*)d_in[11];
    const float* W2        =(const float*)d_in[12];
    const float* b2        =(const float*)d_in[13];
    const float* mu_th_W   =(const float*)d_in[14];
    const float* mu_th_b   =(const float*)d_in[15];
    const float* ls_th_W   =(const float*)d_in[16];
    const float* ls_th_b   =(const float*)d_in[17];
    const float* eta_map_W =(const float*)d_in[18];
    const float* eta_map_b =(const float*)d_in[19];
    const float* lstm_Wih  =(const float*)d_in[20];
    const float* lstm_Whh  =(const float*)d_in[21];
    const float* lstm_bih  =(const float*)d_in[22];
    const float* lstm_bhh  =(const float*)d_in[23];
    const float* mu_eta_W  =(const float*)d_in[24];
    const float* mu_eta_b  =(const float*)d_in[25];
    const float* ls_eta_W  =(const float*)d_in[26];
    const float* ls_eta_b  =(const float*)d_in[27];
    const float* cls_W     =(const float*)d_in[28];
    const float* cls_b     =(const float*)d_in[29];
    float* out=(float*)d_out;

    float *E,*rsumP,*w1c,*part1,*partx,*mapped,*xz,*part4,*part5,*h1,*h2;
    __nv_bfloat16 *Abf,*Bbf;
    cudaGetSymbolAddress((void**)&Abf,g_Abf);
    cudaGetSymbolAddress((void**)&Bbf,g_Bbf);
    cudaGetSymbolAddress((void**)&E,g_E);
    cudaGetSymbolAddress((void**)&rsumP,g_rsumP);
    cudaGetSymbolAddress((void**)&w1c,g_w1c);
    cudaGetSymbolAddress((void**)&part1,g_part1);
    cudaGetSymbolAddress((void**)&partx,g_partx);
    cudaGetSymbolAddress((void**)&mapped,g_mapped);
    cudaGetSymbolAddress((void**)&xz,g_xz);
    cudaGetSymbolAddress((void**)&part4,g_part4);
    cudaGetSymbolAddress((void**)&part5,g_part5);
    cudaGetSymbolAddress((void**)&h1,g_h1);
    cudaGetSymbolAddress((void**)&h2,g_h2);

    // prep
    prep_whh<<<(EHH*4*EHH+255)/256,256>>>(lstm_Whh);
    prep_abf<<<(MT*128*KP+255)/256,256>>>(mu_q_alpha);
    prep_bbf<<<((int)(VP*KP)+255)/256,256>>>(rho_W);
    w1copy_kernel<<<(THH*(VV/2)+255)/256,256>>>(W1);
    transpose_heads<<<(KT*THH+255)/256,256>>>(mu_eta_W, ls_eta_W, mu_th_W, ls_th_W);
    kl_alpha_kernel<<<KT*TT,128>>>(mu_q_alpha, ls_q_alpha);

    // ---- beta path: HMMA bf16 GEMM + fused exp/rowsum ----
    {
        dim3 g(NT,MT,1);
        beta_hmma_kernel<<<g,256>>>(Abf,Bbf,E,rsumP);
    }
    rsum_reduce<<<(TT*KT+255)/256,256>>>();

    // ---- eta path ----
    {
        dim3 g((EHH+127)/128,(500+127)/128,24);
        sgemm128<0><<<g,256>>>(500,EHH,VV, rnn_inp,VV, eta_map_W,VV,
                               part1,EHH, nullptr,nullptr);
        reduce_split<<<(500*EHH+255)/256,256>>>(part1,24,500*EHH,EHH, eta_map_b,nullptr,0, mapped);
    }
    {
        dim3 g((4*EHH+127)/128,(500+127)/128,4);
        sgemm128<0><<<g,256>>>(500,4*EHH,EHH, mapped,EHH, lstm_Wih,EHH,
                               partx,4*EHH, nullptr,nullptr);
        reduce_split<<<(500*4*EHH+255)/256,256>>>(partx,4,500*4*EHH,4*EHH, lstm_bih,lstm_bhh,0, xz);
    }
    lstm_kernel<<<SSRC,4*EHH>>>();
    eta_base_kernel<<<(TT*SSRC*KT+255)/256,256>>>();
    eta_rec_kernel<<<1,512>>>(mu_eta_W, ls_eta_W, mu_eta_b, ls_eta_b);
    gather_eta<<<(BB*KT+255)/256,256>>>(sources, times);

    // ---- theta path ----
    {
        dim3 g((THH+127)/128,(BB+127)/128,16);
        sgemm128<0><<<g,256>>>(BB,THH,VV, nbows,VV, w1c,VV,
                               part4,THH, nullptr,nullptr);
    }
    h1_epilogue<<<(BB*THH+255)/256,256>>>(W1, b1);
    {
        dim3 g((THH+127)/128,(BB+127)/128,8);
        sgemm128<0><<<g,256>>>(BB,THH,THH, h1,THH, W2,THH,
                               part5,THH, nullptr,nullptr);
        reduce_split<<<(BB*THH+255)/256,256>>>(part5,8,BB*THH,THH, b2,nullptr,1, h2);
    }
    theta_head<<<(BB*KT+255)/256,256>>>(mu_th_b, ls_th_b);
    softmax_kltheta<<<BB,64>>>();
    pred_kernel<<<1,BB>>>(cls_W, cls_b, sources);

    // ---- NLL ----
    wdoc_kernel<<<(BB*KT+255)/256,256>>>(times);
    doclist_kernel<<<1,64>>>(times);
    {
        dim3 g(TT,NVTILE,1);
        nll2_kernel<<<g,256>>>(bows);
    }

    // ---- combine ----
    final_kernel<<<1,256>>>(num_docs, out);
    (void)in_sizes; (void)n_in; (void)out_size;
}

// round 7
// speedup vs baseline: 2.6152x; 1.2899x over previous
#include <cuda_runtime.h>
#include <cuda_bf16.h>
#include <math.h>
#include <stdint.h>

#define KT   50
#define TT   50
#define RHOD 300
#define KP   320            // K padded for beta MMA
#define VV   20000
#define KP2  20032          // K padded for V-contraction HMMA (2504 chunks)
#define KCH  2504           // KP2/8 16B-chunks per row
#define KSTG 313            // ceil(2504/8) BK=64 stages
#define VP   20096          // V padded to 157*128
#define NT   157
#define NT2  (2*NT)
#define MT   20
#define THH  800
#define EHH  200
#define SSRC 10
#define BB   256
#define H1Z  21             // h1 splitK
#define EMZ  35             // eta_map splitK
#define DELTAF 0.005f
#define LOG_DELTA_F (-5.2983173665480363f)
#define EPSF 1e-6f
#define NVTILE 20

// ---------------- device scratch ----------------
__device__ __align__(16) __nv_bfloat16 g_Abf[(size_t)MT*128*KP];
__device__ __align__(16) __nv_bfloat16 g_Bbf[(size_t)VP*KP];
__device__ __align__(16) __nv_bfloat16 g_nbbf[(size_t)256*KP2];
__device__ __align__(16) __nv_bfloat16 g_w1bf[(size_t)896*KP2];
__device__ __align__(16) __nv_bfloat16 g_rnnbf[(size_t)512*KP2];
__device__ __align__(16) __nv_bfloat16 g_emwbf[(size_t)256*KP2];
__device__ __align__(16) float g_E[(size_t)TT*KT*VV];     // 200MB
__device__ float g_rsumP[(size_t)TT*KT*NT2];
__device__ float g_invZ[TT*KT];
__device__ __align__(16) float g_part1[EMZ*500*EHH];
__device__ __align__(16) float g_partx[4*500*4*EHH];
__device__ __align__(16) float g_mapped[500*EHH];
__device__ __align__(16) float g_xz[500*4*EHH];
__device__ float g_WhhT[EHH*4*EHH];
__device__ float g_lstm_out[TT*SSRC*EHH];
__device__ float g_base_mu[TT*SSRC*KT];
__device__ float g_base_ls[TT*SSRC*KT];
__device__ float g_etas[SSRC*TT*KT];
__device__ float g_eta_std[BB*KT];
__device__ __align__(16) float g_part4[H1Z*BB*THH];
__device__ __align__(16) float g_part5[8*BB*THH];
__device__ __align__(16) float g_h1[BB*THH];
__device__ __align__(16) float g_h2[BB*THH];
__device__ float g_mu_t[BB*KT];
__device__ float g_ls_t[BB*KT];
__device__ float g_theta[BB*KT];
__device__ float g_wdoc[BB*KT];
__device__ float g_metaT[EHH*KT];
__device__ float g_letaT[EHH*KT];
__device__ float g_mthT[THH*KT];
__device__ float g_lthT[THH*KT];
__device__ int   g_dlist[TT*BB];
__device__ int   g_dcnt[TT];
__device__ float g_pa[KT*TT];
__device__ float g_pnllT[TT*NVTILE];
__device__ float g_pth[BB];
__device__ float g_ppred[BB];
__device__ float g_kleta[1];

__device__ __forceinline__ float sigm_(float x){ return 1.f/(1.f+expf(-x)); }

// ---------------- HMMA primitives ----------------
__device__ __forceinline__ void ldsm_x4(uint32_t& r0,uint32_t& r1,uint32_t& r2,uint32_t& r3,uint32_t a){
    asm volatile("ldmatrix.sync.aligned.m8n8.x4.shared.b16 {%0,%1,%2,%3}, [%4];"
                 : "=r"(r0),"=r"(r1),"=r"(r2),"=r"(r3) : "r"(a));
}
__device__ __forceinline__ void mma16816(float* d,const uint32_t* a,const uint32_t* b){
    asm volatile("mma.sync.aligned.m16n8k16.row.col.f32.bf16.bf16.f32 "
        "{%0,%1,%2,%3}, {%4,%5,%6,%7}, {%8,%9}, {%0,%1,%2,%3};"
        : "+f"(d[0]),"+f"(d[1]),"+f"(d[2]),"+f"(d[3])
        : "r"(a[0]),"r"(a[1]),"r"(a[2]),"r"(a[3]), "r"(b[0]),"r"(b[1]));
}

// ================= beta HMMA: E = exp(A @ B^T), fused rowsum ==============
__global__ void __launch_bounds__(256,2)
beta_hmma_kernel(const __nv_bfloat16* __restrict__ Abf,
                 const __nv_bfloat16* __restrict__ Bbf,
                 float* __restrict__ E, float* __restrict__ rsumP)
{
    __shared__ __align__(16) uint8_t smA[16384];
    __shared__ __align__(16) uint8_t smB[16384];
    const int tid=threadIdx.x, l=tid&31, wid=tid>>5;
    const int wm=(wid&3)*32, wn=(wid>>2)*64;
    const int bn=blockIdx.x*128, bm=blockIdx.y*128;
    const uint32_t sA=(uint32_t)__cvta_generic_to_shared(smA);
    const uint32_t sB=(uint32_t)__cvta_generic_to_shared(smB);
    const uint4* Ag=(const uint4*)Abf;
    const uint4* Bg=(const uint4*)Bbf;

    float acc[2][8][4];
#pragma unroll
    for(int i=0;i<2;i++)
#pragma unroll
        for(int j=0;j<8;j++)
#pragma unroll
            for(int q=0;q<4;q++) acc[i][j][q]=0.f;

    const int ar_=(l&15), ac_=(l>>4);
    const int br_=(l&7)+((l>>4)&1)*8, bc_=(l>>3)&1;

#pragma unroll
    for(int s=0;s<5;s++){
        __syncthreads();
#pragma unroll
        for(int it=0;it<4;it++){
            int c=tid+256*it;
            int row=c>>3, col=c&7;
            uint32_t off=(uint32_t)row*128u + (uint32_t)((col^(row&7))*16);
            *(uint4*)(smA+off)=Ag[(size_t)(bm+row)*40 + s*8 + col];
            *(uint4*)(smB+off)=Bg[(size_t)(bn+row)*40 + s*8 + col];
        }
        __syncthreads();
#pragma unroll
        for(int ks=0;ks<4;ks++){
            uint32_t afr[2][4];
#pragma unroll
            for(int i=0;i<2;i++){
                int row=wm+i*16+ar_;
                int ch=ks*2+ac_;
                ldsm_x4(afr[i][0],afr[i][1],afr[i][2],afr[i][3],
                        sA + row*128 + ((ch^(row&7))*16));
            }
            uint32_t bfr[8][2];
#pragma unroll
            for(int jj=0;jj<4;jj++){
                int row=wn+jj*16+br_;
                int ch=ks*2+bc_;
                uint32_t r0,r1,r2,r3;
                ldsm_x4(r0,r1,r2,r3, sB + row*128 + ((ch^(row&7))*16));
                bfr[jj*2][0]=r0; bfr[jj*2][1]=r1;
                bfr[jj*2+1][0]=r2; bfr[jj*2+1][1]=r3;
            }
#pragma unroll
            for(int i=0;i<2;i++)
#pragma unroll
                for(int j=0;j<8;j++)
                    mma16816(acc[i][j],afr[i],bfr[j]);
        }
    }

#pragma unroll
    for(int i=0;i<2;i++){
        int r0=bm+wm+i*16+(l>>2);
        int r1=r0+8;
        float s0=0.f,s1=0.f;
#pragma unroll
        for(int j=0;j<8;j++){
            int gn=bn+wn+j*8+2*(l&3);
            bool v=gn<VV;
            float e0=expf(acc[i][j][0]), e1=expf(acc[i][j][1]);
            float e2=expf(acc[i][j][2]), e3=expf(acc[i][j][3]);
            if(v){
                if(r0<TT*KT) *(float2*)(E+(size_t)r0*VV+gn)=make_float2(e0,e1);
                if(r1<TT*KT) *(float2*)(E+(size_t)r1*VV+gn)=make_float2(e2,e3);
                s0+=e0+e1; s1+=e2+e3;
            }
        }
        s0+=__shfl_xor_sync(0xffffffffu,s0,1); s0+=__shfl_xor_sync(0xffffffffu,s0,2);
        s1+=__shfl_xor_sync(0xffffffffu,s1,1); s1+=__shfl_xor_sync(0xffffffffu,s1,2);
        if((l&3)==0){
            int slot=blockIdx.x*2+(wid>>2);
            if(r0<TT*KT) rsumP[(size_t)r0*NT2+slot]=s0;
            if(r1<TT*KT) rsumP[(size_t)r1*NT2+slot]=s1;
        }
    }
}

// ============ generic HMMA NT GEMM, splitK raw partials ============
// A: [Mpad x KP2] bf16 (rows padded w/ zeros), B: [Npad x KP2] bf16.
// grid: (ntiles, mtiles, splits). Writes raw fp32 partials to C + z*M*ldc.
__global__ void __launch_bounds__(256,2)
hmma_nt(int M,int N,int ldc,int stagesPer,
        const __nv_bfloat16* __restrict__ A,
        const __nv_bfloat16* __restrict__ B,
        float* __restrict__ C)
{
    __shared__ __align__(16) uint8_t smA[16384];
    __shared__ __align__(16) uint8_t smB[16384];
    const int tid=threadIdx.x, l=tid&31, wid=tid>>5;
    const int wm=(wid&3)*32, wn=(wid>>2)*64;
    const int bn=blockIdx.x*128, bm=blockIdx.y*128;
    const int s0=blockIdx.z*stagesPer;
    const int s1=min(KSTG, s0+stagesPer);
    C += (size_t)blockIdx.z*(size_t)M*(size_t)ldc;
    const uint32_t sA=(uint32_t)__cvta_generic_to_shared(smA);
    const uint32_t sB=(uint32_t)__cvta_generic_to_shared(smB);
    const uint4* Ag=(const uint4*)A;
    const uint4* Bg=(const uint4*)B;

    float acc[2][8][4];
#pragma unroll
    for(int i=0;i<2;i++)
#pragma unroll
        for(int j=0;j<8;j++)
#pragma unroll
            for(int q=0;q<4;q++) acc[i][j][q]=0.f;

    const int ar_=(l&15), ac_=(l>>4);
    const int br_=(l&7)+((l>>4)&1)*8, bc_=(l>>3)&1;

    for(int s=s0;s<s1;s++){
        __syncthreads();
#pragma unroll
        for(int it=0;it<4;it++){
            int c=tid+256*it;
            int row=c>>3, col=c&7;
            uint32_t off=(uint32_t)row*128u + (uint32_t)((col^(row&7))*16);
            int ch=s*8+col;
            uint4 av = (ch<KCH)? Ag[(size_t)(bm+row)*KCH + ch] : make_uint4(0,0,0,0);
            uint4 bv = (ch<KCH)? Bg[(size_t)(bn+row)*KCH + ch] : make_uint4(0,0,0,0);
            *(uint4*)(smA+off)=av;
            *(uint4*)(smB+off)=bv;
        }
        __syncthreads();
#pragma unroll
        for(int ks=0;ks<4;ks++){
            uint32_t afr[2][4];
#pragma unroll
            for(int i=0;i<2;i++){
                int row=wm+i*16+ar_;
                int ch=ks*2+ac_;
                ldsm_x4(afr[i][0],afr[i][1],afr[i][2],afr[i][3],
                        sA + row*128 + ((ch^(row&7))*16));
            }
            uint32_t bfr[8][2];
#pragma unroll
            for(int jj=0;jj<4;jj++){
                int row=wn+jj*16+br_;
                int ch=ks*2+bc_;
                uint32_t r0,r1,r2,r3;
                ldsm_x4(r0,r1,r2,r3, sB + row*128 + ((ch^(row&7))*16));
                bfr[jj*2][0]=r0; bfr[jj*2][1]=r1;
                bfr[jj*2+1][0]=r2; bfr[jj*2+1][1]=r3;
            }
#pragma unroll
            for(int i=0;i<2;i++)
#pragma unroll
                for(int j=0;j<8;j++)
                    mma16816(acc[i][j],afr[i],bfr[j]);
        }
    }

#pragma unroll
    for(int i=0;i<2;i++){
        int r0=bm+wm+i*16+(l>>2);
        int r1=r0+8;
#pragma unroll
        for(int j=0;j<8;j++){
            int gn=bn+wn+j*8+2*(l&3);
            if(gn<N){
                if(r0<M) *(float2*)(C+(size_t)r0*ldc+gn)=make_float2(acc[i][j][0],acc[i][j][1]);
                if(r1<M) *(float2*)(C+(size_t)r1*ldc+gn)=make_float2(acc[i][j][2],acc[i][j][3]);
            }
        }
    }
}

__global__ void rsum_reduce()
{
    int r=blockIdx.x*blockDim.x+threadIdx.x;
    if(r>=TT*KT) return;
    float s=0.f;
    for(int i=0;i<NT2;i++) s+=g_rsumP[(size_t)r*NT2+i];
    g_invZ[r]=1.f/s;
}

// ---------------- bf16 operand prep ----------------
__global__ void prep_abf(const float* __restrict__ mu)
{
    int i=blockIdx.x*blockDim.x+threadIdx.x;
    if(i>=MT*128*KP) return;
    int r=i%KP, m=i/KP;
    float v=0.f;
    if(m<TT*KT && r<RHOD){
        int t=m/KT, k=m%KT;
        v=mu[((size_t)k*TT+t)*RHOD + r];
    }
    g_Abf[i]=__float2bfloat16(v);
}

__global__ void prep_bbf(const float* __restrict__ rho)
{
    int i=blockIdx.x*blockDim.x+threadIdx.x;
    if(i>=(int)(VP*KP)) return;
    int r=i%KP, v=i/KP;
    float x=(v<VV && r<RHOD)? rho[(size_t)v*RHOD+r] : 0.f;
    g_Bbf[i]=__float2bfloat16(x);
}

// generic fp32 -> padded bf16 [dstRows x KP2]
__global__ void conv_bf16(const float* __restrict__ src,int rows,int cols,int lds,
                          __nv_bfloat16* __restrict__ dst,int totalPairs)
{
    int i=blockIdx.x*blockDim.x+threadIdx.x;
    if(i>=totalPairs) return;
    int r=i/(KP2/2), c2=(i%(KP2/2))*2;
    float a=0.f,b=0.f;
    if(r<rows && c2+1<cols){
        a=src[(size_t)r*lds+c2];
        b=src[(size_t)r*lds+c2+1];
    } else if(r<rows && c2<cols){
        a=src[(size_t)r*lds+c2];
    }
    __nv_bfloat162 v;
    v.x=__float2bfloat16(a); v.y=__float2bfloat16(b);
    *(__nv_bfloat162*)(dst+(size_t)i*2)=v;
}

// ============ fp32 NT SGEMM (small GEMMs only) ============
template<int OP>
__global__ void __launch_bounds__(256)
sgemm128(int M,int N,int Kd,
         const float* __restrict__ A,int lda,
         const float* __restrict__ B,int ldb,
         float* __restrict__ C,int ldc,
         const float* __restrict__ bias1,const float* __restrict__ bias2)
{
    __shared__ float As[8][128];
    __shared__ float Bs[8][128];
    const int tid=threadIdx.x;
    const int bm=blockIdx.y*128, bn=blockIdx.x*128;
    int k0=0,k1=Kd;
    const int nz=gridDim.z;
    if(nz>1){
        int kChunk=((Kd + nz*8 - 1)/(nz*8))*8;
        k0=blockIdx.z*kChunk; k1=min(Kd,k0+kChunk);
        C += (size_t)blockIdx.z*(size_t)M*(size_t)ldc;
    }
    const int lr=tid>>1, kq=(tid&1)*4;
    const int tx=tid&15, ty=tid>>4;
    float acc[8][8];
#pragma unroll
    for(int i=0;i<8;i++)
#pragma unroll
        for(int j=0;j<8;j++) acc[i][j]=0.f;

    const bool aval=(bm+lr)<M, bval=(bn+lr)<N;
    const float* Ap=A+(size_t)(bm+lr)*lda;
    const float* Bp=B+(size_t)(bn+lr)*ldb;

    for(int kb=k0;kb<k1;kb+=8){
        float4 av=aval? *(const float4*)(Ap+kb+kq) : make_float4(0.f,0.f,0.f,0.f);
        float4 bv=bval? *(const float4*)(Bp+kb+kq) : make_float4(0.f,0.f,0.f,0.f);
        __syncthreads();
        As[kq+0][lr]=av.x; As[kq+1][lr]=av.y; As[kq+2][lr]=av.z; As[kq+3][lr]=av.w;
        Bs[kq+0][lr]=bv.x; Bs[kq+1][lr]=bv.y; Bs[kq+2][lr]=bv.z; Bs[kq+3][lr]=bv.w;
        __syncthreads();
#pragma unroll
        for(int kk=0;kk<8;kk++){
            float ar[8],br[8];
#pragma unroll
            for(int i=0;i<8;i++) ar[i]=As[kk][ty*8+i];
#pragma unroll
            for(int j=0;j<8;j++) br[j]=Bs[kk][tx*8+j];
#pragma unroll
            for(int i=0;i<8;i++)
#pragma unroll
                for(int j=0;j<8;j++) acc[i][j]=fmaf(ar[i],br[j],acc[i][j]);
        }
    }
    const bool raw=(nz>1);
#pragma unroll
    for(int i=0;i<8;i++){
        int gm=bm+ty*8+i; if(gm>=M) continue;
#pragma unroll
        for(int j=0;j<8;j++){
            int gn=bn+tx*8+j; if(gn>=N) continue;
            float v=acc[i][j];
            if(!raw){
                if(bias1) v+=bias1[gn];
                if(bias2) v+=bias2[gn];
                if(OP==1) v=fmaxf(v,0.f);
                else if(OP==2) v=expf(v);
            }
            C[(size_t)gm*ldc+gn]=v;
        }
    }
}

__global__ void reduce_split(const float* __restrict__ parts,int splits,int total,int N,
                             const float* __restrict__ bias1,const float* __restrict__ bias2,
                             int op, float* __restrict__ out)
{
    int i=blockIdx.x*blockDim.x+threadIdx.x;
    if(i>=total) return;
    float v=0.f;
    for(int z=0;z<splits;z++) v+=parts[(size_t)z*total+i];
    if(bias1) v+=bias1[i%N];
    if(bias2) v+=bias2[i%N];
    if(op==1) v=fmaxf(v,0.f);
    out[i]=v;
}

// ---------------- misc prep ----------------
__global__ void prep_whh(const float* __restrict__ whh)
{
    int i=blockIdx.x*blockDim.x+threadIdx.x;
    if(i>=EHH*4*EHH) return;
    int k=i/(4*EHH), j=i%(4*EHH);
    g_WhhT[i]=whh[(size_t)j*EHH + k];
}

__global__ void transpose_heads(const float* __restrict__ muEta,const float* __restrict__ lsEta,
                                const float* __restrict__ muTh,const float* __restrict__ lsTh)
{
    int i=blockIdx.x*blockDim.x+threadIdx.x;
    if(i<KT*EHH){
        int k=i/EHH, j=i%EHH;
        g_metaT[j*KT+k]=muEta[(size_t)k*(EHH+KT)+j];
        g_letaT[j*KT+k]=lsEta[(size_t)k*(EHH+KT)+j];
    }
    if(i<KT*THH){
        int k=i/THH, j=i%THH;
        g_mthT[j*KT+k]=muTh[(size_t)k*THH+j];
        g_lthT[j*KT+k]=lsTh[(size_t)k*THH+j];
    }
}

// ---------------- kl_alpha ----------------
__global__ void kl_alpha_kernel(const float* __restrict__ mu,const float* __restrict__ ls)
{
    __shared__ float red[128];
    int b=blockIdx.x; int t=b%TT;
    const float* mup=mu+(size_t)b*RHOD;
    const float* lsp=ls+(size_t)b*RHOD;
    const float* mpv=mu+(size_t)(b-1)*RHOD;
    float s=0.f;
    for(int r=threadIdx.x;r<RHOD;r+=128){
        float m=mup[r], l=lsp[r];
        if(t==0) s += (expf(l)+m*m)/(1.f+EPSF) - 1.f - l;
        else { float d=m-mpv[r]; s += (expf(l)+d*d)/(DELTAF+EPSF) - 1.f + LOG_DELTA_F - l; }
    }
    red[threadIdx.x]=s; __syncthreads();
    for(int off=64;off>0;off>>=1){ if(threadIdx.x<off) red[threadIdx.x]+=red[threadIdx.x+off]; __syncthreads(); }
    if(threadIdx.x==0) g_pa[b]=0.5f*red[0];
}

// ---------------- LSTM ----------------
__global__ void __launch_bounds__(4*EHH) lstm_kernel()
{
    __shared__ float hsm[EHH];
    __shared__ float zsm[4*EHH];
    const int s=blockIdx.x, j=threadIdx.x;
    float c=0.f;
    if(j<EHH) hsm[j]=0.f;
    __syncthreads();
    for(int t=0;t<TT;t++){
        float acc=g_xz[((size_t)s*TT+t)*(4*EHH)+j];
#pragma unroll 4
        for(int k=0;k<EHH;k++) acc=fmaf(hsm[k], g_WhhT[k*(4*EHH)+j], acc);
        zsm[j]=acc;
        __syncthreads();
        if(j<EHH){
            float ig=sigm_(zsm[j]), fg=sigm_(zsm[EHH+j]);
            float gg=tanhf(zsm[2*EHH+j]), og=sigm_(zsm[3*EHH+j]);
            c=fg*c+ig*gg;
            float h=og*tanhf(c);
            hsm[j]=h;
            g_lstm_out[((size_t)t*SSRC+s)*EHH+j]=h;
        }
        __syncthreads();
    }
}

// ---------------- eta base ----------------
__global__ void eta_base_kernel()
{
    int i=blockIdx.x*blockDim.x+threadIdx.x;
    if(i>=TT*SSRC*KT) return;
    int k=i%KT; int ts=i/KT;
    const float* h=g_lstm_out+(size_t)ts*EHH;
    float am=0.f, al=0.f;
    for(int j=0;j<EHH;j++){
        float hv=h[j];
        am=fmaf(hv,g_metaT[j*KT+k],am);
        al=fmaf(hv,g_letaT[j*KT+k],al);
    }
    g_base_mu[i]=am; g_base_ls[i]=al;
}

// ---------------- eta recurrence + kl_eta ----------------
__global__ void __launch_bounds__(512) eta_rec_kernel(const float* __restrict__ muW,const float* __restrict__ lsW,
                                                      const float* __restrict__ mub,const float* __restrict__ lsb)
{
    __shared__ float eprev[SSRC*KT];
    __shared__ float red[512];
    const int tid=threadIdx.x;
    const int s=tid/KT, k=tid%KT;
    const bool act = tid < SSRC*KT;
    float kl=0.f;
    if(act){
        float m=g_base_mu[tid]+mub[k];
        float l=g_base_ls[tid]+lsb[k];
        kl += (expf(l)+m*m)/(1.f+EPSF) - 1.f - l;
        eprev[tid]=m;
        g_etas[((size_t)s*TT+0)*KT+k]=m;
    }
    __syncthreads();
    for(int t=1;t<TT;t++){
        float m=0.f;
        if(act){
            m=g_base_mu[(size_t)t*SSRC*KT+tid]+mub[k];
            float l=g_base_ls[(size_t)t*SSRC*KT+tid]+lsb[k];
            const float* er=eprev+s*KT;
            const float* wm=muW+(size_t)k*(EHH+KT)+EHH;
            const float* wl=lsW+(size_t)k*(EHH+KT)+EHH;
#pragma unroll
            for(int k2=0;k2<KT;k2++){ float e=er[k2]; m=fmaf(e,wm[k2],m); l=fmaf(e,wl[k2],l); }
            l=fminf(fmaxf(l,-10.f),10.f);
            float d=m-eprev[tid];
            kl += (expf(l)+d*d)/(DELTAF+EPSF) - 1.f + LOG_DELTA_F - l;
        }
        __syncthreads();
        if(act){ eprev[tid]=m; g_etas[((size_t)s*TT+t)*KT+k]=m; }
        __syncthreads();
    }
    red[tid]=kl; __syncthreads();
    for(int off=256;off>0;off>>=1){ if(tid<off) red[tid]+=red[tid+off]; __syncthreads(); }
    if(tid==0) g_kleta[0]=0.5f*red[0];
}

__global__ void gather_eta(const int* __restrict__ sources,const int* __restrict__ times)
{
    int i=blockIdx.x*blockDim.x+threadIdx.x;
    if(i>=BB*KT) return;
    int b=i/KT, k=i%KT;
    g_eta_std[i]=g_etas[((size_t)sources[b]*TT+times[b])*KT+k];
}

// ---------------- h1 epilogue ----------------
__global__ void h1_epilogue(const float* __restrict__ W1,const float* __restrict__ b1)
{
    int i=blockIdx.x*blockDim.x+threadIdx.x;
    if(i>=BB*THH) return;
    int b=i/THH, j=i%THH;
    float v=0.f;
    for(int z=0;z<H1Z;z++) v+=g_part4[(size_t)z*BB*THH+i];
    v+=b1[j];
    const float* w=W1+(size_t)j*(VV+KT)+VV;
    const float* e=g_eta_std+(size_t)b*KT;
#pragma unroll
    for(int k=0;k<KT;k++) v=fmaf(e[k],w[k],v);
    g_h1[i]=fmaxf(v,0.f);
}

// ---------------- theta heads ----------------
__global__ void theta_head(const float* __restrict__ mub,const float* __restrict__ lsb)
{
    int i=blockIdx.x*blockDim.x+threadIdx.x;
    if(i>=BB*KT) return;
    int b=i/KT, k=i%KT;
    const float* h=g_h2+(size_t)b*THH;
    float am=mub[k], al=lsb[k];
    for(int j=0;j<THH;j++){
        float hv=h[j];
        am=fmaf(hv,g_mthT[j*KT+k],am);
        al=fmaf(hv,g_lthT[j*KT+k],al);
    }
    g_mu_t[i]=am;
    g_ls_t[i]=fminf(fmaxf(al,-10.f),10.f);
}

// ---------------- softmax(theta) + kl_theta ----------------
__global__ void softmax_kltheta()
{
    __shared__ float red[64];
    const int b=blockIdx.x, tid=threadIdx.x;
    float m=(tid<KT)? g_mu_t[(size_t)b*KT+tid] : -1e30f;
    red[tid]=m; __syncthreads();
    for(int off=32;off>0;off>>=1){ if(tid<off) red[tid]=fmaxf(red[tid],red[tid+off]); __syncthreads(); }
    float mx=red[0]; __syncthreads();
    float e=(tid<KT)? expf(m-mx) : 0.f;
    red[tid]=e; __syncthreads();
    for(int off=32;off>0;off>>=1){ if(tid<off) red[tid]+=red[tid+off]; __syncthreads(); }
    float Z=red[0]; __syncthreads();
    if(tid<KT) g_theta[(size_t)b*KT+tid]=e/Z;
    float term=0.f;
    if(tid<KT){
        float l=g_ls_t[(size_t)b*KT+tid];
        float d=m-g_eta_std[(size_t)b*KT+tid];
        term=(expf(l)+d*d)/(1.f+EPSF)-1.f-l;
    }
    red[tid]=term; __syncthreads();
    for(int off=32;off>0;off>>=1){ if(tid<off) red[tid]+=red[tid+off]; __syncthreads(); }
    if(tid==0) g_pth[b]=0.5f*red[0];
}

// ---------------- source prediction loss ----------------
__global__ void pred_kernel(const float* __restrict__ clsW,const float* __restrict__ clsb,
                            const int* __restrict__ sources)
{
    int b=blockIdx.x*blockDim.x+threadIdx.x;
    if(b>=BB) return;
    const float* th=g_theta+(size_t)b*KT;
    float lg[SSRC], mx=-1e30f;
#pragma unroll
    for(int i=0;i<SSRC;i++){
        float a=clsb[i];
        const float* w=clsW+(size_t)i*KT;
#pragma unroll
        for(int k=0;k<KT;k++) a=fmaf(th[k],w[k],a);
        lg[i]=a; mx=fmaxf(mx,a);
    }
    float se=0.f;
#pragma unroll
    for(int i=0;i<SSRC;i++) se+=expf(lg[i]-mx);
    float lse=mx+logf(se);
    g_ppred[b]=lse-lg[sources[b]];
}

// ---------------- NLL (docs grouped by time) ----------------
__global__ void wdoc_kernel(const int* __restrict__ times)
{
    int i=blockIdx.x*blockDim.x+threadIdx.x;
    if(i>=BB*KT) return;
    int b=i/KT, k=i%KT;
    g_wdoc[i]=g_theta[i]*g_invZ[times[b]*KT+k];
}

__global__ void doclist_kernel(const int* __restrict__ times)
{
    int t=threadIdx.x;
    if(t>=TT) return;
    int cnt=0;
    for(int b=0;b<BB;b++)
        if(times[b]==t) g_dlist[t*BB + (cnt++)]=b;
    g_dcnt[t]=cnt;
}

__global__ void __launch_bounds__(256) nll2_kernel(const float* __restrict__ bows)
{
    const int t=blockIdx.x, vt=blockIdx.y, tid=threadIdx.x;
    __shared__ float ws[32][KT];
    __shared__ int   dls[32];
    __shared__ float red[256];
    const int cnt=g_dcnt[t];
    float s=0.f;
    for(int d0=0; d0<cnt; d0+=32){
        int ch=min(32,cnt-d0);
        __syncthreads();
        for(int i=tid;i<ch*KT;i+=256){
            int d=i/KT, k=i%KT;
            int b=g_dlist[t*BB+d0+d];
            ws[d][k]=g_wdoc[(size_t)b*KT+k];
            if(k==0) dls[d]=b;
        }
        __syncthreads();
        for(int vi=0;vi<4;vi++){
            int v=vt*1024+vi*256+tid;
            if(v>=VV) break;
            float e[KT];
            const float* Ep=g_E+(size_t)t*KT*VV+v;
#pragma unroll
            for(int k=0;k<KT;k++) e[k]=Ep[(size_t)k*VV];
            for(int d=0;d<ch;d++){
                float mix=0.f;
#pragma unroll
                for(int k=0;k<KT;k++) mix=fmaf(ws[d][k],e[k],mix);
                s=fmaf(logf(mix), bows[(size_t)dls[d]*VV+v], s);
            }
        }
    }
    red[tid]=s; __syncthreads();
    for(int off=128;off>0;off>>=1){ if(tid<off) red[tid]+=red[tid+off]; __syncthreads(); }
    if(tid==0) g_pnllT[t*NVTILE+vt]=red[0];
}

// ---------------- final combine ----------------
__global__ void __launch_bounds__(256) final_kernel(const void* __restrict__ ndocs_ptr,
                                                    float* __restrict__ out)
{
    __shared__ float red[256];
    const int tid=threadIdx.x;
    float sa=0.f;
    for(int i=tid;i<KT*TT;i+=256) sa+=g_pa[i];
    red[tid]=sa; __syncthreads();
    for(int off=128;off>0;off>>=1){ if(tid<off) red[tid]+=red[tid+off]; __syncthreads(); }
    float kl_alpha=red[0]; __syncthreads();

    float sl=0.f;
    for(int i=tid;i<TT*NVTILE;i+=256) sl+=g_pnllT[i];
    red[tid]=sl; __syncthreads();
    for(int off=128;off>0;off>>=1){ if(tid<off) red[tid]+=red[tid+off]; __syncthreads(); }
    float sum_ll=red[0]; __syncthreads();

    red[tid]=g_pth[tid]; __syncthreads();
    for(int off=128;off>0;off>>=1){ if(tid<off) red[tid]+=red[tid+off]; __syncthreads(); }
    float sum_th=red[0]; __syncthreads();

    red[tid]=g_ppred[tid]; __syncthreads();
    for(int off=128;off>0;off>>=1){ if(tid<off) red[tid]+=red[tid+off]; __syncthreads(); }
    float sum_pred=red[0]; __syncthreads();

    if(tid==0){
        int v0=*(const int*)ndocs_ptr;
        float nd;
        if(v0>0 && v0<(1<<30)) nd=(float)v0;
        else nd=*(const float*)ndocs_ptr;
        float coeff=nd/(float)BB;
        float nll=-sum_ll*coeff;
        float kl_eta=g_kleta[0];
        float kl_theta=sum_th*coeff;
        float pred=sum_pred*coeff;
        float nelbo=nll+kl_alpha+kl_eta+kl_theta+pred;
        out[0]=nelbo; out[1]=nll; out[2]=kl_alpha;
        out[3]=kl_eta; out[4]=kl_theta; out[5]=pred;
    }
}

// ---------------- launcher ----------------
extern "C" void kernel_launch(void* const* d_in, const int* in_sizes, int n_in,
                              void* d_out, int out_size)
{
    const float* bows      =(const float*)d_in[1];
    const float* nbows     =(const float*)d_in[2];
    const int*   times     =(const int*)  d_in[3];
    const int*   sources   =(const int*)  d_in[4];
    const float* rnn_inp   =(const float*)d_in[5];
    const void*  num_docs  =               d_in[6];
    const float* mu_q_alpha=(const float*)d_in[7];
    const float* ls_q_alpha=(const float*)d_in[8];
    const float* rho_W     =(const float*)d_in[9];
    const float* W1        =(const float*)d_in[10];
    const float* b1        =(const float*)d_in[11];
    const float* W2        =(const float*)d_in[12];
    const float* b2        =(const float*)d_in[13];
    const float* mu_th_W   =(const float*)d_in[14];
    const float* mu_th_b   =(const float*)d_in[15];
    const float* ls_th_W   =(const float*)d_in[16];
    const float* ls_th_b   =(const float*)d_in[17];
    const float* eta_map_W =(const float*)d_in[18];
    const float* eta_map_b =(const float*)d_in[19];
    const float* lstm_Wih  =(const float*)d_in[20];
    const float* lstm_Whh  =(const float*)d_in[21];
    const float* lstm_bih  =(const float*)d_in[22];
    const float* lstm_bhh  =(const float*)d_in[23];
    const float* mu_eta_W  =(const float*)d_in[24];
    const float* mu_eta_b  =(const float*)d_in[25];
    const float* ls_eta_W  =(const float*)d_in[26];
    const float* ls_eta_b  =(const float*)d_in[27];
    const float* cls_W     =(const float*)d_in[28];
    const float* cls_b     =(const float*)d_in[29];
    float* out=(float*)d_out;

    float *E,*rsumP,*part1,*partx,*mapped,*xz,*part4,*part5,*h1,*h2;
    __nv_bfloat16 *Abf,*Bbf,*nbbf,*w1bf,*rnnbf,*emwbf;
    cudaGetSymbolAddress((void**)&Abf,g_Abf);
    cudaGetSymbolAddress((void**)&Bbf,g_Bbf);
    cudaGetSymbolAddress((void**)&nbbf,g_nbbf);
    cudaGetSymbolAddress((void**)&w1bf,g_w1bf);
    cudaGetSymbolAddress((void**)&rnnbf,g_rnnbf);
    cudaGetSymbolAddress((void**)&emwbf,g_emwbf);
    cudaGetSymbolAddress((void**)&E,g_E);
    cudaGetSymbolAddress((void**)&rsumP,g_rsumP);
    cudaGetSymbolAddress((void**)&part1,g_part1);
    cudaGetSymbolAddress((void**)&partx,g_partx);
    cudaGetSymbolAddress((void**)&mapped,g_mapped);
    cudaGetSymbolAddress((void**)&xz,g_xz);
    cudaGetSymbolAddress((void**)&part4,g_part4);
    cudaGetSymbolAddress((void**)&part5,g_part5);
    cudaGetSymbolAddress((void**)&h1,g_h1);
    cudaGetSymbolAddress((void**)&h2,g_h2);

    // ---- prep / conversions ----
    prep_whh<<<(EHH*4*EHH+255)/256,256>>>(lstm_Whh);
    prep_abf<<<(MT*128*KP+255)/256,256>>>(mu_q_alpha);
    prep_bbf<<<((int)(VP*KP)+255)/256,256>>>(rho_W);
    conv_bf16<<<(256*(KP2/2)+255)/256,256>>>(nbows,256,VV,VV, nbbf, 256*(KP2/2));
    conv_bf16<<<(896*(KP2/2)+255)/256,256>>>(W1,THH,VV,VV+KT, w1bf, 896*(KP2/2));
    conv_bf16<<<(512*(KP2/2)+255)/256,256>>>(rnn_inp,500,VV,VV, rnnbf, 512*(KP2/2));
    conv_bf16<<<(256*(KP2/2)+255)/256,256>>>(eta_map_W,EHH,VV,VV, emwbf, 256*(KP2/2));
    transpose_heads<<<(KT*THH+255)/256,256>>>(mu_eta_W, ls_eta_W, mu_th_W, ls_th_W);
    kl_alpha_kernel<<<KT*TT,128>>>(mu_q_alpha, ls_q_alpha);

    // ---- beta path ----
    {
        dim3 g(NT,MT,1);
        beta_hmma_kernel<<<g,256>>>(Abf,Bbf,E,rsumP);
    }
    rsum_reduce<<<(TT*KT+255)/256,256>>>();

    // ---- eta path: mapped = rnn_inp @ eta_map_W^T + b  (HMMA, splitK) ----
    {
        dim3 g(2,4,EMZ);   // N=200->2 tiles, M=500->4 tiles
        hmma_nt<<<g,256>>>(500,EHH,EHH,(KSTG+EMZ-1)/EMZ, rnnbf, emwbf, part1);
        reduce_split<<<(500*EHH+255)/256,256>>>(part1,EMZ,500*EHH,EHH, eta_map_b,nullptr,0, mapped);
    }
    {
        dim3 g((4*EHH+127)/128,(500+127)/128,4);
        sgemm128<0><<<g,256>>>(500,4*EHH,EHH, mapped,EHH, lstm_Wih,EHH,
                               partx,4*EHH, nullptr,nullptr);
        reduce_split<<<(500*4*EHH+255)/256,256>>>(partx,4,500*4*EHH,4*EHH, lstm_bih,lstm_bhh,0, xz);
    }
    lstm_kernel<<<SSRC,4*EHH>>>();
    eta_base_kernel<<<(TT*SSRC*KT+255)/256,256>>>();
    eta_rec_kernel<<<1,512>>>(mu_eta_W, ls_eta_W, mu_eta_b, ls_eta_b);
    gather_eta<<<(BB*KT+255)/256,256>>>(sources, times);

    // ---- theta path: h1 bow-part (HMMA, splitK) ----
    {
        dim3 g(7,2,H1Z);   // N=800->7 tiles, M=256->2 tiles
        hmma_nt<<<g,256>>>(BB,THH,THH,(KSTG+H1Z-1)/H1Z, nbbf, w1bf, part4);
    }
    h1_epilogue<<<(BB*THH+255)/256,256>>>(W1, b1);
    {
        dim3 g((THH+127)/128,(BB+127)/128,8);
        sgemm128<0><<<g,256>>>(BB,THH,THH, h1,THH, W2,THH,
                               part5,THH, nullptr,nullptr);
        reduce_split<<<(BB*THH+255)/256,256>>>(part5,8,BB*THH,THH, b2,nullptr,1, h2);
    }
    theta_head<<<(BB*KT+255)/256,256>>>(mu_th_b, ls_th_b);
    softmax_kltheta<<<BB,64>>>();
    pred_kernel<<<1,BB>>>(cls_W, cls_b, sources);

    // ---- NLL ----
    wdoc_kernel<<<(BB*KT+255)/256,256>>>(times);
    doclist_kernel<<<1,64>>>(times);
    {
        dim3 g(TT,NVTILE,1);
        nll2_kernel<<<g,256>>>(bows);
    }

    // ---- combine ----
    final_kernel<<<1,256>>>(num_docs, out);
    (void)in_sizes; (void)n_in; (void)out_size;
}

// round 8
// speedup vs baseline: 2.6866x; 1.0273x over previous
#include <cuda_runtime.h>
#include <cuda_bf16.h>
#include <math.h>
#include <stdint.h>

#define KT   50
#define TT   50
#define RHOD 300
#define KP   320
#define VV   20000
#define KP2  20032
#define KCH  2504
#define KSTG 313
#define VP   20096
#define NT   157
#define NT2  (2*NT)
#define MT   20
#define THH  800
#define EHH  200
#define SSRC 10
#define BB   256
#define H1Z  21
#define EMZ  35
#define DELTAF 0.005f
#define LOG_DELTA_F (-5.2983173665480363f)
#define EPSF 1e-6f
#define NVTILE 20

// ---------------- device scratch ----------------
__device__ __align__(16) __nv_bfloat16 g_Abf[(size_t)MT*128*KP];
__device__ __align__(16) __nv_bfloat16 g_Bbf[(size_t)VP*KP];
__device__ __align__(16) __nv_bfloat16 g_nbbf[(size_t)256*KP2];
__device__ __align__(16) __nv_bfloat16 g_w1bf[(size_t)896*KP2];
__device__ __align__(16) __nv_bfloat16 g_rnnbf[(size_t)512*KP2];
__device__ __align__(16) __nv_bfloat16 g_emwbf[(size_t)256*KP2];
__device__ __align__(16) float g_E[(size_t)TT*KT*VV];
__device__ float g_rsumP[(size_t)TT*KT*NT2];
__device__ float g_invZ[TT*KT];
__device__ __align__(16) float g_part1[EMZ*500*EHH];
__device__ __align__(16) float g_partx[4*500*4*EHH];
__device__ __align__(16) float g_mapped[500*EHH];
__device__ __align__(16) float g_xz[500*4*EHH];
__device__ float g_WhhT[EHH*4*EHH];
__device__ float g_lstm_out[TT*SSRC*EHH];
__device__ float g_base_mu[TT*SSRC*KT];
__device__ float g_base_ls[TT*SSRC*KT];
__device__ float g_etas[SSRC*TT*KT];
__device__ float g_eta_std[BB*KT];
__device__ __align__(16) float g_part4[H1Z*BB*THH];
__device__ __align__(16) float g_part5[8*BB*THH];
__device__ __align__(16) float g_h1[BB*THH];
__device__ __align__(16) float g_h2[BB*THH];
__device__ float g_mu_t[BB*KT];
__device__ float g_ls_t[BB*KT];
__device__ float g_theta[BB*KT];
__device__ float g_wdoc[BB*KT];
__device__ float g_metaT[EHH*KT];
__device__ float g_letaT[EHH*KT];
__device__ float g_mthT[THH*KT];
__device__ float g_lthT[THH*KT];
__device__ int   g_dlist[TT*BB];
__device__ int   g_dcnt[TT];
__device__ float g_pa[KT*TT];
__device__ float g_pnllT[TT*NVTILE];
__device__ float g_pth[BB];
__device__ float g_ppred[BB];
__device__ float g_kleta[1];

__device__ __forceinline__ float sigm_(float x){ return 1.f/(1.f+expf(-x)); }

// ---------------- HMMA / async primitives ----------------
__device__ __forceinline__ void ldsm_x4(uint32_t& r0,uint32_t& r1,uint32_t& r2,uint32_t& r3,uint32_t a){
    asm volatile("ldmatrix.sync.aligned.m8n8.x4.shared.b16 {%0,%1,%2,%3}, [%4];"
                 : "=r"(r0),"=r"(r1),"=r"(r2),"=r"(r3) : "r"(a));
}
__device__ __forceinline__ void mma16816(float* d,const uint32_t* a,const uint32_t* b){
    asm volatile("mma.sync.aligned.m16n8k16.row.col.f32.bf16.bf16.f32 "
        "{%0,%1,%2,%3}, {%4,%5,%6,%7}, {%8,%9}, {%0,%1,%2,%3};"
        : "+f"(d[0]),"+f"(d[1]),"+f"(d[2]),"+f"(d[3])
        : "r"(a[0]),"r"(a[1]),"r"(a[2]),"r"(a[3]), "r"(b[0]),"r"(b[1]));
}
__device__ __forceinline__ void cpasync16(uint32_t dst, const void* src){
    asm volatile("cp.async.cg.shared.global [%0], [%1], 16;" :: "r"(dst), "l"(src));
}
__device__ __forceinline__ void cpcommit(){ asm volatile("cp.async.commit_group;" ::: "memory"); }

// ================= beta HMMA: E = exp(A @ B^T), fused rowsum ==============
// double-buffered cp.async pipeline; dyn smem = 2 x (16KB A + 16KB B) = 64KB
__global__ void __launch_bounds__(256,2)
beta_hmma_kernel(const __nv_bfloat16* __restrict__ Abf,
                 const __nv_bfloat16* __restrict__ Bbf,
                 float* __restrict__ E, float* __restrict__ rsumP)
{
    extern __shared__ __align__(16) uint8_t smem[];
    const int tid=threadIdx.x, l=tid&31, wid=tid>>5;
    const int wm=(wid&3)*32, wn=(wid>>2)*64;
    const int bn=blockIdx.x*128, bm=blockIdx.y*128;
    const uint32_t sbase=(uint32_t)__cvta_generic_to_shared(smem);
    const uint4* Ag=(const uint4*)Abf;
    const uint4* Bg=(const uint4*)Bbf;

    float acc[2][8][4];
#pragma unroll
    for(int i=0;i<2;i++)
#pragma unroll
        for(int j=0;j<8;j++)
#pragma unroll
            for(int q=0;q<4;q++) acc[i][j][q]=0.f;

    const int ar_=(l&15), ac_=(l>>4);
    const int br_=(l&7)+((l>>4)&1)*8, bc_=(l>>3)&1;

    // per-thread load geometry (4 chunks each for A and B per stage)
    const int lrow=tid>>3, lcol=tid&7;     // covers rows 0..31 per it-step
    // issue stage s into buffer (s&1)
    auto issue=[&](int s){
        uint32_t sb=sbase+(uint32_t)(s&1)*32768u;
#pragma unroll
        for(int it=0;it<4;it++){
            int row=lrow+32*it;
            uint32_t off=(uint32_t)row*128u + (uint32_t)((lcol^(row&7))*16);
            cpasync16(sb+off,        &Ag[(size_t)(bm+row)*40 + s*8 + lcol]);
            cpasync16(sb+16384u+off, &Bg[(size_t)(bn+row)*40 + s*8 + lcol]);
        }
        cpcommit();
    };

    issue(0);
#pragma unroll
    for(int s=0;s<5;s++){
        if(s<4) issue(s+1);
        if(s<4) asm volatile("cp.async.wait_group 1;" ::: "memory");
        else    asm volatile("cp.async.wait_group 0;" ::: "memory");
        __syncthreads();
        const uint32_t sA=sbase+(uint32_t)(s&1)*32768u;
        const uint32_t sB=sA+16384u;
#pragma unroll
        for(int ks=0;ks<4;ks++){
            uint32_t afr[2][4];
#pragma unroll
            for(int i=0;i<2;i++){
                int row=wm+i*16+ar_;
                int ch=ks*2+ac_;
                ldsm_x4(afr[i][0],afr[i][1],afr[i][2],afr[i][3],
                        sA + row*128 + ((ch^(row&7))*16));
            }
            uint32_t bfr[8][2];
#pragma unroll
            for(int jj=0;jj<4;jj++){
                int row=wn+jj*16+br_;
                int ch=ks*2+bc_;
                uint32_t r0,r1,r2,r3;
                ldsm_x4(r0,r1,r2,r3, sB + row*128 + ((ch^(row&7))*16));
                bfr[jj*2][0]=r0; bfr[jj*2][1]=r1;
                bfr[jj*2+1][0]=r2; bfr[jj*2+1][1]=r3;
            }
#pragma unroll
            for(int i=0;i<2;i++)
#pragma unroll
                for(int j=0;j<8;j++)
                    mma16816(acc[i][j],afr[i],bfr[j]);
        }
        __syncthreads();
    }

#pragma unroll
    for(int i=0;i<2;i++){
        int r0=bm+wm+i*16+(l>>2);
        int r1=r0+8;
        float s0=0.f,s1=0.f;
#pragma unroll
        for(int j=0;j<8;j++){
            int gn=bn+wn+j*8+2*(l&3);
            bool v=gn<VV;
            float e0=expf(acc[i][j][0]), e1=expf(acc[i][j][1]);
            float e2=expf(acc[i][j][2]), e3=expf(acc[i][j][3]);
            if(v){
                if(r0<TT*KT) *(float2*)(E+(size_t)r0*VV+gn)=make_float2(e0,e1);
                if(r1<TT*KT) *(float2*)(E+(size_t)r1*VV+gn)=make_float2(e2,e3);
                s0+=e0+e1; s1+=e2+e3;
            }
        }
        s0+=__shfl_xor_sync(0xffffffffu,s0,1); s0+=__shfl_xor_sync(0xffffffffu,s0,2);
        s1+=__shfl_xor_sync(0xffffffffu,s1,1); s1+=__shfl_xor_sync(0xffffffffu,s1,2);
        if((l&3)==0){
            int slot=blockIdx.x*2+(wid>>2);
            if(r0<TT*KT) rsumP[(size_t)r0*NT2+slot]=s0;
            if(r1<TT*KT) rsumP[(size_t)r1*NT2+slot]=s1;
        }
    }
}

// ============ generic HMMA NT GEMM, splitK raw partials, cp.async ============
__global__ void __launch_bounds__(256,2)
hmma_nt(int M,int N,int ldc,int stagesPer,
        const __nv_bfloat16* __restrict__ A,
        const __nv_bfloat16* __restrict__ B,
        float* __restrict__ C)
{
    extern __shared__ __align__(16) uint8_t smem[];
    const int tid=threadIdx.x, l=tid&31, wid=tid>>5;
    const int wm=(wid&3)*32, wn=(wid>>2)*64;
    const int bn=blockIdx.x*128, bm=blockIdx.y*128;
    const int s0=blockIdx.z*stagesPer;
    const int s1=min(KSTG, s0+stagesPer);
    C += (size_t)blockIdx.z*(size_t)M*(size_t)ldc;
    const uint32_t sbase=(uint32_t)__cvta_generic_to_shared(smem);
    const uint4* Ag=(const uint4*)A;
    const uint4* Bg=(const uint4*)B;

    float acc[2][8][4];
#pragma unroll
    for(int i=0;i<2;i++)
#pragma unroll
        for(int j=0;j<8;j++)
#pragma unroll
            for(int q=0;q<4;q++) acc[i][j][q]=0.f;

    const int ar_=(l&15), ac_=(l>>4);
    const int br_=(l&7)+((l>>4)&1)*8, bc_=(l>>3)&1;
    const int lrow=tid>>3, lcol=tid&7;

    auto issue=[&](int s){
        uint32_t sb=sbase+(uint32_t)(s&1)*32768u;
#pragma unroll
        for(int it=0;it<4;it++){
            int row=lrow+32*it;
            uint32_t off=(uint32_t)row*128u + (uint32_t)((lcol^(row&7))*16);
            cpasync16(sb+off,        &Ag[(size_t)(bm+row)*KCH + s*8 + lcol]);
            cpasync16(sb+16384u+off, &Bg[(size_t)(bn+row)*KCH + s*8 + lcol]);
        }
        cpcommit();
    };

    issue(s0);
    for(int s=s0;s<s1;s++){
        if(s+1<s1) issue(s+1);
        if(s+1<s1) asm volatile("cp.async.wait_group 1;" ::: "memory");
        else       asm volatile("cp.async.wait_group 0;" ::: "memory");
        __syncthreads();
        const uint32_t sA=sbase+(uint32_t)(s&1)*32768u;
        const uint32_t sB=sA+16384u;
#pragma unroll
        for(int ks=0;ks<4;ks++){
            uint32_t afr[2][4];
#pragma unroll
            for(int i=0;i<2;i++){
                int row=wm+i*16+ar_;
                int ch=ks*2+ac_;
                ldsm_x4(afr[i][0],afr[i][1],afr[i][2],afr[i][3],
                        sA + row*128 + ((ch^(row&7))*16));
            }
            uint32_t bfr[8][2];
#pragma unroll
            for(int jj=0;jj<4;jj++){
                int row=wn+jj*16+br_;
                int ch=ks*2+bc_;
                uint32_t r0,r1,r2,r3;
                ldsm_x4(r0,r1,r2,r3, sB + row*128 + ((ch^(row&7))*16));
                bfr[jj*2][0]=r0; bfr[jj*2][1]=r1;
                bfr[jj*2+1][0]=r2; bfr[jj*2+1][1]=r3;
            }
#pragma unroll
            for(int i=0;i<2;i++)
#pragma unroll
                for(int j=0;j<8;j++)
                    mma16816(acc[i][j],afr[i],bfr[j]);
        }
        __syncthreads();
    }

#pragma unroll
    for(int i=0;i<2;i++){
        int r0=bm+wm+i*16+(l>>2);
        int r1=r0+8;
#pragma unroll
        for(int j=0;j<8;j++){
            int gn=bn+wn+j*8+2*(l&3);
            if(gn<N){
                if(r0<M) *(float2*)(C+(size_t)r0*ldc+gn)=make_float2(acc[i][j][0],acc[i][j][1]);
                if(r1<M) *(float2*)(C+(size_t)r1*ldc+gn)=make_float2(acc[i][j][2],acc[i][j][3]);
            }
        }
    }
}

__global__ void rsum_reduce()
{
    int r=blockIdx.x*blockDim.x+threadIdx.x;
    if(r>=TT*KT) return;
    float s=0.f;
    for(int i=0;i<NT2;i++) s+=g_rsumP[(size_t)r*NT2+i];
    g_invZ[r]=1.f/s;
}

// ---------------- bf16 operand prep ----------------
__global__ void prep_abf(const float* __restrict__ mu)
{
    int i=blockIdx.x*blockDim.x+threadIdx.x;
    if(i>=MT*128*KP) return;
    int r=i%KP, m=i/KP;
    float v=0.f;
    if(m<TT*KT && r<RHOD){
        int t=m/KT, k=m%KT;
        v=mu[((size_t)k*TT+t)*RHOD + r];
    }
    g_Abf[i]=__float2bfloat16(v);
}

__global__ void prep_bbf(const float* __restrict__ rho)
{
    int i=blockIdx.x*blockDim.x+threadIdx.x;
    if(i>=(int)(VP*KP)) return;
    int r=i%KP, v=i/KP;
    float x=(v<VV && r<RHOD)? rho[(size_t)v*RHOD+r] : 0.f;
    g_Bbf[i]=__float2bfloat16(x);
}

__global__ void conv_bf16(const float* __restrict__ src,int rows,int cols,int lds,
                          __nv_bfloat16* __restrict__ dst,int totalPairs)
{
    int i=blockIdx.x*blockDim.x+threadIdx.x;
    if(i>=totalPairs) return;
    int r=i/(KP2/2), c2=(i%(KP2/2))*2;
    float a=0.f,b=0.f;
    if(r<rows && c2+1<cols){
        a=src[(size_t)r*lds+c2];
        b=src[(size_t)r*lds+c2+1];
    } else if(r<rows && c2<cols){
        a=src[(size_t)r*lds+c2];
    }
    __nv_bfloat162 v;
    v.x=__float2bfloat16(a); v.y=__float2bfloat16(b);
    *(__nv_bfloat162*)(dst+(size_t)i*2)=v;
}

// ============ fp32 NT SGEMM (small GEMMs only) ============
template<int OP>
__global__ void __launch_bounds__(256)
sgemm128(int M,int N,int Kd,
         const float* __restrict__ A,int lda,
         const float* __restrict__ B,int ldb,
         float* __restrict__ C,int ldc,
         const float* __restrict__ bias1,const float* __restrict__ bias2)
{
    __shared__ float As[8][128];
    __shared__ float Bs[8][128];
    const int tid=threadIdx.x;
    const int bm=blockIdx.y*128, bn=blockIdx.x*128;
    int k0=0,k1=Kd;
    const int nz=gridDim.z;
    if(nz>1){
        int kChunk=((Kd + nz*8 - 1)/(nz*8))*8;
        k0=blockIdx.z*kChunk; k1=min(Kd,k0+kChunk);
        C += (size_t)blockIdx.z*(size_t)M*(size_t)ldc;
    }
    const int lr=tid>>1, kq=(tid&1)*4;
    const int tx=tid&15, ty=tid>>4;
    float acc[8][8];
#pragma unroll
    for(int i=0;i<8;i++)
#pragma unroll
        for(int j=0;j<8;j++) acc[i][j]=0.f;

    const bool aval=(bm+lr)<M, bval=(bn+lr)<N;
    const float* Ap=A+(size_t)(bm+lr)*lda;
    const float* Bp=B+(size_t)(bn+lr)*ldb;

    for(int kb=k0;kb<k1;kb+=8){
        float4 av=aval? *(const float4*)(Ap+kb+kq) : make_float4(0.f,0.f,0.f,0.f);
        float4 bv=bval? *(const float4*)(Bp+kb+kq) : make_float4(0.f,0.f,0.f,0.f);
        __syncthreads();
        As[kq+0][lr]=av.x; As[kq+1][lr]=av.y; As[kq+2][lr]=av.z; As[kq+3][lr]=av.w;
        Bs[kq+0][lr]=bv.x; Bs[kq+1][lr]=bv.y; Bs[kq+2][lr]=bv.z; Bs[kq+3][lr]=bv.w;
        __syncthreads();
#pragma unroll
        for(int kk=0;kk<8;kk++){
            float ar[8],br[8];
#pragma unroll
            for(int i=0;i<8;i++) ar[i]=As[kk][ty*8+i];
#pragma unroll
            for(int j=0;j<8;j++) br[j]=Bs[kk][tx*8+j];
#pragma unroll
            for(int i=0;i<8;i++)
#pragma unroll
                for(int j=0;j<8;j++) acc[i][j]=fmaf(ar[i],br[j],acc[i][j]);
        }
    }
    const bool raw=(nz>1);
#pragma unroll
    for(int i=0;i<8;i++){
        int gm=bm+ty*8+i; if(gm>=M) continue;
#pragma unroll
        for(int j=0;j<8;j++){
            int gn=bn+tx*8+j; if(gn>=N) continue;
            float v=acc[i][j];
            if(!raw){
                if(bias1) v+=bias1[gn];
                if(bias2) v+=bias2[gn];
                if(OP==1) v=fmaxf(v,0.f);
                else if(OP==2) v=expf(v);
            }
            C[(size_t)gm*ldc+gn]=v;
        }
    }
}

__global__ void reduce_split(const float* __restrict__ parts,int splits,int total,int N,
                             const float* __restrict__ bias1,const float* __restrict__ bias2,
                             int op, float* __restrict__ out)
{
    int i=blockIdx.x*blockDim.x+threadIdx.x;
    if(i>=total) return;
    float v=0.f;
    for(int z=0;z<splits;z++) v+=parts[(size_t)z*total+i];
    if(bias1) v+=bias1[i%N];
    if(bias2) v+=bias2[i%N];
    if(op==1) v=fmaxf(v,0.f);
    out[i]=v;
}

// ---------------- misc prep ----------------
__global__ void prep_whh(const float* __restrict__ whh)
{
    int i=blockIdx.x*blockDim.x+threadIdx.x;
    if(i>=EHH*4*EHH) return;
    int k=i/(4*EHH), j=i%(4*EHH);
    g_WhhT[i]=whh[(size_t)j*EHH + k];
}

__global__ void transpose_heads(const float* __restrict__ muEta,const float* __restrict__ lsEta,
                                const float* __restrict__ muTh,const float* __restrict__ lsTh)
{
    int i=blockIdx.x*blockDim.x+threadIdx.x;
    if(i<KT*EHH){
        int k=i/EHH, j=i%EHH;
        g_metaT[j*KT+k]=muEta[(size_t)k*(EHH+KT)+j];
        g_letaT[j*KT+k]=lsEta[(size_t)k*(EHH+KT)+j];
    }
    if(i<KT*THH){
        int k=i/THH, j=i%THH;
        g_mthT[j*KT+k]=muTh[(size_t)k*THH+j];
        g_lthT[j*KT+k]=lsTh[(size_t)k*THH+j];
    }
}

// ---------------- kl_alpha ----------------
__global__ void kl_alpha_kernel(const float* __restrict__ mu,const float* __restrict__ ls)
{
    __shared__ float red[128];
    int b=blockIdx.x; int t=b%TT;
    const float* mup=mu+(size_t)b*RHOD;
    const float* lsp=ls+(size_t)b*RHOD;
    const float* mpv=mu+(size_t)(b-1)*RHOD;
    float s=0.f;
    for(int r=threadIdx.x;r<RHOD;r+=128){
        float m=mup[r], l=lsp[r];
        if(t==0) s += (expf(l)+m*m)/(1.f+EPSF) - 1.f - l;
        else { float d=m-mpv[r]; s += (expf(l)+d*d)/(DELTAF+EPSF) - 1.f + LOG_DELTA_F - l; }
    }
    red[threadIdx.x]=s; __syncthreads();
    for(int off=64;off>0;off>>=1){ if(threadIdx.x<off) red[threadIdx.x]+=red[threadIdx.x+off]; __syncthreads(); }
    if(threadIdx.x==0) g_pa[b]=0.5f*red[0];
}

// ---------------- LSTM ----------------
__global__ void __launch_bounds__(4*EHH) lstm_kernel()
{
    __shared__ float hsm[EHH];
    __shared__ float zsm[4*EHH];
    const int s=blockIdx.x, j=threadIdx.x;
    float c=0.f;
    if(j<EHH) hsm[j]=0.f;
    __syncthreads();
    for(int t=0;t<TT;t++){
        float acc=g_xz[((size_t)s*TT+t)*(4*EHH)+j];
#pragma unroll 4
        for(int k=0;k<EHH;k++) acc=fmaf(hsm[k], g_WhhT[k*(4*EHH)+j], acc);
        zsm[j]=acc;
        __syncthreads();
        if(j<EHH){
            float ig=sigm_(zsm[j]), fg=sigm_(zsm[EHH+j]);
            float gg=tanhf(zsm[2*EHH+j]), og=sigm_(zsm[3*EHH+j]);
            c=fg*c+ig*gg;
            float h=og*tanhf(c);
            hsm[j]=h;
            g_lstm_out[((size_t)t*SSRC+s)*EHH+j]=h;
        }
        __syncthreads();
    }
}

// ---------------- eta base ----------------
__global__ void eta_base_kernel()
{
    int i=blockIdx.x*blockDim.x+threadIdx.x;
    if(i>=TT*SSRC*KT) return;
    int k=i%KT; int ts=i/KT;
    const float* h=g_lstm_out+(size_t)ts*EHH;
    float am=0.f, al=0.f;
    for(int j=0;j<EHH;j++){
        float hv=h[j];
        am=fmaf(hv,g_metaT[j*KT+k],am);
        al=fmaf(hv,g_letaT[j*KT+k],al);
    }
    g_base_mu[i]=am; g_base_ls[i]=al;
}

// ---------------- eta recurrence + kl_eta ----------------
__global__ void __launch_bounds__(512) eta_rec_kernel(const float* __restrict__ muW,const float* __restrict__ lsW,
                                                      const float* __restrict__ mub,const float* __restrict__ lsb)
{
    __shared__ float eprev[SSRC*KT];
    __shared__ float red[512];
    const int tid=threadIdx.x;
    const int s=tid/KT, k=tid%KT;
    const bool act = tid < SSRC*KT;
    float kl=0.f;
    if(act){
        float m=g_base_mu[tid]+mub[k];
        float l=g_base_ls[tid]+lsb[k];
        kl += (expf(l)+m*m)/(1.f+EPSF) - 1.f - l;
        eprev[tid]=m;
        g_etas[((size_t)s*TT+0)*KT+k]=m;
    }
    __syncthreads();
    for(int t=1;t<TT;t++){
        float m=0.f;
        if(act){
            m=g_base_mu[(size_t)t*SSRC*KT+tid]+mub[k];
            float l=g_base_ls[(size_t)t*SSRC*KT+tid]+lsb[k];
            const float* er=eprev+s*KT;
            const float* wm=muW+(size_t)k*(EHH+KT)+EHH;
            const float* wl=lsW+(size_t)k*(EHH+KT)+EHH;
#pragma unroll
            for(int k2=0;k2<KT;k2++){ float e=er[k2]; m=fmaf(e,wm[k2],m); l=fmaf(e,wl[k2],l); }
            l=fminf(fmaxf(l,-10.f),10.f);
            float d=m-eprev[tid];
            kl += (expf(l)+d*d)/(DELTAF+EPSF) - 1.f + LOG_DELTA_F - l;
        }
        __syncthreads();
        if(act){ eprev[tid]=m; g_etas[((size_t)s*TT+t)*KT+k]=m; }
        __syncthreads();
    }
    red[tid]=kl; __syncthreads();
    for(int off=256;off>0;off>>=1){ if(tid<off) red[tid]+=red[tid+off]; __syncthreads(); }
    if(tid==0) g_kleta[0]=0.5f*red[0];
}

__global__ void gather_eta(const int* __restrict__ sources,const int* __restrict__ times)
{
    int i=blockIdx.x*blockDim.x+threadIdx.x;
    if(i>=BB*KT) return;
    int b=i/KT, k=i%KT;
    g_eta_std[i]=g_etas[((size_t)sources[b]*TT+times[b])*KT+k];
}

// ---------------- h1 epilogue ----------------
__global__ void h1_epilogue(const float* __restrict__ W1,const float* __restrict__ b1)
{
    int i=blockIdx.x*blockDim.x+threadIdx.x;
    if(i>=BB*THH) return;
    int b=i/THH, j=i%THH;
    float v=0.f;
    for(int z=0;z<H1Z;z++) v+=g_part4[(size_t)z*BB*THH+i];
    v+=b1[j];
    const float* w=W1+(size_t)j*(VV+KT)+VV;
    const float* e=g_eta_std+(size_t)b*KT;
#pragma unroll
    for(int k=0;k<KT;k++) v=fmaf(e[k],w[k],v);
    g_h1[i]=fmaxf(v,0.f);
}

// ---------------- theta heads ----------------
__global__ void theta_head(const float* __restrict__ mub,const float* __restrict__ lsb)
{
    int i=blockIdx.x*blockDim.x+threadIdx.x;
    if(i>=BB*KT) return;
    int b=i/KT, k=i%KT;
    const float* h=g_h2+(size_t)b*THH;
    float am=mub[k], al=lsb[k];
    for(int j=0;j<THH;j++){
        float hv=h[j];
        am=fmaf(hv,g_mthT[j*KT+k],am);
        al=fmaf(hv,g_lthT[j*KT+k],al);
    }
    g_mu_t[i]=am;
    g_ls_t[i]=fminf(fmaxf(al,-10.f),10.f);
}

// ---------------- softmax(theta) + kl_theta ----------------
__global__ void softmax_kltheta()
{
    __shared__ float red[64];
    const int b=blockIdx.x, tid=threadIdx.x;
    float m=(tid<KT)? g_mu_t[(size_t)b*KT+tid] : -1e30f;
    red[tid]=m; __syncthreads();
    for(int off=32;off>0;off>>=1){ if(tid<off) red[tid]=fmaxf(red[tid],red[tid+off]); __syncthreads(); }
    float mx=red[0]; __syncthreads();
    float e=(tid<KT)? expf(m-mx) : 0.f;
    red[tid]=e; __syncthreads();
    for(int off=32;off>0;off>>=1){ if(tid<off) red[tid]+=red[tid+off]; __syncthreads(); }
    float Z=red[0]; __syncthreads();
    if(tid<KT) g_theta[(size_t)b*KT+tid]=e/Z;
    float term=0.f;
    if(tid<KT){
        float l=g_ls_t[(size_t)b*KT+tid];
        float d=m-g_eta_std[(size_t)b*KT+tid];
        term=(expf(l)+d*d)/(1.f+EPSF)-1.f-l;
    }
    red[tid]=term; __syncthreads();
    for(int off=32;off>0;off>>=1){ if(tid<off) red[tid]+=red[tid+off]; __syncthreads(); }
    if(tid==0) g_pth[b]=0.5f*red[0];
}

// ---------------- source prediction loss ----------------
__global__ void pred_kernel(const float* __restrict__ clsW,const float* __restrict__ clsb,
                            const int* __restrict__ sources)
{
    int b=blockIdx.x*blockDim.x+threadIdx.x;
    if(b>=BB) return;
    const float* th=g_theta+(size_t)b*KT;
    float lg[SSRC], mx=-1e30f;
#pragma unroll
    for(int i=0;i<SSRC;i++){
        float a=clsb[i];
        const float* w=clsW+(size_t)i*KT;
#pragma unroll
        for(int k=0;k<KT;k++) a=fmaf(th[k],w[k],a);
        lg[i]=a; mx=fmaxf(mx,a);
    }
    float se=0.f;
#pragma unroll
    for(int i=0;i<SSRC;i++) se+=expf(lg[i]-mx);
    float lse=mx+logf(se);
    g_ppred[b]=lse-lg[sources[b]];
}

// ---------------- NLL (docs grouped by time) ----------------
__global__ void wdoc_kernel(const int* __restrict__ times)
{
    int i=blockIdx.x*blockDim.x+threadIdx.x;
    if(i>=BB*KT) return;
    int b=i/KT, k=i%KT;
    g_wdoc[i]=g_theta[i]*g_invZ[times[b]*KT+k];
}

__global__ void doclist_kernel(const int* __restrict__ times)
{
    int t=threadIdx.x;
    if(t>=TT) return;
    int cnt=0;
    for(int b=0;b<BB;b++)
        if(times[b]==t) g_dlist[t*BB + (cnt++)]=b;
    g_dcnt[t]=cnt;
}

__global__ void __launch_bounds__(256) nll2_kernel(const float* __restrict__ bows)
{
    const int t=blockIdx.x, vt=blockIdx.y, tid=threadIdx.x;
    __shared__ float ws[32][KT];
    __shared__ int   dls[32];
    __shared__ float red[256];
    const int cnt=g_dcnt[t];
    float s=0.f;
    for(int d0=0; d0<cnt; d0+=32){
        int ch=min(32,cnt-d0);
        __syncthreads();
        for(int i=tid;i<ch*KT;i+=256){
            int d=i/KT, k=i%KT;
            int b=g_dlist[t*BB+d0+d];
            ws[d][k]=g_wdoc[(size_t)b*KT+k];
            if(k==0) dls[d]=b;
        }
        __syncthreads();
        for(int vi=0;vi<4;vi++){
            int v=vt*1024+vi*256+tid;
            if(v>=VV) break;
            float e[KT];
            const float* Ep=g_E+(size_t)t*KT*VV+v;
#pragma unroll
            for(int k=0;k<KT;k++) e[k]=Ep[(size_t)k*VV];
            for(int d=0;d<ch;d++){
                float mix=0.f;
#pragma unroll
                for(int k=0;k<KT;k++) mix=fmaf(ws[d][k],e[k],mix);
                s=fmaf(logf(mix), bows[(size_t)dls[d]*VV+v], s);
            }
        }
    }
    red[tid]=s; __syncthreads();
    for(int off=128;off>0;off>>=1){ if(tid<off) red[tid]+=red[tid+off]; __syncthreads(); }
    if(tid==0) g_pnllT[t*NVTILE+vt]=red[0];
}

// ---------------- final combine ----------------
__global__ void __launch_bounds__(256) final_kernel(const void* __restrict__ ndocs_ptr,
                                                    float* __restrict__ out)
{
    __shared__ float red[256];
    const int tid=threadIdx.x;
    float sa=0.f;
    for(int i=tid;i<KT*TT;i+=256) sa+=g_pa[i];
    red[tid]=sa; __syncthreads();
    for(int off=128;off>0;off>>=1){ if(tid<off) red[tid]+=red[tid+off]; __syncthreads(); }
    float kl_alpha=red[0]; __syncthreads();

    float sl=0.f;
    for(int i=tid;i<TT*NVTILE;i+=256) sl+=g_pnllT[i];
    red[tid]=sl; __syncthreads();
    for(int off=128;off>0;off>>=1){ if(tid<off) red[tid]+=red[tid+off]; __syncthreads(); }
    float sum_ll=red[0]; __syncthreads();

    red[tid]=g_pth[tid]; __syncthreads();
    for(int off=128;off>0;off>>=1){ if(tid<off) red[tid]+=red[tid+off]; __syncthreads(); }
    float sum_th=red[0]; __syncthreads();

    red[tid]=g_ppred[tid]; __syncthreads();
    for(int off=128;off>0;off>>=1){ if(tid<off) red[tid]+=red[tid+off]; __syncthreads(); }
    float sum_pred=red[0]; __syncthreads();

    if(tid==0){
        int v0=*(const int*)ndocs_ptr;
        float nd;
        if(v0>0 && v0<(1<<30)) nd=(float)v0;
        else nd=*(const float*)ndocs_ptr;
        float coeff=nd/(float)BB;
        float nll=-sum_ll*coeff;
        float kl_eta=g_kleta[0];
        float kl_theta=sum_th*coeff;
        float pred=sum_pred*coeff;
        float nelbo=nll+kl_alpha+kl_eta+kl_theta+pred;
        out[0]=nelbo; out[1]=nll; out[2]=kl_alpha;
        out[3]=kl_eta; out[4]=kl_theta; out[5]=pred;
    }
}

// ---------------- launcher ----------------
extern "C" void kernel_launch(void* const* d_in, const int* in_sizes, int n_in,
                              void* d_out, int out_size)
{
    const float* bows      =(const float*)d_in[1];
    const float* nbows     =(const float*)d_in[2];
    const int*   times     =(const int*)  d_in[3];
    const int*   sources   =(const int*)  d_in[4];
    const float* rnn_inp   =(const float*)d_in[5];
    const void*  num_docs  =               d_in[6];
    const float* mu_q_alpha=(const float*)d_in[7];
    const float* ls_q_alpha=(const float*)d_in[8];
    const float* rho_W     =(const float*)d_in[9];
    const float* W1        =(const float*)d_in[10];
    const float* b1        =(const float*)d_in[11];
    const float* W2        =(const float*)d_in[12];
    const float* b2        =(const float*)d_in[13];
    const float* mu_th_W   =(const float*)d_in[14];
    const float* mu_th_b   =(const float*)d_in[15];
    const float* ls_th_W   =(const float*)d_in[16];
    const float* ls_th_b   =(const float*)d_in[17];
    const float* eta_map_W =(const float*)d_in[18];
    const float* eta_map_b =(const float*)d_in[19];
    const float* lstm_Wih  =(const float*)d_in[20];
    const float* lstm_Whh  =(const float*)d_in[21];
    const float* lstm_bih  =(const float*)d_in[22];
    const float* lstm_bhh  =(const float*)d_in[23];
    const float* mu_eta_W  =(const float*)d_in[24];
    const float* mu_eta_b  =(const float*)d_in[25];
    const float* ls_eta_W  =(const float*)d_in[26];
    const float* ls_eta_b  =(const float*)d_in[27];
    const float* cls_W     =(const float*)d_in[28];
    const float* cls_b     =(const float*)d_in[29];
    float* out=(float*)d_out;

    float *E,*rsumP,*part1,*partx,*mapped,*xz,*part4,*part5,*h1,*h2;
    __nv_bfloat16 *Abf,*Bbf,*nbbf,*w1bf,*rnnbf,*emwbf;
    cudaGetSymbolAddress((void**)&Abf,g_Abf);
    cudaGetSymbolAddress((void**)&Bbf,g_Bbf);
    cudaGetSymbolAddress((void**)&nbbf,g_nbbf);
    cudaGetSymbolAddress((void**)&w1bf,g_w1bf);
    cudaGetSymbolAddress((void**)&rnnbf,g_rnnbf);
    cudaGetSymbolAddress((void**)&emwbf,g_emwbf);
    cudaGetSymbolAddress((void**)&E,g_E);
    cudaGetSymbolAddress((void**)&rsumP,g_rsumP);
    cudaGetSymbolAddress((void**)&part1,g_part1);
    cudaGetSymbolAddress((void**)&partx,g_partx);
    cudaGetSymbolAddress((void**)&mapped,g_mapped);
    cudaGetSymbolAddress((void**)&xz,g_xz);
    cudaGetSymbolAddress((void**)&part4,g_part4);
    cudaGetSymbolAddress((void**)&part5,g_part5);
    cudaGetSymbolAddress((void**)&h1,g_h1);
    cudaGetSymbolAddress((void**)&h2,g_h2);

    static int attr_done=0;
    if(!attr_done){
        cudaFuncSetAttribute(beta_hmma_kernel, cudaFuncAttributeMaxDynamicSharedMemorySize, 65536);
        cudaFuncSetAttribute(hmma_nt, cudaFuncAttributeMaxDynamicSharedMemorySize, 65536);
        attr_done=1;
    }

    // ---- prep / conversions ----
    prep_whh<<<(EHH*4*EHH+255)/256,256>>>(lstm_Whh);
    prep_abf<<<(MT*128*KP+255)/256,256>>>(mu_q_alpha);
    prep_bbf<<<((int)(VP*KP)+255)/256,256>>>(rho_W);
    conv_bf16<<<(256*(KP2/2)+255)/256,256>>>(nbows,256,VV,VV, nbbf, 256*(KP2/2));
    conv_bf16<<<(896*(KP2/2)+255)/256,256>>>(W1,THH,VV,VV+KT, w1bf, 896*(KP2/2));
    conv_bf16<<<(512*(KP2/2)+255)/256,256>>>(rnn_inp,500,VV,VV, rnnbf, 512*(KP2/2));
    conv_bf16<<<(256*(KP2/2)+255)/256,256>>>(eta_map_W,EHH,VV,VV, emwbf, 256*(KP2/2));
    transpose_heads<<<(KT*THH+255)/256,256>>>(mu_eta_W, ls_eta_W, mu_th_W, ls_th_W);
    kl_alpha_kernel<<<KT*TT,128>>>(mu_q_alpha, ls_q_alpha);

    // ---- beta path ----
    {
        dim3 g(NT,MT,1);
        beta_hmma_kernel<<<g,256,65536>>>(Abf,Bbf,E,rsumP);
    }
    rsum_reduce<<<(TT*KT+255)/256,256>>>();

    // ---- eta path ----
    {
        dim3 g(2,4,EMZ);
        hmma_nt<<<g,256,65536>>>(500,EHH,EHH,(KSTG+EMZ-1)/EMZ, rnnbf, emwbf, part1);
        reduce_split<<<(500*EHH+255)/256,256>>>(part1,EMZ,500*EHH,EHH, eta_map_b,nullptr,0, mapped);
    }
    {
        dim3 g((4*EHH+127)/128,(500+127)/128,4);
        sgemm128<0><<<g,256>>>(500,4*EHH,EHH, mapped,EHH, lstm_Wih,EHH,
                               partx,4*EHH, nullptr,nullptr);
        reduce_split<<<(500*4*EHH+255)/256,256>>>(partx,4,500*4*EHH,4*EHH, lstm_bih,lstm_bhh,0, xz);
    }
    lstm_kernel<<<SSRC,4*EHH>>>();
    eta_base_kernel<<<(TT*SSRC*KT+255)/256,256>>>();
    eta_rec_kernel<<<1,512>>>(mu_eta_W, ls_eta_W, mu_eta_b, ls_eta_b);
    gather_eta<<<(BB*KT+255)/256,256>>>(sources, times);

    // ---- theta path ----
    {
        dim3 g(7,2,H1Z);
        hmma_nt<<<g,256,65536>>>(BB,THH,THH,(KSTG+H1Z-1)/H1Z, nbbf, w1bf, part4);
    }
    h1_epilogue<<<(BB*THH+255)/256,256>>>(W1, b1);
    {
        dim3 g((THH+127)/128,(BB+127)/128,8);
        sgemm128<0><<<g,256>>>(BB,THH,THH, h1,THH, W2,THH,
                               part5,THH, nullptr,nullptr);
        reduce_split<<<(BB*THH+255)/256,256>>>(part5,8,BB*THH,THH, b2,nullptr,1, h2);
    }
    theta_head<<<(BB*KT+255)/256,256>>>(mu_th_b, ls_th_b);
    softmax_kltheta<<<BB,64>>>();
    pred_kernel<<<1,BB>>>(cls_W, cls_b, sources);

    // ---- NLL ----
    wdoc_kernel<<<(BB*KT+255)/256,256>>>(times);
    doclist_kernel<<<1,64>>>(times);
    {
        dim3 g(TT,NVTILE,1);
        nll2_kernel<<<g,256>>>(bows);
    }

    // ---- combine ----
    final_kernel<<<1,256>>>(num_docs, out);
    (void)in_sizes; (void)n_in; (void)out_size;
}

// round 9
// speedup vs baseline: 2.7748x; 1.0328x over previous
#include <cuda_runtime.h>
#include <cuda_bf16.h>
#include <math.h>
#include <stdint.h>

#define KT   50
#define TT   50
#define RHOD 300
#define KP   320
#define VV   20000
#define KP2  20032
#define KCH  2504
#define KSTG 313
#define VP   20096
#define NT   157
#define NT2  (2*NT)
#define MT   20
#define THH  800
#define EHH  200
#define SSRC 10
#define BB   256
#define H1Z  21
#define EMZ  35
#define DELTAF 0.005f
#define LOG_DELTA_F (-5.2983173665480363f)
#define EPSF 1e-6f
#define NVTILE 20

// ---------------- device scratch ----------------
__device__ __align__(16) __nv_bfloat16 g_Abf[(size_t)MT*128*KP];
__device__ __align__(16) __nv_bfloat16 g_Bbf[(size_t)VP*KP];
__device__ __align__(16) __nv_bfloat16 g_nbbf[(size_t)256*KP2];
__device__ __align__(16) __nv_bfloat16 g_w1bf[(size_t)896*KP2];
__device__ __align__(16) __nv_bfloat16 g_rnnbf[(size_t)512*KP2];
__device__ __align__(16) __nv_bfloat16 g_emwbf[(size_t)256*KP2];
__device__ __align__(16) __nv_bfloat16 g_E[(size_t)TT*KT*VV];   // bf16 now (100MB)
__device__ float g_rsumP[(size_t)TT*KT*NT2];
__device__ float g_invZ[TT*KT];
__device__ __align__(16) float g_part1[EMZ*500*EHH];
__device__ __align__(16) float g_partx[4*500*4*EHH];
__device__ __align__(16) float g_mapped[500*EHH];
__device__ __align__(16) float g_xz[500*4*EHH];
__device__ float g_WhhT[EHH*4*EHH];
__device__ float g_lstm_out[TT*SSRC*EHH];
__device__ float g_base_mu[TT*SSRC*KT];
__device__ float g_base_ls[TT*SSRC*KT];
__device__ float g_etas[SSRC*TT*KT];
__device__ float g_eta_std[BB*KT];
__device__ __align__(16) float g_part4[H1Z*BB*THH];
__device__ __align__(16) float g_part5[8*BB*THH];
__device__ __align__(16) float g_h1[BB*THH];
__device__ __align__(16) float g_h2[BB*THH];
__device__ float g_mu_t[BB*KT];
__device__ float g_ls_t[BB*KT];
__device__ float g_theta[BB*KT];
__device__ float g_wdoc[BB*KT];
__device__ float g_metaT[EHH*KT];
__device__ float g_letaT[EHH*KT];
__device__ float g_mthT[THH*KT];
__device__ float g_lthT[THH*KT];
__device__ int   g_dlist[TT*BB];
__device__ int   g_dcnt[TT];
__device__ float g_pa[KT*TT];
__device__ float g_pnllT[TT*NVTILE];
__device__ float g_pth[BB];
__device__ float g_ppred[BB];
__device__ float g_kleta[1];

__device__ __forceinline__ float sigm_(float x){ return 1.f/(1.f+expf(-x)); }

// ---------------- HMMA / async primitives ----------------
__device__ __forceinline__ void ldsm_x4(uint32_t& r0,uint32_t& r1,uint32_t& r2,uint32_t& r3,uint32_t a){
    asm volatile("ldmatrix.sync.aligned.m8n8.x4.shared.b16 {%0,%1,%2,%3}, [%4];"
                 : "=r"(r0),"=r"(r1),"=r"(r2),"=r"(r3) : "r"(a));
}
__device__ __forceinline__ void mma16816(float* d,const uint32_t* a,const uint32_t* b){
    asm volatile("mma.sync.aligned.m16n8k16.row.col.f32.bf16.bf16.f32 "
        "{%0,%1,%2,%3}, {%4,%5,%6,%7}, {%8,%9}, {%0,%1,%2,%3};"
        : "+f"(d[0]),"+f"(d[1]),"+f"(d[2]),"+f"(d[3])
        : "r"(a[0]),"r"(a[1]),"r"(a[2]),"r"(a[3]), "r"(b[0]),"r"(b[1]));
}
__device__ __forceinline__ void cpasync16(uint32_t dst, const void* src){
    asm volatile("cp.async.cg.shared.global [%0], [%1], 16;" :: "r"(dst), "l"(src));
}
__device__ __forceinline__ void cpcommit(){ asm volatile("cp.async.commit_group;" ::: "memory"); }

// ================= beta HMMA: E = exp(A @ B^T) bf16 out, fused rowsum =====
__global__ void __launch_bounds__(256,2)
beta_hmma_kernel(const __nv_bfloat16* __restrict__ Abf,
                 const __nv_bfloat16* __restrict__ Bbf,
                 __nv_bfloat16* __restrict__ E, float* __restrict__ rsumP)
{
    extern __shared__ __align__(16) uint8_t smem[];
    const int tid=threadIdx.x, l=tid&31, wid=tid>>5;
    const int wm=(wid&3)*32, wn=(wid>>2)*64;
    const int bn=blockIdx.x*128, bm=blockIdx.y*128;
    const uint32_t sbase=(uint32_t)__cvta_generic_to_shared(smem);
    const uint4* Ag=(const uint4*)Abf;
    const uint4* Bg=(const uint4*)Bbf;

    float acc[2][8][4];
#pragma unroll
    for(int i=0;i<2;i++)
#pragma unroll
        for(int j=0;j<8;j++)
#pragma unroll
            for(int q=0;q<4;q++) acc[i][j][q]=0.f;

    const int ar_=(l&15), ac_=(l>>4);
    const int br_=(l&7)+((l>>4)&1)*8, bc_=(l>>3)&1;
    const int lrow=tid>>3, lcol=tid&7;

    auto issue=[&](int s){
        uint32_t sb=sbase+(uint32_t)(s&1)*32768u;
#pragma unroll
        for(int it=0;it<4;it++){
            int row=lrow+32*it;
            uint32_t off=(uint32_t)row*128u + (uint32_t)((lcol^(row&7))*16);
            cpasync16(sb+off,        &Ag[(size_t)(bm+row)*40 + s*8 + lcol]);
            cpasync16(sb+16384u+off, &Bg[(size_t)(bn+row)*40 + s*8 + lcol]);
        }
        cpcommit();
    };

    issue(0);
#pragma unroll
    for(int s=0;s<5;s++){
        if(s<4) issue(s+1);
        if(s<4) asm volatile("cp.async.wait_group 1;" ::: "memory");
        else    asm volatile("cp.async.wait_group 0;" ::: "memory");
        __syncthreads();
        const uint32_t sA=sbase+(uint32_t)(s&1)*32768u;
        const uint32_t sB=sA+16384u;
#pragma unroll
        for(int ks=0;ks<4;ks++){
            uint32_t afr[2][4];
#pragma unroll
            for(int i=0;i<2;i++){
                int row=wm+i*16+ar_;
                int ch=ks*2+ac_;
                ldsm_x4(afr[i][0],afr[i][1],afr[i][2],afr[i][3],
                        sA + row*128 + ((ch^(row&7))*16));
            }
            uint32_t bfr[8][2];
#pragma unroll
            for(int jj=0;jj<4;jj++){
                int row=wn+jj*16+br_;
                int ch=ks*2+bc_;
                uint32_t r0,r1,r2,r3;
                ldsm_x4(r0,r1,r2,r3, sB + row*128 + ((ch^(row&7))*16));
                bfr[jj*2][0]=r0; bfr[jj*2][1]=r1;
                bfr[jj*2+1][0]=r2; bfr[jj*2+1][1]=r3;
            }
#pragma unroll
            for(int i=0;i<2;i++)
#pragma unroll
                for(int j=0;j<8;j++)
                    mma16816(acc[i][j],afr[i],bfr[j]);
        }
        __syncthreads();
    }

#pragma unroll
    for(int i=0;i<2;i++){
        int r0=bm+wm+i*16+(l>>2);
        int r1=r0+8;
        float s0=0.f,s1=0.f;
#pragma unroll
        for(int j=0;j<8;j++){
            int gn=bn+wn+j*8+2*(l&3);
            bool v=gn<VV;
            float e0=expf(acc[i][j][0]), e1=expf(acc[i][j][1]);
            float e2=expf(acc[i][j][2]), e3=expf(acc[i][j][3]);
            if(v){
                __nv_bfloat162 p01, p23;
                p01.x=__float2bfloat16(e0); p01.y=__float2bfloat16(e1);
                p23.x=__float2bfloat16(e2); p23.y=__float2bfloat16(e3);
                if(r0<TT*KT) *(__nv_bfloat162*)(E+(size_t)r0*VV+gn)=p01;
                if(r1<TT*KT) *(__nv_bfloat162*)(E+(size_t)r1*VV+gn)=p23;
                s0+=e0+e1; s1+=e2+e3;
            }
        }
        s0+=__shfl_xor_sync(0xffffffffu,s0,1); s0+=__shfl_xor_sync(0xffffffffu,s0,2);
        s1+=__shfl_xor_sync(0xffffffffu,s1,1); s1+=__shfl_xor_sync(0xffffffffu,s1,2);
        if((l&3)==0){
            int slot=blockIdx.x*2+(wid>>2);
            if(r0<TT*KT) rsumP[(size_t)r0*NT2+slot]=s0;
            if(r1<TT*KT) rsumP[(size_t)r1*NT2+slot]=s1;
        }
    }
}

// ============ generic HMMA NT GEMM, splitK raw partials, cp.async ============
__global__ void __launch_bounds__(256,2)
hmma_nt(int M,int N,int ldc,int stagesPer,
        const __nv_bfloat16* __restrict__ A,
        const __nv_bfloat16* __restrict__ B,
        float* __restrict__ C)
{
    extern __shared__ __align__(16) uint8_t smem[];
    const int tid=threadIdx.x, l=tid&31, wid=tid>>5;
    const int wm=(wid&3)*32, wn=(wid>>2)*64;
    const int bn=blockIdx.x*128, bm=blockIdx.y*128;
    const int s0=blockIdx.z*stagesPer;
    const int s1=min(KSTG, s0+stagesPer);
    C += (size_t)blockIdx.z*(size_t)M*(size_t)ldc;
    const uint32_t sbase=(uint32_t)__cvta_generic_to_shared(smem);
    const uint4* Ag=(const uint4*)A;
    const uint4* Bg=(const uint4*)B;

    float acc[2][8][4];
#pragma unroll
    for(int i=0;i<2;i++)
#pragma unroll
        for(int j=0;j<8;j++)
#pragma unroll
            for(int q=0;q<4;q++) acc[i][j][q]=0.f;

    const int ar_=(l&15), ac_=(l>>4);
    const int br_=(l&7)+((l>>4)&1)*8, bc_=(l>>3)&1;
    const int lrow=tid>>3, lcol=tid&7;

    auto issue=[&](int s){
        uint32_t sb=sbase+(uint32_t)(s&1)*32768u;
#pragma unroll
        for(int it=0;it<4;it++){
            int row=lrow+32*it;
            uint32_t off=(uint32_t)row*128u + (uint32_t)((lcol^(row&7))*16);
            cpasync16(sb+off,        &Ag[(size_t)(bm+row)*KCH + s*8 + lcol]);
            cpasync16(sb+16384u+off, &Bg[(size_t)(bn+row)*KCH + s*8 + lcol]);
        }
        cpcommit();
    };

    issue(s0);
    for(int s=s0;s<s1;s++){
        if(s+1<s1) issue(s+1);
        if(s+1<s1) asm volatile("cp.async.wait_group 1;" ::: "memory");
        else       asm volatile("cp.async.wait_group 0;" ::: "memory");
        __syncthreads();
        const uint32_t sA=sbase+(uint32_t)(s&1)*32768u;
        const uint32_t sB=sA+16384u;
#pragma unroll
        for(int ks=0;ks<4;ks++){
            uint32_t afr[2][4];
#pragma unroll
            for(int i=0;i<2;i++){
                int row=wm+i*16+ar_;
                int ch=ks*2+ac_;
                ldsm_x4(afr[i][0],afr[i][1],afr[i][2],afr[i][3],
                        sA + row*128 + ((ch^(row&7))*16));
            }
            uint32_t bfr[8][2];
#pragma unroll
            for(int jj=0;jj<4;jj++){
                int row=wn+jj*16+br_;
                int ch=ks*2+bc_;
                uint32_t r0,r1,r2,r3;
                ldsm_x4(r0,r1,r2,r3, sB + row*128 + ((ch^(row&7))*16));
                bfr[jj*2][0]=r0; bfr[jj*2][1]=r1;
                bfr[jj*2+1][0]=r2; bfr[jj*2+1][1]=r3;
            }
#pragma unroll
            for(int i=0;i<2;i++)
#pragma unroll
                for(int j=0;j<8;j++)
                    mma16816(acc[i][j],afr[i],bfr[j]);
        }
        __syncthreads();
    }

#pragma unroll
    for(int i=0;i<2;i++){
        int r0=bm+wm+i*16+(l>>2);
        int r1=r0+8;
#pragma unroll
        for(int j=0;j<8;j++){
            int gn=bn+wn+j*8+2*(l&3);
            if(gn<N){
                if(r0<M) *(float2*)(C+(size_t)r0*ldc+gn)=make_float2(acc[i][j][0],acc[i][j][1]);
                if(r1<M) *(float2*)(C+(size_t)r1*ldc+gn)=make_float2(acc[i][j][2],acc[i][j][3]);
            }
        }
    }
}

__global__ void rsum_reduce()
{
    int r=blockIdx.x*blockDim.x+threadIdx.x;
    if(r>=TT*KT) return;
    float s=0.f;
    for(int i=0;i<NT2;i++) s+=g_rsumP[(size_t)r*NT2+i];
    g_invZ[r]=1.f/s;
}

// ---------------- bf16 operand prep ----------------
__global__ void prep_abf(const float* __restrict__ mu)
{
    int i=blockIdx.x*blockDim.x+threadIdx.x;
    if(i>=MT*128*KP) return;
    int r=i%KP, m=i/KP;
    float v=0.f;
    if(m<TT*KT && r<RHOD){
        int t=m/KT, k=m%KT;
        v=mu[((size_t)k*TT+t)*RHOD + r];
    }
    g_Abf[i]=__float2bfloat16(v);
}

__global__ void prep_bbf(const float* __restrict__ rho)
{
    int i=blockIdx.x*blockDim.x+threadIdx.x;
    if(i>=(int)(VP*KP)) return;
    int r=i%KP, v=i/KP;
    float x=(v<VV && r<RHOD)? rho[(size_t)v*RHOD+r] : 0.f;
    g_Bbf[i]=__float2bfloat16(x);
}

__global__ void conv_bf16(const float* __restrict__ src,int rows,int cols,int lds,
                          __nv_bfloat16* __restrict__ dst,int totalPairs)
{
    int i=blockIdx.x*blockDim.x+threadIdx.x;
    if(i>=totalPairs) return;
    int r=i/(KP2/2), c2=(i%(KP2/2))*2;
    float a=0.f,b=0.f;
    if(r<rows && c2+1<cols){
        a=src[(size_t)r*lds+c2];
        b=src[(size_t)r*lds+c2+1];
    } else if(r<rows && c2<cols){
        a=src[(size_t)r*lds+c2];
    }
    __nv_bfloat162 v;
    v.x=__float2bfloat16(a); v.y=__float2bfloat16(b);
    *(__nv_bfloat162*)(dst+(size_t)i*2)=v;
}

// ============ fp32 NT SGEMM (small GEMMs only) ============
template<int OP>
__global__ void __launch_bounds__(256)
sgemm128(int M,int N,int Kd,
         const float* __restrict__ A,int lda,
         const float* __restrict__ B,int ldb,
         float* __restrict__ C,int ldc,
         const float* __restrict__ bias1,const float* __restrict__ bias2)
{
    __shared__ float As[8][128];
    __shared__ float Bs[8][128];
    const int tid=threadIdx.x;
    const int bm=blockIdx.y*128, bn=blockIdx.x*128;
    int k0=0,k1=Kd;
    const int nz=gridDim.z;
    if(nz>1){
        int kChunk=((Kd + nz*8 - 1)/(nz*8))*8;
        k0=blockIdx.z*kChunk; k1=min(Kd,k0+kChunk);
        C += (size_t)blockIdx.z*(size_t)M*(size_t)ldc;
    }
    const int lr=tid>>1, kq=(tid&1)*4;
    const int tx=tid&15, ty=tid>>4;
    float acc[8][8];
#pragma unroll
    for(int i=0;i<8;i++)
#pragma unroll
        for(int j=0;j<8;j++) acc[i][j]=0.f;

    const bool aval=(bm+lr)<M, bval=(bn+lr)<N;
    const float* Ap=A+(size_t)(bm+lr)*lda;
    const float* Bp=B+(size_t)(bn+lr)*ldb;

    for(int kb=k0;kb<k1;kb+=8){
        float4 av=aval? *(const float4*)(Ap+kb+kq) : make_float4(0.f,0.f,0.f,0.f);
        float4 bv=bval? *(const float4*)(Bp+kb+kq) : make_float4(0.f,0.f,0.f,0.f);
        __syncthreads();
        As[kq+0][lr]=av.x; As[kq+1][lr]=av.y; As[kq+2][lr]=av.z; As[kq+3][lr]=av.w;
        Bs[kq+0][lr]=bv.x; Bs[kq+1][lr]=bv.y; Bs[kq+2][lr]=bv.z; Bs[kq+3][lr]=bv.w;
        __syncthreads();
#pragma unroll
        for(int kk=0;kk<8;kk++){
            float ar[8],br[8];
#pragma unroll
            for(int i=0;i<8;i++) ar[i]=As[kk][ty*8+i];
#pragma unroll
            for(int j=0;j<8;j++) br[j]=Bs[kk][tx*8+j];
#pragma unroll
            for(int i=0;i<8;i++)
#pragma unroll
                for(int j=0;j<8;j++) acc[i][j]=fmaf(ar[i],br[j],acc[i][j]);
        }
    }
    const bool raw=(nz>1);
#pragma unroll
    for(int i=0;i<8;i++){
        int gm=bm+ty*8+i; if(gm>=M) continue;
#pragma unroll
        for(int j=0;j<8;j++){
            int gn=bn+tx*8+j; if(gn>=N) continue;
            float v=acc[i][j];
            if(!raw){
                if(bias1) v+=bias1[gn];
                if(bias2) v+=bias2[gn];
                if(OP==1) v=fmaxf(v,0.f);
                else if(OP==2) v=expf(v);
            }
            C[(size_t)gm*ldc+gn]=v;
        }
    }
}

__global__ void reduce_split(const float* __restrict__ parts,int splits,int total,int N,
                             const float* __restrict__ bias1,const float* __restrict__ bias2,
                             int op, float* __restrict__ out)
{
    int i=blockIdx.x*blockDim.x+threadIdx.x;
    if(i>=total) return;
    float v=0.f;
    for(int z=0;z<splits;z++) v+=parts[(size_t)z*total+i];
    if(bias1) v+=bias1[i%N];
    if(bias2) v+=bias2[i%N];
    if(op==1) v=fmaxf(v,0.f);
    out[i]=v;
}

// ---------------- misc prep ----------------
__global__ void prep_whh(const float* __restrict__ whh)
{
    int i=blockIdx.x*blockDim.x+threadIdx.x;
    if(i>=EHH*4*EHH) return;
    int k=i/(4*EHH), j=i%(4*EHH);
    g_WhhT[i]=whh[(size_t)j*EHH + k];
}

__global__ void transpose_heads(const float* __restrict__ muEta,const float* __restrict__ lsEta,
                                const float* __restrict__ muTh,const float* __restrict__ lsTh)
{
    int i=blockIdx.x*blockDim.x+threadIdx.x;
    if(i<KT*EHH){
        int k=i/EHH, j=i%EHH;
        g_metaT[j*KT+k]=muEta[(size_t)k*(EHH+KT)+j];
        g_letaT[j*KT+k]=lsEta[(size_t)k*(EHH+KT)+j];
    }
    if(i<KT*THH){
        int k=i/THH, j=i%THH;
        g_mthT[j*KT+k]=muTh[(size_t)k*THH+j];
        g_lthT[j*KT+k]=lsTh[(size_t)k*THH+j];
    }
}

// ---------------- kl_alpha ----------------
__global__ void kl_alpha_kernel(const float* __restrict__ mu,const float* __restrict__ ls)
{
    __shared__ float red[128];
    int b=blockIdx.x; int t=b%TT;
    const float* mup=mu+(size_t)b*RHOD;
    const float* lsp=ls+(size_t)b*RHOD;
    const float* mpv=mu+(size_t)(b-1)*RHOD;
    float s=0.f;
    for(int r=threadIdx.x;r<RHOD;r+=128){
        float m=mup[r], l=lsp[r];
        if(t==0) s += (expf(l)+m*m)/(1.f+EPSF) - 1.f - l;
        else { float d=m-mpv[r]; s += (expf(l)+d*d)/(DELTAF+EPSF) - 1.f + LOG_DELTA_F - l; }
    }
    red[threadIdx.x]=s; __syncthreads();
    for(int off=64;off>0;off>>=1){ if(threadIdx.x<off) red[threadIdx.x]+=red[threadIdx.x+off]; __syncthreads(); }
    if(threadIdx.x==0) g_pa[b]=0.5f*red[0];
}

// ---------------- LSTM ----------------
__global__ void __launch_bounds__(4*EHH) lstm_kernel()
{
    __shared__ float hsm[EHH];
    __shared__ float zsm[4*EHH];
    const int s=blockIdx.x, j=threadIdx.x;
    float c=0.f;
    if(j<EHH) hsm[j]=0.f;
    __syncthreads();
    for(int t=0;t<TT;t++){
        float acc=g_xz[((size_t)s*TT+t)*(4*EHH)+j];
#pragma unroll 4
        for(int k=0;k<EHH;k++) acc=fmaf(hsm[k], g_WhhT[k*(4*EHH)+j], acc);
        zsm[j]=acc;
        __syncthreads();
        if(j<EHH){
            float ig=sigm_(zsm[j]), fg=sigm_(zsm[EHH+j]);
            float gg=tanhf(zsm[2*EHH+j]), og=sigm_(zsm[3*EHH+j]);
            c=fg*c+ig*gg;
            float h=og*tanhf(c);
            hsm[j]=h;
            g_lstm_out[((size_t)t*SSRC+s)*EHH+j]=h;
        }
        __syncthreads();
    }
}

// ---------------- eta base ----------------
__global__ void eta_base_kernel()
{
    int i=blockIdx.x*blockDim.x+threadIdx.x;
    if(i>=TT*SSRC*KT) return;
    int k=i%KT; int ts=i/KT;
    const float* h=g_lstm_out+(size_t)ts*EHH;
    float am=0.f, al=0.f;
    for(int j=0;j<EHH;j++){
        float hv=h[j];
        am=fmaf(hv,g_metaT[j*KT+k],am);
        al=fmaf(hv,g_letaT[j*KT+k],al);
    }
    g_base_mu[i]=am; g_base_ls[i]=al;
}

// ---------------- eta recurrence + kl_eta ----------------
__global__ void __launch_bounds__(512) eta_rec_kernel(const float* __restrict__ muW,const float* __restrict__ lsW,
                                                      const float* __restrict__ mub,const float* __restrict__ lsb)
{
    __shared__ float eprev[SSRC*KT];
    __shared__ float red[512];
    const int tid=threadIdx.x;
    const int s=tid/KT, k=tid%KT;
    const bool act = tid < SSRC*KT;
    float kl=0.f;
    if(act){
        float m=g_base_mu[tid]+mub[k];
        float l=g_base_ls[tid]+lsb[k];
        kl += (expf(l)+m*m)/(1.f+EPSF) - 1.f - l;
        eprev[tid]=m;
        g_etas[((size_t)s*TT+0)*KT+k]=m;
    }
    __syncthreads();
    for(int t=1;t<TT;t++){
        float m=0.f;
        if(act){
            m=g_base_mu[(size_t)t*SSRC*KT+tid]+mub[k];
            float l=g_base_ls[(size_t)t*SSRC*KT+tid]+lsb[k];
            const float* er=eprev+s*KT;
            const float* wm=muW+(size_t)k*(EHH+KT)+EHH;
            const float* wl=lsW+(size_t)k*(EHH+KT)+EHH;
#pragma unroll
            for(int k2=0;k2<KT;k2++){ float e=er[k2]; m=fmaf(e,wm[k2],m); l=fmaf(e,wl[k2],l); }
            l=fminf(fmaxf(l,-10.f),10.f);
            float d=m-eprev[tid];
            kl += (expf(l)+d*d)/(DELTAF+EPSF) - 1.f + LOG_DELTA_F - l;
        }
        __syncthreads();
        if(act){ eprev[tid]=m; g_etas[((size_t)s*TT+t)*KT+k]=m; }
        __syncthreads();
    }
    red[tid]=kl; __syncthreads();
    for(int off=256;off>0;off>>=1){ if(tid<off) red[tid]+=red[tid+off]; __syncthreads(); }
    if(tid==0) g_kleta[0]=0.5f*red[0];
}

__global__ void gather_eta(const int* __restrict__ sources,const int* __restrict__ times)
{
    int i=blockIdx.x*blockDim.x+threadIdx.x;
    if(i>=BB*KT) return;
    int b=i/KT, k=i%KT;
    g_eta_std[i]=g_etas[((size_t)sources[b]*TT+times[b])*KT+k];
}

// ---------------- h1 epilogue ----------------
__global__ void h1_epilogue(const float* __restrict__ W1,const float* __restrict__ b1)
{
    int i=blockIdx.x*blockDim.x+threadIdx.x;
    if(i>=BB*THH) return;
    int b=i/THH, j=i%THH;
    float v=0.f;
    for(int z=0;z<H1Z;z++) v+=g_part4[(size_t)z*BB*THH+i];
    v+=b1[j];
    const float* w=W1+(size_t)j*(VV+KT)+VV;
    const float* e=g_eta_std+(size_t)b*KT;
#pragma unroll
    for(int k=0;k<KT;k++) v=fmaf(e[k],w[k],v);
    g_h1[i]=fmaxf(v,0.f);
}

// ---------------- theta heads ----------------
__global__ void theta_head(const float* __restrict__ mub,const float* __restrict__ lsb)
{
    int i=blockIdx.x*blockDim.x+threadIdx.x;
    if(i>=BB*KT) return;
    int b=i/KT, k=i%KT;
    const float* h=g_h2+(size_t)b*THH;
    float am=mub[k], al=lsb[k];
    for(int j=0;j<THH;j++){
        float hv=h[j];
        am=fmaf(hv,g_mthT[j*KT+k],am);
        al=fmaf(hv,g_lthT[j*KT+k],al);
    }
    g_mu_t[i]=am;
    g_ls_t[i]=fminf(fmaxf(al,-10.f),10.f);
}

// ---------------- softmax(theta) + kl_theta ----------------
__global__ void softmax_kltheta()
{
    __shared__ float red[64];
    const int b=blockIdx.x, tid=threadIdx.x;
    float m=(tid<KT)? g_mu_t[(size_t)b*KT+tid] : -1e30f;
    red[tid]=m; __syncthreads();
    for(int off=32;off>0;off>>=1){ if(tid<off) red[tid]=fmaxf(red[tid],red[tid+off]); __syncthreads(); }
    float mx=red[0]; __syncthreads();
    float e=(tid<KT)? expf(m-mx) : 0.f;
    red[tid]=e; __syncthreads();
    for(int off=32;off>0;off>>=1){ if(tid<off) red[tid]+=red[tid+off]; __syncthreads(); }
    float Z=red[0]; __syncthreads();
    if(tid<KT) g_theta[(size_t)b*KT+tid]=e/Z;
    float term=0.f;
    if(tid<KT){
        float l=g_ls_t[(size_t)b*KT+tid];
        float d=m-g_eta_std[(size_t)b*KT+tid];
        term=(expf(l)+d*d)/(1.f+EPSF)-1.f-l;
    }
    red[tid]=term; __syncthreads();
    for(int off=32;off>0;off>>=1){ if(tid<off) red[tid]+=red[tid+off]; __syncthreads(); }
    if(tid==0) g_pth[b]=0.5f*red[0];
}

// ---------------- source prediction loss ----------------
__global__ void pred_kernel(const float* __restrict__ clsW,const float* __restrict__ clsb,
                            const int* __restrict__ sources)
{
    int b=blockIdx.x*blockDim.x+threadIdx.x;
    if(b>=BB) return;
    const float* th=g_theta+(size_t)b*KT;
    float lg[SSRC], mx=-1e30f;
#pragma unroll
    for(int i=0;i<SSRC;i++){
        float a=clsb[i];
        const float* w=clsW+(size_t)i*KT;
#pragma unroll
        for(int k=0;k<KT;k++) a=fmaf(th[k],w[k],a);
        lg[i]=a; mx=fmaxf(mx,a);
    }
    float se=0.f;
#pragma unroll
    for(int i=0;i<SSRC;i++) se+=expf(lg[i]-mx);
    float lse=mx+logf(se);
    g_ppred[b]=lse-lg[sources[b]];
}

// ---------------- NLL (docs grouped by time, bf16 E) ----------------
__global__ void wdoc_kernel(const int* __restrict__ times)
{
    int i=blockIdx.x*blockDim.x+threadIdx.x;
    if(i>=BB*KT) return;
    int b=i/KT, k=i%KT;
    g_wdoc[i]=g_theta[i]*g_invZ[times[b]*KT+k];
}

__global__ void doclist_kernel(const int* __restrict__ times)
{
    int t=threadIdx.x;
    if(t>=TT) return;
    int cnt=0;
    for(int b=0;b<BB;b++)
        if(times[b]==t) g_dlist[t*BB + (cnt++)]=b;
    g_dcnt[t]=cnt;
}

__global__ void __launch_bounds__(256) nll2_kernel(const float* __restrict__ bows)
{
    const int t=blockIdx.x, vt=blockIdx.y, tid=threadIdx.x;
    __shared__ float ws[32][KT];
    __shared__ int   dls[32];
    __shared__ float red[256];
    const int cnt=g_dcnt[t];
    float s=0.f;
    for(int d0=0; d0<cnt; d0+=32){
        int ch=min(32,cnt-d0);
        __syncthreads();
        for(int i=tid;i<ch*KT;i+=256){
            int d=i/KT, k=i%KT;
            int b=g_dlist[t*BB+d0+d];
            ws[d][k]=g_wdoc[(size_t)b*KT+k];
            if(k==0) dls[d]=b;
        }
        __syncthreads();
        for(int vi=0;vi<4;vi++){
            int v=vt*1024+vi*256+tid;
            if(v>=VV) break;
            float e[KT];
            const __nv_bfloat16* Ep=g_E+(size_t)t*KT*VV+v;
#pragma unroll
            for(int k=0;k<KT;k++) e[k]=__bfloat162float(Ep[(size_t)k*VV]);
            for(int d=0;d<ch;d++){
                float mix=0.f;
#pragma unroll
                for(int k=0;k<KT;k++) mix=fmaf(ws[d][k],e[k],mix);
                s=fmaf(logf(mix), bows[(size_t)dls[d]*VV+v], s);
            }
        }
    }
    red[tid]=s; __syncthreads();
    for(int off=128;off>0;off>>=1){ if(tid<off) red[tid]+=red[tid+off]; __syncthreads(); }
    if(tid==0) g_pnllT[t*NVTILE+vt]=red[0];
}

// ---------------- final combine ----------------
__global__ void __launch_bounds__(256) final_kernel(const void* __restrict__ ndocs_ptr,
                                                    float* __restrict__ out)
{
    __shared__ float red[256];
    const int tid=threadIdx.x;
    float sa=0.f;
    for(int i=tid;i<KT*TT;i+=256) sa+=g_pa[i];
    red[tid]=sa; __syncthreads();
    for(int off=128;off>0;off>>=1){ if(tid<off) red[tid]+=red[tid+off]; __syncthreads(); }
    float kl_alpha=red[0]; __syncthreads();

    float sl=0.f;
    for(int i=tid;i<TT*NVTILE;i+=256) sl+=g_pnllT[i];
    red[tid]=sl; __syncthreads();
    for(int off=128;off>0;off>>=1){ if(tid<off) red[tid]+=red[tid+off]; __syncthreads(); }
    float sum_ll=red[0]; __syncthreads();

    red[tid]=g_pth[tid]; __syncthreads();
    for(int off=128;off>0;off>>=1){ if(tid<off) red[tid]+=red[tid+off]; __syncthreads(); }
    float sum_th=red[0]; __syncthreads();

    red[tid]=g_ppred[tid]; __syncthreads();
    for(int off=128;off>0;off>>=1){ if(tid<off) red[tid]+=red[tid+off]; __syncthreads(); }
    float sum_pred=red[0]; __syncthreads();

    if(tid==0){
        int v0=*(const int*)ndocs_ptr;
        float nd;
        if(v0>0 && v0<(1<<30)) nd=(float)v0;
        else nd=*(const float*)ndocs_ptr;
        float coeff=nd/(float)BB;
        float nll=-sum_ll*coeff;
        float kl_eta=g_kleta[0];
        float kl_theta=sum_th*coeff;
        float pred=sum_pred*coeff;
        float nelbo=nll+kl_alpha+kl_eta+kl_theta+pred;
        out[0]=nelbo; out[1]=nll; out[2]=kl_alpha;
        out[3]=kl_eta; out[4]=kl_theta; out[5]=pred;
    }
}

// ---------------- launcher ----------------
extern "C" void kernel_launch(void* const* d_in, const int* in_sizes, int n_in,
                              void* d_out, int out_size)
{
    const float* bows      =(const float*)d_in[1];
    const float* nbows     =(const float*)d_in[2];
    const int*   times     =(const int*)  d_in[3];
    const int*   sources   =(const int*)  d_in[4];
    const float* rnn_inp   =(const float*)d_in[5];
    const void*  num_docs  =               d_in[6];
    const float* mu_q_alpha=(const float*)d_in[7];
    const float* ls_q_alpha=(const float*)d_in[8];
    const float* rho_W     =(const float*)d_in[9];
    const float* W1        =(const float*)d_in[10];
    const float* b1        =(const float*)d_in[11];
    const float* W2        =(const float*)d_in[12];
    const float* b2        =(const float*)d_in[13];
    const float* mu_th_W   =(const float*)d_in[14];
    const float* mu_th_b   =(const float*)d_in[15];
    const float* ls_th_W   =(const float*)d_in[16];
    const float* ls_th_b   =(const float*)d_in[17];
    const float* eta_map_W =(const float*)d_in[18];
    const float* eta_map_b =(const float*)d_in[19];
    const float* lstm_Wih  =(const float*)d_in[20];
    const float* lstm_Whh  =(const float*)d_in[21];
    const float* lstm_bih  =(const float*)d_in[22];
    const float* lstm_bhh  =(const float*)d_in[23];
    const float* mu_eta_W  =(const float*)d_in[24];
    const float* mu_eta_b  =(const float*)d_in[25];
    const float* ls_eta_W  =(const float*)d_in[26];
    const float* ls_eta_b  =(const float*)d_in[27];
    const float* cls_W     =(const float*)d_in[28];
    const float* cls_b     =(const float*)d_in[29];
    float* out=(float*)d_out;

    float *rsumP,*part1,*partx,*mapped,*xz,*part4,*part5,*h1,*h2;
    __nv_bfloat16 *Abf,*Bbf,*nbbf,*w1bf,*rnnbf,*emwbf,*E;
    cudaGetSymbolAddress((void**)&Abf,g_Abf);
    cudaGetSymbolAddress((void**)&Bbf,g_Bbf);
    cudaGetSymbolAddress((void**)&nbbf,g_nbbf);
    cudaGetSymbolAddress((void**)&w1bf,g_w1bf);
    cudaGetSymbolAddress((void**)&rnnbf,g_rnnbf);
    cudaGetSymbolAddress((void**)&emwbf,g_emwbf);
    cudaGetSymbolAddress((void**)&E,g_E);
    cudaGetSymbolAddress((void**)&rsumP,g_rsumP);
    cudaGetSymbolAddress((void**)&part1,g_part1);
    cudaGetSymbolAddress((void**)&partx,g_partx);
    cudaGetSymbolAddress((void**)&mapped,g_mapped);
    cudaGetSymbolAddress((void**)&xz,g_xz);
    cudaGetSymbolAddress((void**)&part4,g_part4);
    cudaGetSymbolAddress((void**)&part5,g_part5);
    cudaGetSymbolAddress((void**)&h1,g_h1);
    cudaGetSymbolAddress((void**)&h2,g_h2);

    static int attr_done=0;
    if(!attr_done){
        cudaFuncSetAttribute(beta_hmma_kernel, cudaFuncAttributeMaxDynamicSharedMemorySize, 65536);
        cudaFuncSetAttribute(hmma_nt, cudaFuncAttributeMaxDynamicSharedMemorySize, 65536);
        attr_done=1;
    }

    // ---- launches 0..4: beta operand prep + big conversions ----
    prep_abf<<<(MT*128*KP+255)/256,256>>>(mu_q_alpha);                             // 0
    prep_bbf<<<((int)(VP*KP)+255)/256,256>>>(rho_W);                               // 1
    conv_bf16<<<(256*(KP2/2)+255)/256,256>>>(nbows,256,VV,VV, nbbf, 256*(KP2/2));  // 2
    conv_bf16<<<(896*(KP2/2)+255)/256,256>>>(W1,THH,VV,VV+KT, w1bf, 896*(KP2/2));  // 3
    conv_bf16<<<(512*(KP2/2)+255)/256,256>>>(rnn_inp,500,VV,VV, rnnbf, 512*(KP2/2)); // 4

    // ---- launch 5: beta HMMA (ncu -s 5 captures this) ----
    {
        dim3 g(NT,MT,1);
        beta_hmma_kernel<<<g,256,65536>>>(Abf,Bbf,E,rsumP);                        // 5
    }

    // ---- remaining prep ----
    conv_bf16<<<(256*(KP2/2)+255)/256,256>>>(eta_map_W,EHH,VV,VV, emwbf, 256*(KP2/2));
    prep_whh<<<(EHH*4*EHH+255)/256,256>>>(lstm_Whh);
    transpose_heads<<<(KT*THH+255)/256,256>>>(mu_eta_W, ls_eta_W, mu_th_W, ls_th_W);
    kl_alpha_kernel<<<KT*TT,128>>>(mu_q_alpha, ls_q_alpha);
    rsum_reduce<<<(TT*KT+255)/256,256>>>();

    // ---- eta path ----
    {
        dim3 g(2,4,EMZ);
        hmma_nt<<<g,256,65536>>>(500,EHH,EHH,(KSTG+EMZ-1)/EMZ, rnnbf, emwbf, part1);
        reduce_split<<<(500*EHH+255)/256,256>>>(part1,EMZ,500*EHH,EHH, eta_map_b,nullptr,0, mapped);
    }
    {
        dim3 g((4*EHH+127)/128,(500+127)/128,4);
        sgemm128<0><<<g,256>>>(500,4*EHH,EHH, mapped,EHH, lstm_Wih,EHH,
                               partx,4*EHH, nullptr,nullptr);
        reduce_split<<<(500*4*EHH+255)/256,256>>>(partx,4,500*4*EHH,4*EHH, lstm_bih,lstm_bhh,0, xz);
    }
    lstm_kernel<<<SSRC,4*EHH>>>();
    eta_base_kernel<<<(TT*SSRC*KT+255)/256,256>>>();
    eta_rec_kernel<<<1,512>>>(mu_eta_W, ls_eta_W, mu_eta_b, ls_eta_b);
    gather_eta<<<(BB*KT+255)/256,256>>>(sources, times);

    // ---- theta path ----
    {
        dim3 g(7,2,H1Z);
        hmma_nt<<<g,256,65536>>>(BB,THH,THH,(KSTG+H1Z-1)/H1Z, nbbf, w1bf, part4);
    }
    h1_epilogue<<<(BB*THH+255)/256,256>>>(W1, b1);
    {
        dim3 g((THH+127)/128,(BB+127)/128,8);
        sgemm128<0><<<g,256>>>(BB,THH,THH, h1,THH, W2,THH,
                               part5,THH, nullptr,nullptr);
        reduce_split<<<(BB*THH+255)/256,256>>>(part5,8,BB*THH,THH, b2,nullptr,1, h2);
    }
    theta_head<<<(BB*KT+255)/256,256>>>(mu_th_b, ls_th_b);
    softmax_kltheta<<<BB,64>>>();
    pred_kernel<<<1,BB>>>(cls_W, cls_b, sources);

    // ---- NLL ----
    wdoc_kernel<<<(BB*KT+255)/256,256>>>(times);
    doclist_kernel<<<1,64>>>(times);
    {
        dim3 g(TT,NVTILE,1);
        nll2_kernel<<<g,256>>>(bows);
    }

    // ---- combine ----
    final_kernel<<<1,256>>>(num_docs, out);
    (void)in_sizes; (void)n_in; (void)out_size;
}

// round 10
// speedup vs baseline: 2.8327x; 1.0209x over previous
#include <cuda_runtime.h>
#include <cuda_bf16.h>
#include <math.h>
#include <stdint.h>

#define KT   50
#define TT   50
#define RHOD 300
#define KP   320
#define VV   20000
#define KP2  20032
#define KCH  2504
#define KSTG 313
#define VP   20096
#define NT   157
#define NT2  (2*NT)
#define MT   20
#define THH  800
#define EHH  200
#define SSRC 10
#define BB   256
#define H1Z  21
#define EMZ  35
#define DELTAF 0.005f
#define LOG_DELTA_F (-5.2983173665480363f)
#define EPSF 1e-6f
#define NVTILE 20
#define NG8  (KP2/8)   // 2504 8-elem groups per row

// ---------------- device scratch ----------------
__device__ __align__(16) __nv_bfloat16 g_Abf[(size_t)MT*128*KP];
__device__ __align__(16) __nv_bfloat16 g_Bbf[(size_t)VP*KP];
__device__ __align__(16) __nv_bfloat16 g_nbbf[(size_t)256*KP2];
__device__ __align__(16) __nv_bfloat16 g_w1bf[(size_t)896*KP2];
__device__ __align__(16) __nv_bfloat16 g_rnnbf[(size_t)512*KP2];
__device__ __align__(16) __nv_bfloat16 g_emwbf[(size_t)256*KP2];
__device__ __align__(16) __nv_bfloat16 g_E[(size_t)TT*KT*VV];   // bf16 (100MB)
__device__ float g_rsumP[(size_t)TT*KT*NT2];
__device__ float g_invZ[TT*KT];
__device__ __align__(16) float g_part1[EMZ*500*EHH];
__device__ __align__(16) float g_partx[4*500*4*EHH];
__device__ __align__(16) float g_mapped[500*EHH];
__device__ __align__(16) float g_xz[500*4*EHH];
__device__ float g_WhhT[EHH*4*EHH];
__device__ float g_lstm_out[TT*SSRC*EHH];
__device__ float g_base_mu[TT*SSRC*KT];
__device__ float g_base_ls[TT*SSRC*KT];
__device__ float g_etas[SSRC*TT*KT];
__device__ float g_eta_std[BB*KT];
__device__ __align__(16) float g_part4[H1Z*BB*THH];
__device__ __align__(16) float g_part5[8*BB*THH];
__device__ __align__(16) float g_h1[BB*THH];
__device__ __align__(16) float g_h2[BB*THH];
__device__ float g_mu_t[BB*KT];
__device__ float g_ls_t[BB*KT];
__device__ float g_theta[BB*KT];
__device__ float g_wdoc[BB*KT];
__device__ float g_metaT[EHH*KT];
__device__ float g_letaT[EHH*KT];
__device__ float g_mthT[THH*KT];
__device__ float g_lthT[THH*KT];
__device__ float g_w1etaT[KT*THH];     // transposed eta-part of W1
__device__ int   g_dlist[TT*BB];
__device__ int   g_dcnt[TT];
__device__ float g_pa[KT*TT];
__device__ float g_pnllT[TT*NVTILE];
__device__ float g_pth[BB];
__device__ float g_ppred[BB];
__device__ float g_kleta[1];

__device__ __forceinline__ float sigm_(float x){ return 1.f/(1.f+expf(-x)); }

// ---------------- HMMA / async primitives ----------------
__device__ __forceinline__ void ldsm_x4(uint32_t& r0,uint32_t& r1,uint32_t& r2,uint32_t& r3,uint32_t a){
    asm volatile("ldmatrix.sync.aligned.m8n8.x4.shared.b16 {%0,%1,%2,%3}, [%4];"
                 : "=r"(r0),"=r"(r1),"=r"(r2),"=r"(r3) : "r"(a));
}
__device__ __forceinline__ void mma16816(float* d,const uint32_t* a,const uint32_t* b){
    asm volatile("mma.sync.aligned.m16n8k16.row.col.f32.bf16.bf16.f32 "
        "{%0,%1,%2,%3}, {%4,%5,%6,%7}, {%8,%9}, {%0,%1,%2,%3};"
        : "+f"(d[0]),"+f"(d[1]),"+f"(d[2]),"+f"(d[3])
        : "r"(a[0]),"r"(a[1]),"r"(a[2]),"r"(a[3]), "r"(b[0]),"r"(b[1]));
}
__device__ __forceinline__ void cpasync16(uint32_t dst, const void* src){
    asm volatile("cp.async.cg.shared.global [%0], [%1], 16;" :: "r"(dst), "l"(src));
}
__device__ __forceinline__ void cpcommit(){ asm volatile("cp.async.commit_group;" ::: "memory"); }

// ================= beta HMMA: E = exp(A @ B^T) bf16 out, fused rowsum =====
__global__ void __launch_bounds__(256,2)
beta_hmma_kernel(const __nv_bfloat16* __restrict__ Abf,
                 const __nv_bfloat16* __restrict__ Bbf,
                 __nv_bfloat16* __restrict__ E, float* __restrict__ rsumP)
{
    extern __shared__ __align__(16) uint8_t smem[];
    const int tid=threadIdx.x, l=tid&31, wid=tid>>5;
    const int wm=(wid&3)*32, wn=(wid>>2)*64;
    const int bn=blockIdx.x*128, bm=blockIdx.y*128;
    const uint32_t sbase=(uint32_t)__cvta_generic_to_shared(smem);
    const uint4* Ag=(const uint4*)Abf;
    const uint4* Bg=(const uint4*)Bbf;

    float acc[2][8][4];
#pragma unroll
    for(int i=0;i<2;i++)
#pragma unroll
        for(int j=0;j<8;j++)
#pragma unroll
            for(int q=0;q<4;q++) acc[i][j][q]=0.f;

    const int ar_=(l&15), ac_=(l>>4);
    const int br_=(l&7)+((l>>4)&1)*8, bc_=(l>>3)&1;
    const int lrow=tid>>3, lcol=tid&7;

    auto issue=[&](int s){
        uint32_t sb=sbase+(uint32_t)(s&1)*32768u;
#pragma unroll
        for(int it=0;it<4;it++){
            int row=lrow+32*it;
            uint32_t off=(uint32_t)row*128u + (uint32_t)((lcol^(row&7))*16);
            cpasync16(sb+off,        &Ag[(size_t)(bm+row)*40 + s*8 + lcol]);
            cpasync16(sb+16384u+off, &Bg[(size_t)(bn+row)*40 + s*8 + lcol]);
        }
        cpcommit();
    };

    issue(0);
#pragma unroll
    for(int s=0;s<5;s++){
        if(s<4) issue(s+1);
        if(s<4) asm volatile("cp.async.wait_group 1;" ::: "memory");
        else    asm volatile("cp.async.wait_group 0;" ::: "memory");
        __syncthreads();
        const uint32_t sA=sbase+(uint32_t)(s&1)*32768u;
        const uint32_t sB=sA+16384u;
#pragma unroll
        for(int ks=0;ks<4;ks++){
            uint32_t afr[2][4];
#pragma unroll
            for(int i=0;i<2;i++){
                int row=wm+i*16+ar_;
                int ch=ks*2+ac_;
                ldsm_x4(afr[i][0],afr[i][1],afr[i][2],afr[i][3],
                        sA + row*128 + ((ch^(row&7))*16));
            }
            uint32_t bfr[8][2];
#pragma unroll
            for(int jj=0;jj<4;jj++){
                int row=wn+jj*16+br_;
                int ch=ks*2+bc_;
                uint32_t r0,r1,r2,r3;
                ldsm_x4(r0,r1,r2,r3, sB + row*128 + ((ch^(row&7))*16));
                bfr[jj*2][0]=r0; bfr[jj*2][1]=r1;
                bfr[jj*2+1][0]=r2; bfr[jj*2+1][1]=r3;
            }
#pragma unroll
            for(int i=0;i<2;i++)
#pragma unroll
                for(int j=0;j<8;j++)
                    mma16816(acc[i][j],afr[i],bfr[j]);
        }
        __syncthreads();
    }

#pragma unroll
    for(int i=0;i<2;i++){
        int r0=bm+wm+i*16+(l>>2);
        int r1=r0+8;
        float s0=0.f,s1=0.f;
#pragma unroll
        for(int j=0;j<8;j++){
            int gn=bn+wn+j*8+2*(l&3);
            bool v=gn<VV;
            float e0=__expf(acc[i][j][0]), e1=__expf(acc[i][j][1]);
            float e2=__expf(acc[i][j][2]), e3=__expf(acc[i][j][3]);
            if(v){
                __nv_bfloat162 p01, p23;
                p01.x=__float2bfloat16(e0); p01.y=__float2bfloat16(e1);
                p23.x=__float2bfloat16(e2); p23.y=__float2bfloat16(e3);
                if(r0<TT*KT) *(__nv_bfloat162*)(E+(size_t)r0*VV+gn)=p01;
                if(r1<TT*KT) *(__nv_bfloat162*)(E+(size_t)r1*VV+gn)=p23;
                s0+=e0+e1; s1+=e2+e3;
            }
        }
        s0+=__shfl_xor_sync(0xffffffffu,s0,1); s0+=__shfl_xor_sync(0xffffffffu,s0,2);
        s1+=__shfl_xor_sync(0xffffffffu,s1,1); s1+=__shfl_xor_sync(0xffffffffu,s1,2);
        if((l&3)==0){
            int slot=blockIdx.x*2+(wid>>2);
            if(r0<TT*KT) rsumP[(size_t)r0*NT2+slot]=s0;
            if(r1<TT*KT) rsumP[(size_t)r1*NT2+slot]=s1;
        }
    }
}

// ============ generic HMMA NT GEMM, splitK raw partials, cp.async ============
__global__ void __launch_bounds__(256,2)
hmma_nt(int M,int N,int ldc,int stagesPer,
        const __nv_bfloat16* __restrict__ A,
        const __nv_bfloat16* __restrict__ B,
        float* __restrict__ C)
{
    extern __shared__ __align__(16) uint8_t smem[];
    const int tid=threadIdx.x, l=tid&31, wid=tid>>5;
    const int wm=(wid&3)*32, wn=(wid>>2)*64;
    const int bn=blockIdx.x*128, bm=blockIdx.y*128;
    const int s0=blockIdx.z*stagesPer;
    const int s1=min(KSTG, s0+stagesPer);
    C += (size_t)blockIdx.z*(size_t)M*(size_t)ldc;
    const uint32_t sbase=(uint32_t)__cvta_generic_to_shared(smem);
    const uint4* Ag=(const uint4*)A;
    const uint4* Bg=(const uint4*)B;

    float acc[2][8][4];
#pragma unroll
    for(int i=0;i<2;i++)
#pragma unroll
        for(int j=0;j<8;j++)
#pragma unroll
            for(int q=0;q<4;q++) acc[i][j][q]=0.f;

    const int ar_=(l&15), ac_=(l>>4);
    const int br_=(l&7)+((l>>4)&1)*8, bc_=(l>>3)&1;
    const int lrow=tid>>3, lcol=tid&7;

    auto issue=[&](int s){
        uint32_t sb=sbase+(uint32_t)(s&1)*32768u;
#pragma unroll
        for(int it=0;it<4;it++){
            int row=lrow+32*it;
            uint32_t off=(uint32_t)row*128u + (uint32_t)((lcol^(row&7))*16);
            cpasync16(sb+off,        &Ag[(size_t)(bm+row)*KCH + s*8 + lcol]);
            cpasync16(sb+16384u+off, &Bg[(size_t)(bn+row)*KCH + s*8 + lcol]);
        }
        cpcommit();
    };

    issue(s0);
    for(int s=s0;s<s1;s++){
        if(s+1<s1) issue(s+1);
        if(s+1<s1) asm volatile("cp.async.wait_group 1;" ::: "memory");
        else       asm volatile("cp.async.wait_group 0;" ::: "memory");
        __syncthreads();
        const uint32_t sA=sbase+(uint32_t)(s&1)*32768u;
        const uint32_t sB=sA+16384u;
#pragma unroll
        for(int ks=0;ks<4;ks++){
            uint32_t afr[2][4];
#pragma unroll
            for(int i=0;i<2;i++){
                int row=wm+i*16+ar_;
                int ch=ks*2+ac_;
                ldsm_x4(afr[i][0],afr[i][1],afr[i][2],afr[i][3],
                        sA + row*128 + ((ch^(row&7))*16));
            }
            uint32_t bfr[8][2];
#pragma unroll
            for(int jj=0;jj<4;jj++){
                int row=wn+jj*16+br_;
                int ch=ks*2+bc_;
                uint32_t r0,r1,r2,r3;
                ldsm_x4(r0,r1,r2,r3, sB + row*128 + ((ch^(row&7))*16));
                bfr[jj*2][0]=r0; bfr[jj*2][1]=r1;
                bfr[jj*2+1][0]=r2; bfr[jj*2+1][1]=r3;
            }
#pragma unroll
            for(int i=0;i<2;i++)
#pragma unroll
                for(int j=0;j<8;j++)
                    mma16816(acc[i][j],afr[i],bfr[j]);
        }
        __syncthreads();
    }

#pragma unroll
    for(int i=0;i<2;i++){
        int r0=bm+wm+i*16+(l>>2);
        int r1=r0+8;
#pragma unroll
        for(int j=0;j<8;j++){
            int gn=bn+wn+j*8+2*(l&3);
            if(gn<N){
                if(r0<M) *(float2*)(C+(size_t)r0*ldc+gn)=make_float2(acc[i][j][0],acc[i][j][1]);
                if(r1<M) *(float2*)(C+(size_t)r1*ldc+gn)=make_float2(acc[i][j][2],acc[i][j][3]);
            }
        }
    }
}

__global__ void rsum_reduce()
{
    int r=blockIdx.x*blockDim.x+threadIdx.x;
    if(r>=TT*KT) return;
    float s=0.f;
    for(int i=0;i<NT2;i++) s+=g_rsumP[(size_t)r*NT2+i];
    g_invZ[r]=1.f/s;
}

// ---------------- bf16 operand prep ----------------
__global__ void prep_abf(const float* __restrict__ mu)
{
    int i=blockIdx.x*blockDim.x+threadIdx.x;
    if(i>=MT*128*KP) return;
    int r=i%KP, m=i/KP;
    float v=0.f;
    if(m<TT*KT && r<RHOD){
        int t=m/KT, k=m%KT;
        v=mu[((size_t)k*TT+t)*RHOD + r];
    }
    g_Abf[i]=__float2bfloat16(v);
}

__global__ void prep_bbf(const float* __restrict__ rho)
{
    int i=blockIdx.x*blockDim.x+threadIdx.x;
    if(i>=(int)(VP*KP)) return;
    int r=i%KP, v=i/KP;
    float x=(v<VV && r<RHOD)? rho[(size_t)v*RHOD+r] : 0.f;
    g_Bbf[i]=__float2bfloat16(x);
}

// vectorized fp32 -> padded bf16 [dstRows x KP2]; 8 elems/thread
// requires cols == 20000 (mult of 8) and lds even (8B-aligned float2 reads)
__global__ void conv_bf16v(const float* __restrict__ src,int rows,int lds,
                           __nv_bfloat16* __restrict__ dst,int totalGroups)
{
    int i=blockIdx.x*blockDim.x+threadIdx.x;
    if(i>=totalGroups) return;
    int r=i/NG8, c0=(i%NG8)*8;
    __nv_bfloat16 o[8];
    if(r<rows && c0+7<VV){
        const float* p=src+(size_t)r*lds+c0;
        float2 a=*(const float2*)(p+0);
        float2 b=*(const float2*)(p+2);
        float2 c=*(const float2*)(p+4);
        float2 d=*(const float2*)(p+6);
        o[0]=__float2bfloat16(a.x); o[1]=__float2bfloat16(a.y);
        o[2]=__float2bfloat16(b.x); o[3]=__float2bfloat16(b.y);
        o[4]=__float2bfloat16(c.x); o[5]=__float2bfloat16(c.y);
        o[6]=__float2bfloat16(d.x); o[7]=__float2bfloat16(d.y);
    } else {
#pragma unroll
        for(int q=0;q<8;q++) o[q]=__float2bfloat16(0.f);
    }
    *(uint4*)(dst+(size_t)r*KP2+c0)=*(uint4*)o;
}

// ============ fp32 NT SGEMM (small GEMMs only) ============
template<int OP>
__global__ void __launch_bounds__(256)
sgemm128(int M,int N,int Kd,
         const float* __restrict__ A,int lda,
         const float* __restrict__ B,int ldb,
         float* __restrict__ C,int ldc,
         const float* __restrict__ bias1,const float* __restrict__ bias2)
{
    __shared__ float As[8][128];
    __shared__ float Bs[8][128];
    const int tid=threadIdx.x;
    const int bm=blockIdx.y*128, bn=blockIdx.x*128;
    int k0=0,k1=Kd;
    const int nz=gridDim.z;
    if(nz>1){
        int kChunk=((Kd + nz*8 - 1)/(nz*8))*8;
        k0=blockIdx.z*kChunk; k1=min(Kd,k0+kChunk);
        C += (size_t)blockIdx.z*(size_t)M*(size_t)ldc;
    }
    const int lr=tid>>1, kq=(tid&1)*4;
    const int tx=tid&15, ty=tid>>4;
    float acc[8][8];
#pragma unroll
    for(int i=0;i<8;i++)
#pragma unroll
        for(int j=0;j<8;j++) acc[i][j]=0.f;

    const bool aval=(bm+lr)<M, bval=(bn+lr)<N;
    const float* Ap=A+(size_t)(bm+lr)*lda;
    const float* Bp=B+(size_t)(bn+lr)*ldb;

    for(int kb=k0;kb<k1;kb+=8){
        float4 av=aval? *(const float4*)(Ap+kb+kq) : make_float4(0.f,0.f,0.f,0.f);
        float4 bv=bval? *(const float4*)(Bp+kb+kq) : make_float4(0.f,0.f,0.f,0.f);
        __syncthreads();
        As[kq+0][lr]=av.x; As[kq+1][lr]=av.y; As[kq+2][lr]=av.z; As[kq+3][lr]=av.w;
        Bs[kq+0][lr]=bv.x; Bs[kq+1][lr]=bv.y; Bs[kq+2][lr]=bv.z; Bs[kq+3][lr]=bv.w;
        __syncthreads();
#pragma unroll
        for(int kk=0;kk<8;kk++){
            float ar[8],br[8];
#pragma unroll
            for(int i=0;i<8;i++) ar[i]=As[kk][ty*8+i];
#pragma unroll
            for(int j=0;j<8;j++) br[j]=Bs[kk][tx*8+j];
#pragma unroll
            for(int i=0;i<8;i++)
#pragma unroll
                for(int j=0;j<8;j++) acc[i][j]=fmaf(ar[i],br[j],acc[i][j]);
        }
    }
    const bool raw=(nz>1);
#pragma unroll
    for(int i=0;i<8;i++){
        int gm=bm+ty*8+i; if(gm>=M) continue;
#pragma unroll
        for(int j=0;j<8;j++){
            int gn=bn+tx*8+j; if(gn>=N) continue;
            float v=acc[i][j];
            if(!raw){
                if(bias1) v+=bias1[gn];
                if(bias2) v+=bias2[gn];
                if(OP==1) v=fmaxf(v,0.f);
                else if(OP==2) v=expf(v);
            }
            C[(size_t)gm*ldc+gn]=v;
        }
    }
}

__global__ void reduce_split(const float* __restrict__ parts,int splits,int total,int N,
                             const float* __restrict__ bias1,const float* __restrict__ bias2,
                             int op, float* __restrict__ out)
{
    int i=blockIdx.x*blockDim.x+threadIdx.x;
    if(i>=total) return;
    float v=0.f;
    for(int z=0;z<splits;z++) v+=parts[(size_t)z*total+i];
    if(bias1) v+=bias1[i%N];
    if(bias2) v+=bias2[i%N];
    if(op==1) v=fmaxf(v,0.f);
    out[i]=v;
}

// ---------------- misc prep ----------------
__global__ void prep_whh(const float* __restrict__ whh)
{
    int i=blockIdx.x*blockDim.x+threadIdx.x;
    if(i>=EHH*4*EHH) return;
    int k=i/(4*EHH), j=i%(4*EHH);
    g_WhhT[i]=whh[(size_t)j*EHH + k];
}

__global__ void transpose_heads(const float* __restrict__ muEta,const float* __restrict__ lsEta,
                                const float* __restrict__ muTh,const float* __restrict__ lsTh,
                                const float* __restrict__ W1)
{
    int i=blockIdx.x*blockDim.x+threadIdx.x;
    if(i<KT*EHH){
        int k=i/EHH, j=i%EHH;
        g_metaT[j*KT+k]=muEta[(size_t)k*(EHH+KT)+j];
        g_letaT[j*KT+k]=lsEta[(size_t)k*(EHH+KT)+j];
    }
    if(i<KT*THH){
        int k=i/THH, j=i%THH;
        g_mthT[j*KT+k]=muTh[(size_t)k*THH+j];
        g_lthT[j*KT+k]=lsTh[(size_t)k*THH+j];
        // transposed eta-part of W1: w1etaT[k][j] = W1[j][VV+k]
        g_w1etaT[i]=W1[(size_t)j*(VV+KT)+VV+k];
    }
}

// ---------------- kl_alpha ----------------
__global__ void kl_alpha_kernel(const float* __restrict__ mu,const float* __restrict__ ls)
{
    __shared__ float red[128];
    int b=blockIdx.x; int t=b%TT;
    const float* mup=mu+(size_t)b*RHOD;
    const float* lsp=ls+(size_t)b*RHOD;
    const float* mpv=mu+(size_t)(b-1)*RHOD;
    float s=0.f;
    for(int r=threadIdx.x;r<RHOD;r+=128){
        float m=mup[r], l=lsp[r];
        if(t==0) s += (expf(l)+m*m)/(1.f+EPSF) - 1.f - l;
        else { float d=m-mpv[r]; s += (expf(l)+d*d)/(DELTAF+EPSF) - 1.f + LOG_DELTA_F - l; }
    }
    red[threadIdx.x]=s; __syncthreads();
    for(int off=64;off>0;off>>=1){ if(threadIdx.x<off) red[threadIdx.x]+=red[threadIdx.x+off]; __syncthreads(); }
    if(threadIdx.x==0) g_pa[b]=0.5f*red[0];
}

// ---------------- LSTM ----------------
__global__ void __launch_bounds__(4*EHH) lstm_kernel()
{
    __shared__ float hsm[EHH];
    __shared__ float zsm[4*EHH];
    const int s=blockIdx.x, j=threadIdx.x;
    float c=0.f;
    if(j<EHH) hsm[j]=0.f;
    __syncthreads();
    for(int t=0;t<TT;t++){
        float acc=g_xz[((size_t)s*TT+t)*(4*EHH)+j];
#pragma unroll 4
        for(int k=0;k<EHH;k++) acc=fmaf(hsm[k], g_WhhT[k*(4*EHH)+j], acc);
        zsm[j]=acc;
        __syncthreads();
        if(j<EHH){
            float ig=sigm_(zsm[j]), fg=sigm_(zsm[EHH+j]);
            float gg=tanhf(zsm[2*EHH+j]), og=sigm_(zsm[3*EHH+j]);
            c=fg*c+ig*gg;
            float h=og*tanhf(c);
            hsm[j]=h;
            g_lstm_out[((size_t)t*SSRC+s)*EHH+j]=h;
        }
        __syncthreads();
    }
}

// ---------------- eta base ----------------
__global__ void eta_base_kernel()
{
    int i=blockIdx.x*blockDim.x+threadIdx.x;
    if(i>=TT*SSRC*KT) return;
    int k=i%KT; int ts=i/KT;
    const float* h=g_lstm_out+(size_t)ts*EHH;
    float am=0.f, al=0.f;
    for(int j=0;j<EHH;j++){
        float hv=h[j];
        am=fmaf(hv,g_metaT[j*KT+k],am);
        al=fmaf(hv,g_letaT[j*KT+k],al);
    }
    g_base_mu[i]=am; g_base_ls[i]=al;
}

// ---------------- eta recurrence + kl_eta ----------------
__global__ void __launch_bounds__(512) eta_rec_kernel(const float* __restrict__ muW,const float* __restrict__ lsW,
                                                      const float* __restrict__ mub,const float* __restrict__ lsb)
{
    __shared__ float eprev[SSRC*KT];
    __shared__ float red[512];
    const int tid=threadIdx.x;
    const int s=tid/KT, k=tid%KT;
    const bool act = tid < SSRC*KT;
    float kl=0.f;
    if(act){
        float m=g_base_mu[tid]+mub[k];
        float l=g_base_ls[tid]+lsb[k];
        kl += (expf(l)+m*m)/(1.f+EPSF) - 1.f - l;
        eprev[tid]=m;
        g_etas[((size_t)s*TT+0)*KT+k]=m;
    }
    __syncthreads();
    for(int t=1;t<TT;t++){
        float m=0.f;
        if(act){
            m=g_base_mu[(size_t)t*SSRC*KT+tid]+mub[k];
            float l=g_base_ls[(size_t)t*SSRC*KT+tid]+lsb[k];
            const float* er=eprev+s*KT;
            const float* wm=muW+(size_t)k*(EHH+KT)+EHH;
            const float* wl=lsW+(size_t)k*(EHH+KT)+EHH;
#pragma unroll
            for(int k2=0;k2<KT;k2++){ float e=er[k2]; m=fmaf(e,wm[k2],m); l=fmaf(e,wl[k2],l); }
            l=fminf(fmaxf(l,-10.f),10.f);
            float d=m-eprev[tid];
            kl += (expf(l)+d*d)/(DELTAF+EPSF) - 1.f + LOG_DELTA_F - l;
        }
        __syncthreads();
        if(act){ eprev[tid]=m; g_etas[((size_t)s*TT+t)*KT+k]=m; }
        __syncthreads();
    }
    red[tid]=kl; __syncthreads();
    for(int off=256;off>0;off>>=1){ if(tid<off) red[tid]+=red[tid+off]; __syncthreads(); }
    if(tid==0) g_kleta[0]=0.5f*red[0];
}

__global__ void gather_eta(const int* __restrict__ sources,const int* __restrict__ times)
{
    int i=blockIdx.x*blockDim.x+threadIdx.x;
    if(i>=BB*KT) return;
    int b=i/KT, k=i%KT;
    g_eta_std[i]=g_etas[((size_t)sources[b]*TT+times[b])*KT+k];
}

// ---------------- h1 epilogue (coalesced W1-eta reads) ----------------
__global__ void h1_epilogue(const float* __restrict__ b1)
{
    int i=blockIdx.x*blockDim.x+threadIdx.x;
    if(i>=BB*THH) return;
    int b=i/THH, j=i%THH;
    float v=0.f;
    for(int z=0;z<H1Z;z++) v+=g_part4[(size_t)z*BB*THH+i];
    v+=b1[j];
    const float* e=g_eta_std+(size_t)b*KT;
#pragma unroll
    for(int k=0;k<KT;k++) v=fmaf(e[k], g_w1etaT[k*THH+j], v);
    g_h1[i]=fmaxf(v,0.f);
}

// ---------------- theta heads ----------------
__global__ void theta_head(const float* __restrict__ mub,const float* __restrict__ lsb)
{
    int i=blockIdx.x*blockDim.x+threadIdx.x;
    if(i>=BB*KT) return;
    int b=i/KT, k=i%KT;
    const float* h=g_h2+(size_t)b*THH;
    float am=mub[k], al=lsb[k];
    for(int j=0;j<THH;j++){
        float hv=h[j];
        am=fmaf(hv,g_mthT[j*KT+k],am);
        al=fmaf(hv,g_lthT[j*KT+k],al);
    }
    g_mu_t[i]=am;
    g_ls_t[i]=fminf(fmaxf(al,-10.f),10.f);
}

// ---------------- softmax(theta) + kl_theta ----------------
__global__ void softmax_kltheta()
{
    __shared__ float red[64];
    const int b=blockIdx.x, tid=threadIdx.x;
    float m=(tid<KT)? g_mu_t[(size_t)b*KT+tid] : -1e30f;
    red[tid]=m; __syncthreads();
    for(int off=32;off>0;off>>=1){ if(tid<off) red[tid]=fmaxf(red[tid],red[tid+off]); __syncthreads(); }
    float mx=red[0]; __syncthreads();
    float e=(tid<KT)? expf(m-mx) : 0.f;
    red[tid]=e; __syncthreads();
    for(int off=32;off>0;off>>=1){ if(tid<off) red[tid]+=red[tid+off]; __syncthreads(); }
    float Z=red[0]; __syncthreads();
    if(tid<KT) g_theta[(size_t)b*KT+tid]=e/Z;
    float term=0.f;
    if(tid<KT){
        float l=g_ls_t[(size_t)b*KT+tid];
        float d=m-g_eta_std[(size_t)b*KT+tid];
        term=(expf(l)+d*d)/(1.f+EPSF)-1.f-l;
    }
    red[tid]=term; __syncthreads();
    for(int off=32;off>0;off>>=1){ if(tid<off) red[tid]+=red[tid+off]; __syncthreads(); }
    if(tid==0) g_pth[b]=0.5f*red[0];
}

// ---------------- source prediction loss ----------------
__global__ void pred_kernel(const float* __restrict__ clsW,const float* __restrict__ clsb,
                            const int* __restrict__ sources)
{
    int b=blockIdx.x*blockDim.x+threadIdx.x;
    if(b>=BB) return;
    const float* th=g_theta+(size_t)b*KT;
    float lg[SSRC], mx=-1e30f;
#pragma unroll
    for(int i=0;i<SSRC;i++){
        float a=clsb[i];
        const float* w=clsW+(size_t)i*KT;
#pragma unroll
        for(int k=0;k<KT;k++) a=fmaf(th[k],w[k],a);
        lg[i]=a; mx=fmaxf(mx,a);
    }
    float se=0.f;
#pragma unroll
    for(int i=0;i<SSRC;i++) se+=expf(lg[i]-mx);
    float lse=mx+logf(se);
    g_ppred[b]=lse-lg[sources[b]];
}

// ---------------- NLL (docs grouped by time, bf16 E) ----------------
__global__ void wdoc_kernel(const int* __restrict__ times)
{
    int i=blockIdx.x*blockDim.x+threadIdx.x;
    if(i>=BB*KT) return;
    int b=i/KT, k=i%KT;
    g_wdoc[i]=g_theta[i]*g_invZ[times[b]*KT+k];
}

__global__ void doclist_kernel(const int* __restrict__ times)
{
    int t=threadIdx.x;
    if(t>=TT) return;
    int cnt=0;
    for(int b=0;b<BB;b++)
        if(times[b]==t) g_dlist[t*BB + (cnt++)]=b;
    g_dcnt[t]=cnt;
}

__global__ void __launch_bounds__(256) nll2_kernel(const float* __restrict__ bows)
{
    const int t=blockIdx.x, vt=blockIdx.y, tid=threadIdx.x;
    __shared__ float ws[32][KT];
    __shared__ int   dls[32];
    __shared__ float red[256];
    const int cnt=g_dcnt[t];
    float s=0.f;
    for(int d0=0; d0<cnt; d0+=32){
        int ch=min(32,cnt-d0);
        __syncthreads();
        for(int i=tid;i<ch*KT;i+=256){
            int d=i/KT, k=i%KT;
            int b=g_dlist[t*BB+d0+d];
            ws[d][k]=g_wdoc[(size_t)b*KT+k];
            if(k==0) dls[d]=b;
        }
        __syncthreads();
        for(int vi=0;vi<4;vi++){
            int v=vt*1024+vi*256+tid;
            if(v>=VV) break;
            float e[KT];
            const __nv_bfloat16* Ep=g_E+(size_t)t*KT*VV+v;
#pragma unroll
            for(int k=0;k<KT;k++) e[k]=__bfloat162float(Ep[(size_t)k*VV]);
            for(int d=0;d<ch;d++){
                float mix=0.f;
#pragma unroll
                for(int k=0;k<KT;k++) mix=fmaf(ws[d][k],e[k],mix);
                s=fmaf(__logf(mix), bows[(size_t)dls[d]*VV+v], s);
            }
        }
    }
    red[tid]=s; __syncthreads();
    for(int off=128;off>0;off>>=1){ if(tid<off) red[tid]+=red[tid+off]; __syncthreads(); }
    if(tid==0) g_pnllT[t*NVTILE+vt]=red[0];
}

// ---------------- final combine ----------------
__global__ void __launch_bounds__(256) final_kernel(const void* __restrict__ ndocs_ptr,
                                                    float* __restrict__ out)
{
    __shared__ float red[256];
    const int tid=threadIdx.x;
    float sa=0.f;
    for(int i=tid;i<KT*TT;i+=256) sa+=g_pa[i];
    red[tid]=sa; __syncthreads();
    for(int off=128;off>0;off>>=1){ if(tid<off) red[tid]+=red[tid+off]; __syncthreads(); }
    float kl_alpha=red[0]; __syncthreads();

    float sl=0.f;
    for(int i=tid;i<TT*NVTILE;i+=256) sl+=g_pnllT[i];
    red[tid]=sl; __syncthreads();
    for(int off=128;off>0;off>>=1){ if(tid<off) red[tid]+=red[tid+off]; __syncthreads(); }
    float sum_ll=red[0]; __syncthreads();

    red[tid]=g_pth[tid]; __syncthreads();
    for(int off=128;off>0;off>>=1){ if(tid<off) red[tid]+=red[tid+off]; __syncthreads(); }
    float sum_th=red[0]; __syncthreads();

    red[tid]=g_ppred[tid]; __syncthreads();
    for(int off=128;off>0;off>>=1){ if(tid<off) red[tid]+=red[tid+off]; __syncthreads(); }
    float sum_pred=red[0]; __syncthreads();

    if(tid==0){
        int v0=*(const int*)ndocs_ptr;
        float nd;
        if(v0>0 && v0<(1<<30)) nd=(float)v0;
        else nd=*(const float*)ndocs_ptr;
        float coeff=nd/(float)BB;
        float nll=-sum_ll*coeff;
        float kl_eta=g_kleta[0];
        float kl_theta=sum_th*coeff;
        float pred=sum_pred*coeff;
        float nelbo=nll+kl_alpha+kl_eta+kl_theta+pred;
        out[0]=nelbo; out[1]=nll; out[2]=kl_alpha;
        out[3]=kl_eta; out[4]=kl_theta; out[5]=pred;
    }
}

// ---------------- launcher ----------------
extern "C" void kernel_launch(void* const* d_in, const int* in_sizes, int n_in,
                              void* d_out, int out_size)
{
    const float* bows      =(const float*)d_in[1];
    const float* nbows     =(const float*)d_in[2];
    const int*   times     =(const int*)  d_in[3];
    const int*   sources   =(const int*)  d_in[4];
    const float* rnn_inp   =(const float*)d_in[5];
    const void*  num_docs  =               d_in[6];
    const float* mu_q_alpha=(const float*)d_in[7];
    const float* ls_q_alpha=(const float*)d_in[8];
    const float* rho_W     =(const float*)d_in[9];
    const float* W1        =(const float*)d_in[10];
    const float* b1        =(const float*)d_in[11];
    const float* W2        =(const float*)d_in[12];
    const float* b2        =(const float*)d_in[13];
    const float* mu_th_W   =(const float*)d_in[14];
    const float* mu_th_b   =(const float*)d_in[15];
    const float* ls_th_W   =(const float*)d_in[16];
    const float* ls_th_b   =(const float*)d_in[17];
    const float* eta_map_W =(const float*)d_in[18];
    const float* eta_map_b =(const float*)d_in[19];
    const float* lstm_Wih  =(const float*)d_in[20];
    const float* lstm_Whh  =(const float*)d_in[21];
    const float* lstm_bih  =(const float*)d_in[22];
    const float* lstm_bhh  =(const float*)d_in[23];
    const float* mu_eta_W  =(const float*)d_in[24];
    const float* mu_eta_b  =(const float*)d_in[25];
    const float* ls_eta_W  =(const float*)d_in[26];
    const float* ls_eta_b  =(const float*)d_in[27];
    const float* cls_W     =(const float*)d_in[28];
    const float* cls_b     =(const float*)d_in[29];
    float* out=(float*)d_out;

    float *rsumP,*part1,*partx,*mapped,*xz,*part4,*part5,*h1,*h2;
    __nv_bfloat16 *Abf,*Bbf,*nbbf,*w1bf,*rnnbf,*emwbf,*E;
    cudaGetSymbolAddress((void**)&Abf,g_Abf);
    cudaGetSymbolAddress((void**)&Bbf,g_Bbf);
    cudaGetSymbolAddress((void**)&nbbf,g_nbbf);
    cudaGetSymbolAddress((void**)&w1bf,g_w1bf);
    cudaGetSymbolAddress((void**)&rnnbf,g_rnnbf);
    cudaGetSymbolAddress((void**)&emwbf,g_emwbf);
    cudaGetSymbolAddress((void**)&E,g_E);
    cudaGetSymbolAddress((void**)&rsumP,g_rsumP);
    cudaGetSymbolAddress((void**)&part1,g_part1);
    cudaGetSymbolAddress((void**)&partx,g_partx);
    cudaGetSymbolAddress((void**)&mapped,g_mapped);
    cudaGetSymbolAddress((void**)&xz,g_xz);
    cudaGetSymbolAddress((void**)&part4,g_part4);
    cudaGetSymbolAddress((void**)&part5,g_part5);
    cudaGetSymbolAddress((void**)&h1,g_h1);
    cudaGetSymbolAddress((void**)&h2,g_h2);

    static int attr_done=0;
    if(!attr_done){
        cudaFuncSetAttribute(beta_hmma_kernel, cudaFuncAttributeMaxDynamicSharedMemorySize, 65536);
        cudaFuncSetAttribute(hmma_nt, cudaFuncAttributeMaxDynamicSharedMemorySize, 65536);
        attr_done=1;
    }

    // ---- prep / conversions ----
    prep_abf<<<(MT*128*KP+255)/256,256>>>(mu_q_alpha);
    prep_bbf<<<((int)(VP*KP)+255)/256,256>>>(rho_W);
    conv_bf16v<<<(256*NG8+255)/256,256>>>(nbows,256,VV, nbbf, 256*NG8);
    conv_bf16v<<<(896*NG8+255)/256,256>>>(W1,THH,VV+KT, w1bf, 896*NG8);
    conv_bf16v<<<(512*NG8+255)/256,256>>>(rnn_inp,500,VV, rnnbf, 512*NG8);

    // ---- beta HMMA ----
    {
        dim3 g(NT,MT,1);
        beta_hmma_kernel<<<g,256,65536>>>(Abf,Bbf,E,rsumP);
    }

    // ---- remaining prep ----
    conv_bf16v<<<(256*NG8+255)/256,256>>>(eta_map_W,EHH,VV, emwbf, 256*NG8);
    prep_whh<<<(EHH*4*EHH+255)/256,256>>>(lstm_Whh);
    transpose_heads<<<(KT*THH+255)/256,256>>>(mu_eta_W, ls_eta_W, mu_th_W, ls_th_W, W1);
    kl_alpha_kernel<<<KT*TT,128>>>(mu_q_alpha, ls_q_alpha);
    rsum_reduce<<<(TT*KT+255)/256,256>>>();

    // ---- eta path ----
    {
        dim3 g(2,4,EMZ);
        hmma_nt<<<g,256,65536>>>(500,EHH,EHH,(KSTG+EMZ-1)/EMZ, rnnbf, emwbf, part1);
        reduce_split<<<(500*EHH+255)/256,256>>>(part1,EMZ,500*EHH,EHH, eta_map_b,nullptr,0, mapped);
    }
    {
        dim3 g((4*EHH+127)/128,(500+127)/128,4);
        sgemm128<0><<<g,256>>>(500,4*EHH,EHH, mapped,EHH, lstm_Wih,EHH,
                               partx,4*EHH, nullptr,nullptr);
        reduce_split<<<(500*4*EHH+255)/256,256>>>(partx,4,500*4*EHH,4*EHH, lstm_bih,lstm_bhh,0, xz);
    }
    lstm_kernel<<<SSRC,4*EHH>>>();
    eta_base_kernel<<<(TT*SSRC*KT+255)/256,256>>>();
    eta_rec_kernel<<<1,512>>>(mu_eta_W, ls_eta_W, mu_eta_b, ls_eta_b);
    gather_eta<<<(BB*KT+255)/256,256>>>(sources, times);

    // ---- theta path ----
    {
        dim3 g(7,2,H1Z);
        hmma_nt<<<g,256,65536>>>(BB,THH,THH,(KSTG+H1Z-1)/H1Z, nbbf, w1bf, part4);
    }
    h1_epilogue<<<(BB*THH+255)/256,256>>>(b1);
    {
        dim3 g((THH+127)/128,(BB+127)/128,8);
        sgemm128<0><<<g,256>>>(BB,THH,THH, h1,THH, W2,THH,
                               part5,THH, nullptr,nullptr);
        reduce_split<<<(BB*THH+255)/256,256>>>(part5,8,BB*THH,THH, b2,nullptr,1, h2);
    }
    theta_head<<<(BB*KT+255)/256,256>>>(mu_th_b, ls_th_b);
    softmax_kltheta<<<BB,64>>>();
    pred_kernel<<<1,BB>>>(cls_W, cls_b, sources);

    // ---- NLL ----
    wdoc_kernel<<<(BB*KT+255)/256,256>>>(times);
    doclist_kernel<<<1,64>>>(times);
    {
        dim3 g(TT,NVTILE,1);
        nll2_kernel<<<g,256>>>(bows);
    }

    // ---- combine ----
    final_kernel<<<1,256>>>(num_docs, out);
    (void)in_sizes; (void)n_in; (void)out_size;
}

// round 11
// speedup vs baseline: 4.9475x; 1.7466x over previous
#include <cuda_runtime.h>
#include <cuda_bf16.h>
#include <math.h>
#include <stdint.h>

#define KT   50
#define TT   50
#define RHOD 300
#define KP   320
#define VV   20000
#define KP2  20032
#define KCH  2504
#define KSTG 313
#define VP   20096
#define NT   157
#define NT2  (2*NT)
#define MT   20
#define THH  800
#define EHH  200
#define SSRC 10
#define BB   256
#define H1Z  21
#define EMZ  35
#define DELTAF 0.005f
#define LOG_DELTA_F (-5.2983173665480363f)
#define EPSF 1e-6f
#define NVTILE 20
#define NG8  (KP2/8)

// mega_prep block-range sizes
#define NB_ABF 3200     // MT*128*KP/256
#define NB_BBF 25120    // VP*KP/256
#define NB_CN  2504     // 256 rows * NG8 /256
#define NB_CW  8764     // 896 rows
#define NB_CR  5008     // 512 rows
#define NB_CE  2504     // 256 rows
#define NB_WH  313      // 100*800/256 (float2 Whh pack)
#define NB_HD  157      // KT*THH/256
#define NB_KA  2500     // kl_alpha rows

// ---------------- device scratch ----------------
__device__ __align__(16) __nv_bfloat16 g_Abf[(size_t)MT*128*KP];
__device__ __align__(16) __nv_bfloat16 g_Bbf[(size_t)VP*KP];
__device__ __align__(16) __nv_bfloat16 g_nbbf[(size_t)256*KP2];
__device__ __align__(16) __nv_bfloat16 g_w1bf[(size_t)896*KP2];
__device__ __align__(16) __nv_bfloat16 g_rnnbf[(size_t)512*KP2];
__device__ __align__(16) __nv_bfloat16 g_emwbf[(size_t)256*KP2];
__device__ __align__(16) __nv_bfloat16 g_E[(size_t)TT*KT*VV];
__device__ float g_rsumP[(size_t)TT*KT*NT2];
__device__ float g_invZ[TT*KT];
__device__ __align__(16) float g_part1[EMZ*500*EHH];
__device__ __align__(16) float g_partx[4*500*4*EHH];
__device__ __align__(16) float g_mapped[500*EHH];
__device__ __align__(16) float g_xz[500*4*EHH];
__device__ __align__(16) float2 g_WhhT2[(EHH/2)*(4*EHH)];
__device__ float g_lstm_out[TT*SSRC*EHH];
__device__ float g_base_mu[TT*SSRC*KT];
__device__ float g_base_ls[TT*SSRC*KT];
__device__ float g_etas[SSRC*TT*KT];
__device__ __align__(16) float g_part4[H1Z*BB*THH];
__device__ __align__(16) float g_part5[8*BB*THH];
__device__ __align__(16) float g_h1[BB*THH];
__device__ __align__(16) float g_h2[BB*THH];
__device__ float g_theta[BB*KT];
__device__ float g_wdoc[BB*KT];
__device__ float g_metaT[EHH*KT];
__device__ float g_letaT[EHH*KT];
__device__ float g_mthT[THH*KT];
__device__ float g_lthT[THH*KT];
__device__ float g_w1etaT[KT*THH];
__device__ float g_muRT[KT*KT];
__device__ float g_lsRT[KT*KT];
__device__ int   g_dlist[TT*BB];
__device__ int   g_dcnt[TT];
__device__ float g_pa[KT*TT];
__device__ float g_pnllT[TT*NVTILE];
__device__ float g_pth[BB];
__device__ float g_ppred[BB];
__device__ float g_kleta[1];

__device__ __forceinline__ float sigm_(float x){ return 1.f/(1.f+expf(-x)); }

// ---------------- HMMA / async primitives ----------------
__device__ __forceinline__ void ldsm_x4(uint32_t& r0,uint32_t& r1,uint32_t& r2,uint32_t& r3,uint32_t a){
    asm volatile("ldmatrix.sync.aligned.m8n8.x4.shared.b16 {%0,%1,%2,%3}, [%4];"
                 : "=r"(r0),"=r"(r1),"=r"(r2),"=r"(r3) : "r"(a));
}
__device__ __forceinline__ void mma16816(float* d,const uint32_t* a,const uint32_t* b){
    asm volatile("mma.sync.aligned.m16n8k16.row.col.f32.bf16.bf16.f32 "
        "{%0,%1,%2,%3}, {%4,%5,%6,%7}, {%8,%9}, {%0,%1,%2,%3};"
        : "+f"(d[0]),"+f"(d[1]),"+f"(d[2]),"+f"(d[3])
        : "r"(a[0]),"r"(a[1]),"r"(a[2]),"r"(a[3]), "r"(b[0]),"r"(b[1]));
}
__device__ __forceinline__ void cpasync16(uint32_t dst, const void* src){
    asm volatile("cp.async.cg.shared.global [%0], [%1], 16;" :: "r"(dst), "l"(src));
}
__device__ __forceinline__ void cpcommit(){ asm volatile("cp.async.commit_group;" ::: "memory"); }

// ================= beta HMMA: E = exp(A @ B^T) bf16 out, fused rowsum =====
__global__ void __launch_bounds__(256,2)
beta_hmma_kernel(const __nv_bfloat16* __restrict__ Abf,
                 const __nv_bfloat16* __restrict__ Bbf,
                 __nv_bfloat16* __restrict__ E, float* __restrict__ rsumP)
{
    extern __shared__ __align__(16) uint8_t smem[];
    const int tid=threadIdx.x, l=tid&31, wid=tid>>5;
    const int wm=(wid&3)*32, wn=(wid>>2)*64;
    const int bn=blockIdx.x*128, bm=blockIdx.y*128;
    const uint32_t sbase=(uint32_t)__cvta_generic_to_shared(smem);
    const uint4* Ag=(const uint4*)Abf;
    const uint4* Bg=(const uint4*)Bbf;

    float acc[2][8][4];
#pragma unroll
    for(int i=0;i<2;i++)
#pragma unroll
        for(int j=0;j<8;j++)
#pragma unroll
            for(int q=0;q<4;q++) acc[i][j][q]=0.f;

    const int ar_=(l&15), ac_=(l>>4);
    const int br_=(l&7)+((l>>4)&1)*8, bc_=(l>>3)&1;
    const int lrow=tid>>3, lcol=tid&7;

    auto issue=[&](int s){
        uint32_t sb=sbase+(uint32_t)(s&1)*32768u;
#pragma unroll
        for(int it=0;it<4;it++){
            int row=lrow+32*it;
            uint32_t off=(uint32_t)row*128u + (uint32_t)((lcol^(row&7))*16);
            cpasync16(sb+off,        &Ag[(size_t)(bm+row)*40 + s*8 + lcol]);
            cpasync16(sb+16384u+off, &Bg[(size_t)(bn+row)*40 + s*8 + lcol]);
        }
        cpcommit();
    };

    issue(0);
#pragma unroll
    for(int s=0;s<5;s++){
        if(s<4) issue(s+1);
        if(s<4) asm volatile("cp.async.wait_group 1;" ::: "memory");
        else    asm volatile("cp.async.wait_group 0;" ::: "memory");
        __syncthreads();
        const uint32_t sA=sbase+(uint32_t)(s&1)*32768u;
        const uint32_t sB=sA+16384u;
#pragma unroll
        for(int ks=0;ks<4;ks++){
            uint32_t afr[2][4];
#pragma unroll
            for(int i=0;i<2;i++){
                int row=wm+i*16+ar_;
                int ch=ks*2+ac_;
                ldsm_x4(afr[i][0],afr[i][1],afr[i][2],afr[i][3],
                        sA + row*128 + ((ch^(row&7))*16));
            }
            uint32_t bfr[8][2];
#pragma unroll
            for(int jj=0;jj<4;jj++){
                int row=wn+jj*16+br_;
                int ch=ks*2+bc_;
                uint32_t r0,r1,r2,r3;
                ldsm_x4(r0,r1,r2,r3, sB + row*128 + ((ch^(row&7))*16));
                bfr[jj*2][0]=r0; bfr[jj*2][1]=r1;
                bfr[jj*2+1][0]=r2; bfr[jj*2+1][1]=r3;
            }
#pragma unroll
            for(int i=0;i<2;i++)
#pragma unroll
                for(int j=0;j<8;j++)
                    mma16816(acc[i][j],afr[i],bfr[j]);
        }
        __syncthreads();
    }

#pragma unroll
    for(int i=0;i<2;i++){
        int r0=bm+wm+i*16+(l>>2);
        int r1=r0+8;
        float s0=0.f,s1=0.f;
#pragma unroll
        for(int j=0;j<8;j++){
            int gn=bn+wn+j*8+2*(l&3);
            bool v=gn<VV;
            float e0=__expf(acc[i][j][0]), e1=__expf(acc[i][j][1]);
            float e2=__expf(acc[i][j][2]), e3=__expf(acc[i][j][3]);
            if(v){
                __nv_bfloat162 p01, p23;
                p01.x=__float2bfloat16(e0); p01.y=__float2bfloat16(e1);
                p23.x=__float2bfloat16(e2); p23.y=__float2bfloat16(e3);
                if(r0<TT*KT) *(__nv_bfloat162*)(E+(size_t)r0*VV+gn)=p01;
                if(r1<TT*KT) *(__nv_bfloat162*)(E+(size_t)r1*VV+gn)=p23;
                s0+=e0+e1; s1+=e2+e3;
            }
        }
        s0+=__shfl_xor_sync(0xffffffffu,s0,1); s0+=__shfl_xor_sync(0xffffffffu,s0,2);
        s1+=__shfl_xor_sync(0xffffffffu,s1,1); s1+=__shfl_xor_sync(0xffffffffu,s1,2);
        if((l&3)==0){
            int slot=blockIdx.x*2+(wid>>2);
            if(r0<TT*KT) rsumP[(size_t)r0*NT2+slot]=s0;
            if(r1<TT*KT) rsumP[(size_t)r1*NT2+slot]=s1;
        }
    }
}

// ============ generic HMMA NT GEMM, splitK raw partials, cp.async ============
__global__ void __launch_bounds__(256,2)
hmma_nt(int M,int N,int ldc,int stagesPer,
        const __nv_bfloat16* __restrict__ A,
        const __nv_bfloat16* __restrict__ B,
        float* __restrict__ C)
{
    extern __shared__ __align__(16) uint8_t smem[];
    const int tid=threadIdx.x, l=tid&31, wid=tid>>5;
    const int wm=(wid&3)*32, wn=(wid>>2)*64;
    const int bn=blockIdx.x*128, bm=blockIdx.y*128;
    const int s0=blockIdx.z*stagesPer;
    const int s1=min(KSTG, s0+stagesPer);
    C += (size_t)blockIdx.z*(size_t)M*(size_t)ldc;
    const uint32_t sbase=(uint32_t)__cvta_generic_to_shared(smem);
    const uint4* Ag=(const uint4*)A;
    const uint4* Bg=(const uint4*)B;

    float acc[2][8][4];
#pragma unroll
    for(int i=0;i<2;i++)
#pragma unroll
        for(int j=0;j<8;j++)
#pragma unroll
            for(int q=0;q<4;q++) acc[i][j][q]=0.f;

    const int ar_=(l&15), ac_=(l>>4);
    const int br_=(l&7)+((l>>4)&1)*8, bc_=(l>>3)&1;
    const int lrow=tid>>3, lcol=tid&7;

    auto issue=[&](int s){
        uint32_t sb=sbase+(uint32_t)(s&1)*32768u;
#pragma unroll
        for(int it=0;it<4;it++){
            int row=lrow+32*it;
            uint32_t off=(uint32_t)row*128u + (uint32_t)((lcol^(row&7))*16);
            cpasync16(sb+off,        &Ag[(size_t)(bm+row)*KCH + s*8 + lcol]);
            cpasync16(sb+16384u+off, &Bg[(size_t)(bn+row)*KCH + s*8 + lcol]);
        }
        cpcommit();
    };

    issue(s0);
    for(int s=s0;s<s1;s++){
        if(s+1<s1) issue(s+1);
        if(s+1<s1) asm volatile("cp.async.wait_group 1;" ::: "memory");
        else       asm volatile("cp.async.wait_group 0;" ::: "memory");
        __syncthreads();
        const uint32_t sA=sbase+(uint32_t)(s&1)*32768u;
        const uint32_t sB=sA+16384u;
#pragma unroll
        for(int ks=0;ks<4;ks++){
            uint32_t afr[2][4];
#pragma unroll
            for(int i=0;i<2;i++){
                int row=wm+i*16+ar_;
                int ch=ks*2+ac_;
                ldsm_x4(afr[i][0],afr[i][1],afr[i][2],afr[i][3],
                        sA + row*128 + ((ch^(row&7))*16));
            }
            uint32_t bfr[8][2];
#pragma unroll
            for(int jj=0;jj<4;jj++){
                int row=wn+jj*16+br_;
                int ch=ks*2+bc_;
                uint32_t r0,r1,r2,r3;
                ldsm_x4(r0,r1,r2,r3, sB + row*128 + ((ch^(row&7))*16));
                bfr[jj*2][0]=r0; bfr[jj*2][1]=r1;
                bfr[jj*2+1][0]=r2; bfr[jj*2+1][1]=r3;
            }
#pragma unroll
            for(int i=0;i<2;i++)
#pragma unroll
                for(int j=0;j<8;j++)
                    mma16816(acc[i][j],afr[i],bfr[j]);
        }
        __syncthreads();
    }

#pragma unroll
    for(int i=0;i<2;i++){
        int r0=bm+wm+i*16+(l>>2);
        int r1=r0+8;
#pragma unroll
        for(int j=0;j<8;j++){
            int gn=bn+wn+j*8+2*(l&3);
            if(gn<N){
                if(r0<M) *(float2*)(C+(size_t)r0*ldc+gn)=make_float2(acc[i][j][0],acc[i][j][1]);
                if(r1<M) *(float2*)(C+(size_t)r1*ldc+gn)=make_float2(acc[i][j][2],acc[i][j][3]);
            }
        }
    }
}

__global__ void rsum_reduce()
{
    int r=blockIdx.x*blockDim.x+threadIdx.x;
    if(r>=TT*KT) return;
    float s=0.f;
    for(int i=0;i<NT2;i++) s+=g_rsumP[(size_t)r*NT2+i];
    g_invZ[r]=1.f/s;
}

// ---------------- mega prep: everything elementwise in ONE launch ----------------
__device__ __forceinline__ void conv_seg(const float* __restrict__ src,int rows,int lds,
                                         __nv_bfloat16* __restrict__ dst,int gi)
{
    int r=gi/NG8, c0=(gi%NG8)*8;
    __nv_bfloat16 o[8];
    if(r<rows && c0+7<VV){
        const float* p=src+(size_t)r*lds+c0;
        float2 a=*(const float2*)(p+0);
        float2 b=*(const float2*)(p+2);
        float2 c=*(const float2*)(p+4);
        float2 d=*(const float2*)(p+6);
        o[0]=__float2bfloat16(a.x); o[1]=__float2bfloat16(a.y);
        o[2]=__float2bfloat16(b.x); o[3]=__float2bfloat16(b.y);
        o[4]=__float2bfloat16(c.x); o[5]=__float2bfloat16(c.y);
        o[6]=__float2bfloat16(d.x); o[7]=__float2bfloat16(d.y);
    } else {
#pragma unroll
        for(int q=0;q<8;q++) o[q]=__float2bfloat16(0.f);
    }
    *(uint4*)(dst+(size_t)r*KP2+c0)=*(uint4*)o;
}

__global__ void __launch_bounds__(256) mega_prep(
    const float* __restrict__ mu_q_alpha, const float* __restrict__ rho,
    const float* __restrict__ nbows, const float* __restrict__ W1,
    const float* __restrict__ rnn, const float* __restrict__ emw,
    const float* __restrict__ whh,
    const float* __restrict__ muEta, const float* __restrict__ lsEta,
    const float* __restrict__ muTh, const float* __restrict__ lsTh,
    const float* __restrict__ lsA)
{
    int bid=blockIdx.x;
    const int tid=threadIdx.x;
    if(bid<NB_ABF){
        int i=bid*256+tid;
        int r=i%KP, m=i/KP;
        float v=0.f;
        if(m<TT*KT && r<RHOD){
            int t=m/KT, k=m%KT;
            v=mu_q_alpha[((size_t)k*TT+t)*RHOD + r];
        }
        g_Abf[i]=__float2bfloat16(v);
        return;
    }
    bid-=NB_ABF;
    if(bid<NB_BBF){
        int i=bid*256+tid;
        int r=i%KP, v=i/KP;
        float x=(v<VV && r<RHOD)? rho[(size_t)v*RHOD+r] : 0.f;
        g_Bbf[i]=__float2bfloat16(x);
        return;
    }
    bid-=NB_BBF;
    if(bid<NB_CN){ conv_seg(nbows,256,VV, g_nbbf, bid*256+tid); return; }
    bid-=NB_CN;
    if(bid<NB_CW){ conv_seg(W1,THH,VV+KT, g_w1bf, bid*256+tid); return; }
    bid-=NB_CW;
    if(bid<NB_CR){ conv_seg(rnn,500,VV, g_rnnbf, bid*256+tid); return; }
    bid-=NB_CR;
    if(bid<NB_CE){ conv_seg(emw,EHH,VV, g_emwbf, bid*256+tid); return; }
    bid-=NB_CE;
    if(bid<NB_WH){
        int i=bid*256+tid;
        if(i<(EHH/2)*(4*EHH)){
            int k2=i/(4*EHH), j=i%(4*EHH);
            float2 w;
            w.x=whh[(size_t)j*EHH+2*k2];
            w.y=whh[(size_t)j*EHH+2*k2+1];
            g_WhhT2[i]=w;
        }
        return;
    }
    bid-=NB_WH;
    if(bid<NB_HD){
        int i=bid*256+tid;
        if(i<KT*EHH){
            int k=i/EHH, j=i%EHH;
            g_metaT[j*KT+k]=muEta[(size_t)k*(EHH+KT)+j];
            g_letaT[j*KT+k]=lsEta[(size_t)k*(EHH+KT)+j];
        }
        if(i<KT*THH){
            int k=i/THH, j=i%THH;
            g_mthT[j*KT+k]=muTh[(size_t)k*THH+j];
            g_lthT[j*KT+k]=lsTh[(size_t)k*THH+j];
            g_w1etaT[i]=W1[(size_t)j*(VV+KT)+VV+k];
        }
        if(i<KT*KT){
            int k2=i/KT, k=i%KT;
            g_muRT[i]=muEta[(size_t)k*(EHH+KT)+EHH+k2];
            g_lsRT[i]=lsEta[(size_t)k*(EHH+KT)+EHH+k2];
        }
        return;
    }
    bid-=NB_HD;
    // kl_alpha: one block per (k,t) row
    {
        __shared__ float red[256];
        int b=bid; int t=b%TT;
        const float* mup=mu_q_alpha+(size_t)b*RHOD;
        const float* lsp=lsA+(size_t)b*RHOD;
        const float* mpv=mu_q_alpha+(size_t)(b-1)*RHOD;
        float s=0.f;
        for(int r=tid;r<RHOD;r+=256){
            float m=mup[r], l=lsp[r];
            if(t==0) s += (expf(l)+m*m)/(1.f+EPSF) - 1.f - l;
            else { float d=m-mpv[r]; s += (expf(l)+d*d)/(DELTAF+EPSF) - 1.f + LOG_DELTA_F - l; }
        }
        red[tid]=s; __syncthreads();
        for(int off=128;off>0;off>>=1){ if(tid<off) red[tid]+=red[tid+off]; __syncthreads(); }
        if(tid==0) g_pa[b]=0.5f*red[0];
    }
}

// ============ fp32 NT SGEMM (small GEMMs only) ============
template<int OP>
__global__ void __launch_bounds__(256)
sgemm128(int M,int N,int Kd,
         const float* __restrict__ A,int lda,
         const float* __restrict__ B,int ldb,
         float* __restrict__ C,int ldc,
         const float* __restrict__ bias1,const float* __restrict__ bias2)
{
    __shared__ float As[8][128];
    __shared__ float Bs[8][128];
    const int tid=threadIdx.x;
    const int bm=blockIdx.y*128, bn=blockIdx.x*128;
    int k0=0,k1=Kd;
    const int nz=gridDim.z;
    if(nz>1){
        int kChunk=((Kd + nz*8 - 1)/(nz*8))*8;
        k0=blockIdx.z*kChunk; k1=min(Kd,k0+kChunk);
        C += (size_t)blockIdx.z*(size_t)M*(size_t)ldc;
    }
    const int lr=tid>>1, kq=(tid&1)*4;
    const int tx=tid&15, ty=tid>>4;
    float acc[8][8];
#pragma unroll
    for(int i=0;i<8;i++)
#pragma unroll
        for(int j=0;j<8;j++) acc[i][j]=0.f;

    const bool aval=(bm+lr)<M, bval=(bn+lr)<N;
    const float* Ap=A+(size_t)(bm+lr)*lda;
    const float* Bp=B+(size_t)(bn+lr)*ldb;

    for(int kb=k0;kb<k1;kb+=8){
        float4 av=aval? *(const float4*)(Ap+kb+kq) : make_float4(0.f,0.f,0.f,0.f);
        float4 bv=bval? *(const float4*)(Bp+kb+kq) : make_float4(0.f,0.f,0.f,0.f);
        __syncthreads();
        As[kq+0][lr]=av.x; As[kq+1][lr]=av.y; As[kq+2][lr]=av.z; As[kq+3][lr]=av.w;
        Bs[kq+0][lr]=bv.x; Bs[kq+1][lr]=bv.y; Bs[kq+2][lr]=bv.z; Bs[kq+3][lr]=bv.w;
        __syncthreads();
#pragma unroll
        for(int kk=0;kk<8;kk++){
            float ar[8],br[8];
#pragma unroll
            for(int i=0;i<8;i++) ar[i]=As[kk][ty*8+i];
#pragma unroll
            for(int j=0;j<8;j++) br[j]=Bs[kk][tx*8+j];
#pragma unroll
            for(int i=0;i<8;i++)
#pragma unroll
                for(int j=0;j<8;j++) acc[i][j]=fmaf(ar[i],br[j],acc[i][j]);
        }
    }
    const bool raw=(nz>1);
#pragma unroll
    for(int i=0;i<8;i++){
        int gm=bm+ty*8+i; if(gm>=M) continue;
#pragma unroll
        for(int j=0;j<8;j++){
            int gn=bn+tx*8+j; if(gn>=N) continue;
            float v=acc[i][j];
            if(!raw){
                if(bias1) v+=bias1[gn];
                if(bias2) v+=bias2[gn];
                if(OP==1) v=fmaxf(v,0.f);
                else if(OP==2) v=expf(v);
            }
            C[(size_t)gm*ldc+gn]=v;
        }
    }
}

__global__ void reduce_split(const float* __restrict__ parts,int splits,int total,int N,
                             const float* __restrict__ bias1,const float* __restrict__ bias2,
                             int op, float* __restrict__ out)
{
    int i=blockIdx.x*blockDim.x+threadIdx.x;
    if(i>=total) return;
    float v=0.f;
    for(int z=0;z<splits;z++) v+=parts[(size_t)z*total+i];
    if(bias1) v+=bias1[i%N];
    if(bias2) v+=bias2[i%N];
    if(op==1) v=fmaxf(v,0.f);
    out[i]=v;
}

// ---------------- LSTM: float2-packed recurrent weights ----------------
__global__ void __launch_bounds__(4*EHH) lstm_kernel()
{
    __shared__ __align__(8) float hsm[EHH];
    __shared__ float zsm[4*EHH];
    const int s=blockIdx.x, j=threadIdx.x;
    float c=0.f;
    if(j<EHH) hsm[j]=0.f;
    __syncthreads();
    for(int t=0;t<TT;t++){
        float acc=g_xz[((size_t)s*TT+t)*(4*EHH)+j];
#pragma unroll 4
        for(int k2=0;k2<EHH/2;k2++){
            float2 w=g_WhhT2[k2*(4*EHH)+j];
            float2 hv=*(const float2*)(hsm+2*k2);
            acc=fmaf(hv.x,w.x,acc);
            acc=fmaf(hv.y,w.y,acc);
        }
        zsm[j]=acc;
        __syncthreads();
        if(j<EHH){
            float ig=sigm_(zsm[j]), fg=sigm_(zsm[EHH+j]);
            float gg=tanhf(zsm[2*EHH+j]), og=sigm_(zsm[3*EHH+j]);
            c=fg*c+ig*gg;
            float h=og*tanhf(c);
            hsm[j]=h;
            g_lstm_out[((size_t)t*SSRC+s)*EHH+j]=h;
        }
        __syncthreads();
    }
}

// ---------------- eta base ----------------
__global__ void eta_base_kernel()
{
    int i=blockIdx.x*blockDim.x+threadIdx.x;
    if(i>=TT*SSRC*KT) return;
    int k=i%KT; int ts=i/KT;
    const float* h=g_lstm_out+(size_t)ts*EHH;
    float am=0.f, al=0.f;
    for(int j=0;j<EHH;j++){
        float hv=h[j];
        am=fmaf(hv,g_metaT[j*KT+k],am);
        al=fmaf(hv,g_letaT[j*KT+k],al);
    }
    g_base_mu[i]=am; g_base_ls[i]=al;
}

// ---------------- eta recurrence + kl_eta (transposed rec weights) ----------------
__global__ void __launch_bounds__(512) eta_rec_kernel(const float* __restrict__ mub,
                                                      const float* __restrict__ lsb)
{
    __shared__ float eprev[SSRC*KT];
    __shared__ float red[512];
    const int tid=threadIdx.x;
    const int s=tid/KT, k=tid%KT;
    const bool act = tid < SSRC*KT;
    float kl=0.f;
    if(act){
        float m=g_base_mu[tid]+mub[k];
        float l=g_base_ls[tid]+lsb[k];
        kl += (expf(l)+m*m)/(1.f+EPSF) - 1.f - l;
        eprev[tid]=m;
        g_etas[((size_t)s*TT+0)*KT+k]=m;
    }
    __syncthreads();
    for(int t=1;t<TT;t++){
        float m=0.f;
        if(act){
            m=g_base_mu[(size_t)t*SSRC*KT+tid]+mub[k];
            float l=g_base_ls[(size_t)t*SSRC*KT+tid]+lsb[k];
            const float* er=eprev+s*KT;
#pragma unroll
            for(int k2=0;k2<KT;k2++){
                float e=er[k2];
                m=fmaf(e,g_muRT[k2*KT+k],m);
                l=fmaf(e,g_lsRT[k2*KT+k],l);
            }
            l=fminf(fmaxf(l,-10.f),10.f);
            float d=m-eprev[tid];
            kl += (expf(l)+d*d)/(DELTAF+EPSF) - 1.f + LOG_DELTA_F - l;
        }
        __syncthreads();
        if(act){ eprev[tid]=m; g_etas[((size_t)s*TT+t)*KT+k]=m; }
        __syncthreads();
    }
    red[tid]=kl; __syncthreads();
    for(int off=256;off>0;off>>=1){ if(tid<off) red[tid]+=red[tid+off]; __syncthreads(); }
    if(tid==0) g_kleta[0]=0.5f*red[0];
}

// ---------------- h1 epilogue (direct eta indexing) ----------------
__global__ void h1_epilogue(const float* __restrict__ b1,
                            const int* __restrict__ sources,const int* __restrict__ times)
{
    int i=blockIdx.x*blockDim.x+threadIdx.x;
    if(i>=BB*THH) return;
    int b=i/THH, j=i%THH;
    float v=0.f;
    for(int z=0;z<H1Z;z++) v+=g_part4[(size_t)z*BB*THH+i];
    v+=b1[j];
    const float* e=g_etas+((size_t)sources[b]*TT+times[b])*KT;
#pragma unroll
    for(int k=0;k<KT;k++) v=fmaf(e[k], g_w1etaT[k*THH+j], v);
    g_h1[i]=fmaxf(v,0.f);
}

// ---------------- fused theta: heads + softmax + kl + pred + wdoc + doclist ----------------
__global__ void __launch_bounds__(256) theta_fused(
    const float* __restrict__ mub,const float* __restrict__ lsb,
    const float* __restrict__ clsW,const float* __restrict__ clsb,
    const int* __restrict__ sources,const int* __restrict__ times)
{
    __shared__ float h[THH];
    __shared__ float pm[KT][5], pl[KT][5];
    __shared__ float muv[KT], lsv[KT], th[KT], es[KT];
    const int b=blockIdx.x, tid=threadIdx.x;
    for(int j=tid;j<THH;j+=256) h[j]=g_h2[(size_t)b*THH+j];
    __syncthreads();
    if(tid<250){
        int k=tid/5, g=tid%5;
        float am=0.f, al=0.f;
        for(int j=g*160;j<(g+1)*160;j++){
            float hv=h[j];
            am=fmaf(hv,g_mthT[j*KT+k],am);
            al=fmaf(hv,g_lthT[j*KT+k],al);
        }
        pm[k][g]=am; pl[k][g]=al;
    }
    __syncthreads();
    const int t=times[b], src=sources[b];
    if(tid<KT){
        float am=mub[tid], al=lsb[tid];
#pragma unroll
        for(int g=0;g<5;g++){ am+=pm[tid][g]; al+=pl[tid][g]; }
        al=fminf(fmaxf(al,-10.f),10.f);
        muv[tid]=am; lsv[tid]=al;
        es[tid]=g_etas[((size_t)src*TT+t)*KT+tid];
    }
    __syncthreads();
    if(tid==0){
        float mx=-1e30f;
        for(int k=0;k<KT;k++) mx=fmaxf(mx,muv[k]);
        float Z=0.f;
        for(int k=0;k<KT;k++){ float e=expf(muv[k]-mx); th[k]=e; Z+=e; }
        float iZ=1.f/Z;
        float kl=0.f;
        for(int k=0;k<KT;k++){
            th[k]*=iZ;
            float d=muv[k]-es[k];
            kl += (expf(lsv[k])+d*d)/(1.f+EPSF)-1.f-lsv[k];
        }
        g_pth[b]=0.5f*kl;
        float lg[SSRC], mxl=-1e30f;
        for(int i=0;i<SSRC;i++){
            float a=clsb[i];
            for(int k=0;k<KT;k++) a=fmaf(th[k],clsW[i*KT+k],a);
            lg[i]=a; mxl=fmaxf(mxl,a);
        }
        float se=0.f;
        for(int i=0;i<SSRC;i++) se+=expf(lg[i]-mxl);
        g_ppred[b]=mxl+logf(se)-lg[src];
    }
    __syncthreads();
    if(tid<KT){
        g_theta[(size_t)b*KT+tid]=th[tid];
        g_wdoc[(size_t)b*KT+tid]=th[tid]*g_invZ[t*KT+tid];
    }
    if(b==0 && tid==255){
        int cnt[TT];
        for(int tt=0;tt<TT;tt++) cnt[tt]=0;
        for(int bb=0;bb<BB;bb++){
            int td=times[bb];
            g_dlist[td*BB + cnt[td]]=bb;
            cnt[td]++;
        }
        for(int tt=0;tt<TT;tt++) g_dcnt[tt]=cnt[tt];
    }
}

// ---------------- NLL (docs grouped by time, bf16 E) ----------------
__global__ void __launch_bounds__(256) nll2_kernel(const float* __restrict__ bows)
{
    const int t=blockIdx.x, vt=blockIdx.y, tid=threadIdx.x;
    __shared__ float ws[32][KT];
    __shared__ int   dls[32];
    __shared__ float red[256];
    const int cnt=g_dcnt[t];
    float s=0.f;
    for(int d0=0; d0<cnt; d0+=32){
        int ch=min(32,cnt-d0);
        __syncthreads();
        for(int i=tid;i<ch*KT;i+=256){
            int d=i/KT, k=i%KT;
            int b=g_dlist[t*BB+d0+d];
            ws[d][k]=g_wdoc[(size_t)b*KT+k];
            if(k==0) dls[d]=b;
        }
        __syncthreads();
        for(int vi=0;vi<4;vi++){
            int v=vt*1024+vi*256+tid;
            if(v>=VV) break;
            float e[KT];
            const __nv_bfloat16* Ep=g_E+(size_t)t*KT*VV+v;
#pragma unroll
            for(int k=0;k<KT;k++) e[k]=__bfloat162float(Ep[(size_t)k*VV]);
            for(int d=0;d<ch;d++){
                float mix=0.f;
#pragma unroll
                for(int k=0;k<KT;k++) mix=fmaf(ws[d][k],e[k],mix);
                s=fmaf(__logf(mix), bows[(size_t)dls[d]*VV+v], s);
            }
        }
    }
    red[tid]=s; __syncthreads();
    for(int off=128;off>0;off>>=1){ if(tid<off) red[tid]+=red[tid+off]; __syncthreads(); }
    if(tid==0) g_pnllT[t*NVTILE+vt]=red[0];
}

// ---------------- final combine ----------------
__global__ void __launch_bounds__(256) final_kernel(const void* __restrict__ ndocs_ptr,
                                                    float* __restrict__ out)
{
    __shared__ float red[256];
    const int tid=threadIdx.x;
    float sa=0.f;
    for(int i=tid;i<KT*TT;i+=256) sa+=g_pa[i];
    red[tid]=sa; __syncthreads();
    for(int off=128;off>0;off>>=1){ if(tid<off) red[tid]+=red[tid+off]; __syncthreads(); }
    float kl_alpha=red[0]; __syncthreads();

    float sl=0.f;
    for(int i=tid;i<TT*NVTILE;i+=256) sl+=g_pnllT[i];
    red[tid]=sl; __syncthreads();
    for(int off=128;off>0;off>>=1){ if(tid<off) red[tid]+=red[tid+off]; __syncthreads(); }
    float sum_ll=red[0]; __syncthreads();

    red[tid]=g_pth[tid]; __syncthreads();
    for(int off=128;off>0;off>>=1){ if(tid<off) red[tid]+=red[tid+off]; __syncthreads(); }
    float sum_th=red[0]; __syncthreads();

    red[tid]=g_ppred[tid]; __syncthreads();
    for(int off=128;off>0;off>>=1){ if(tid<off) red[tid]+=red[tid+off]; __syncthreads(); }
    float sum_pred=red[0]; __syncthreads();

    if(tid==0){
        int v0=*(const int*)ndocs_ptr;
        float nd;
        if(v0>0 && v0<(1<<30)) nd=(float)v0;
        else nd=*(const float*)ndocs_ptr;
        float coeff=nd/(float)BB;
        float nll=-sum_ll*coeff;
        float kl_eta=g_kleta[0];
        float kl_theta=sum_th*coeff;
        float pred=sum_pred*coeff;
        float nelbo=nll+kl_alpha+kl_eta+kl_theta+pred;
        out[0]=nelbo; out[1]=nll; out[2]=kl_alpha;
        out[3]=kl_eta; out[4]=kl_theta; out[5]=pred;
    }
}

// ---------------- launcher ----------------
extern "C" void kernel_launch(void* const* d_in, const int* in_sizes, int n_in,
                              void* d_out, int out_size)
{
    const float* bows      =(const float*)d_in[1];
    const float* nbows     =(const float*)d_in[2];
    const int*   times     =(const int*)  d_in[3];
    const int*   sources   =(const int*)  d_in[4];
    const float* rnn_inp   =(const float*)d_in[5];
    const void*  num_docs  =               d_in[6];
    const float* mu_q_alpha=(const float*)d_in[7];
    const float* ls_q_alpha=(const float*)d_in[8];
    const float* rho_W     =(const float*)d_in[9];
    const float* W1        =(const float*)d_in[10];
    const float* b1        =(const float*)d_in[11];
    const float* W2        =(const float*)d_in[12];
    const float* b2        =(const float*)d_in[13];
    const float* mu_th_W   =(const float*)d_in[14];
    const float* mu_th_b   =(const float*)d_in[15];
    const float* ls_th_W   =(const float*)d_in[16];
    const float* ls_th_b   =(const float*)d_in[17];
    const float* eta_map_W =(const float*)d_in[18];
    const float* eta_map_b =(const float*)d_in[19];
    const float* lstm_Wih  =(const float*)d_in[20];
    const float* lstm_Whh  =(const float*)d_in[21];
    const float* lstm_bih  =(const float*)d_in[22];
    const float* lstm_bhh  =(const float*)d_in[23];
    const float* mu_eta_W  =(const float*)d_in[24];
    const float* mu_eta_b  =(const float*)d_in[25];
    const float* ls_eta_W  =(const float*)d_in[26];
    const float* ls_eta_b  =(const float*)d_in[27];
    const float* cls_W     =(const float*)d_in[28];
    const float* cls_b     =(const float*)d_in[29];
    float* out=(float*)d_out;

    float *rsumP,*part1,*partx,*mapped,*xz,*part4,*part5,*h1,*h2;
    __nv_bfloat16 *Abf,*Bbf,*nbbf,*w1bf,*rnnbf,*emwbf,*E;
    cudaGetSymbolAddress((void**)&Abf,g_Abf);
    cudaGetSymbolAddress((void**)&Bbf,g_Bbf);
    cudaGetSymbolAddress((void**)&nbbf,g_nbbf);
    cudaGetSymbolAddress((void**)&w1bf,g_w1bf);
    cudaGetSymbolAddress((void**)&rnnbf,g_rnnbf);
    cudaGetSymbolAddress((void**)&emwbf,g_emwbf);
    cudaGetSymbolAddress((void**)&E,g_E);
    cudaGetSymbolAddress((void**)&rsumP,g_rsumP);
    cudaGetSymbolAddress((void**)&part1,g_part1);
    cudaGetSymbolAddress((void**)&partx,g_partx);
    cudaGetSymbolAddress((void**)&mapped,g_mapped);
    cudaGetSymbolAddress((void**)&xz,g_xz);
    cudaGetSymbolAddress((void**)&part4,g_part4);
    cudaGetSymbolAddress((void**)&part5,g_part5);
    cudaGetSymbolAddress((void**)&h1,g_h1);
    cudaGetSymbolAddress((void**)&h2,g_h2);

    static int attr_done=0;
    if(!attr_done){
        cudaFuncSetAttribute(beta_hmma_kernel, cudaFuncAttributeMaxDynamicSharedMemorySize, 65536);
        cudaFuncSetAttribute(hmma_nt, cudaFuncAttributeMaxDynamicSharedMemorySize, 65536);
        attr_done=1;
    }

    // ---- 1: all elementwise prep in one launch ----
    {
        int grid=NB_ABF+NB_BBF+NB_CN+NB_CW+NB_CR+NB_CE+NB_WH+NB_HD+NB_KA;
        mega_prep<<<grid,256>>>(mu_q_alpha,rho_W,nbows,W1,rnn_inp,eta_map_W,lstm_Whh,
                                mu_eta_W,ls_eta_W,mu_th_W,ls_th_W,ls_q_alpha);
    }

    // ---- 2-3: beta path ----
    {
        dim3 g(NT,MT,1);
        beta_hmma_kernel<<<g,256,65536>>>(Abf,Bbf,E,rsumP);
    }
    rsum_reduce<<<(TT*KT+255)/256,256>>>();

    // ---- eta path ----
    {
        dim3 g(2,4,EMZ);
        hmma_nt<<<g,256,65536>>>(500,EHH,EHH,(KSTG+EMZ-1)/EMZ, rnnbf, emwbf, part1);
        reduce_split<<<(500*EHH+255)/256,256>>>(part1,EMZ,500*EHH,EHH, eta_map_b,nullptr,0, mapped);
    }
    {
        dim3 g((4*EHH+127)/128,(500+127)/128,4);
        sgemm128<0><<<g,256>>>(500,4*EHH,EHH, mapped,EHH, lstm_Wih,EHH,
                               partx,4*EHH, nullptr,nullptr);
        reduce_split<<<(500*4*EHH+255)/256,256>>>(partx,4,500*4*EHH,4*EHH, lstm_bih,lstm_bhh,0, xz);
    }
    lstm_kernel<<<SSRC,4*EHH>>>();
    eta_base_kernel<<<(TT*SSRC*KT+255)/256,256>>>();
    eta_rec_kernel<<<1,512>>>(mu_eta_b, ls_eta_b);

    // ---- theta path ----
    {
        dim3 g(7,2,H1Z);
        hmma_nt<<<g,256,65536>>>(BB,THH,THH,(KSTG+H1Z-1)/H1Z, nbbf, w1bf, part4);
    }
    h1_epilogue<<<(BB*THH+255)/256,256>>>(b1, sources, times);
    {
        dim3 g((THH+127)/128,(BB+127)/128,8);
        sgemm128<0><<<g,256>>>(BB,THH,THH, h1,THH, W2,THH,
                               part5,THH, nullptr,nullptr);
        reduce_split<<<(BB*THH+255)/256,256>>>(part5,8,BB*THH,THH, b2,nullptr,1, h2);
    }
    theta_fused<<<BB,256>>>(mu_th_b, ls_th_b, cls_W, cls_b, sources, times);

    // ---- NLL ----
    {
        dim3 g(TT,NVTILE,1);
        nll2_kernel<<<g,256>>>(bows);
    }

    // ---- combine ----
    final_kernel<<<1,256>>>(num_docs, out);
    (void)in_sizes; (void)n_in; (void)out_size;
}